// round 5
// baseline (speedup 1.0000x reference)
#include <cuda_runtime.h>
#include <math.h>

#define Bz 8
#define Ln 64
#define WL 32
#define EMBD 256
#define H2 256
#define HIDD 512
#define RECD 128
#define NEGV -1000000000.0f

__device__ float g_embeds[Bz*Ln*EMBD];
__device__ float g_xw[2*Bz*Ln*1024];
__device__ float g_hstate[2][2*Ln*H2];
__device__ float g_cstate[2*Ln*H2];
__device__ float g_hs[Bz*Ln*HIDD];
__device__ float g_u[Bz*Ln];
__device__ float g_v[Bz*Ln];
__device__ float g_p1[Bz*Ln*RECD];
__device__ float g_p2[Bz*Ln*RECD];
__device__ float g_s[Bz*Ln*Ln];
__device__ float g_rowlse[Bz*Ln];
__device__ float g_logZ[Bz];

// K1: word-average embeddings. 512 blocks x 256 threads.
__global__ void k_embed(const int* __restrict__ sents, const float* __restrict__ mask,
                        const float* __restrict__ emb) {
    int row = blockIdx.x, tid = threadIdx.x;
    __shared__ int sw[WL]; __shared__ float sm[WL]; __shared__ float sden;
    if (tid < WL) { sw[tid] = sents[row*WL + tid]; sm[tid] = mask[row*WL + tid]; }
    __syncthreads();
    if (tid == 0) {
        float e = 0.f;
        for (int w = 0; w < WL; w++) e += sm[w];
        sden = e + (e == 0.0f ? 1.0f : 0.0f);
    }
    __syncthreads();
    float acc = 0.f;
    #pragma unroll 8
    for (int w = 0; w < WL; w++) acc += emb[(size_t)sw[w]*EMBD + tid] * sm[w];
    g_embeds[row*EMBD + tid] = acc / sden;
}

// K2: xW = embeds @ Wih^T + (bih+bhh), both dirs. grid (8,16,2) x 256.
__global__ void k_xw(const float* __restrict__ Wf, const float* __restrict__ bif,
                     const float* __restrict__ bhf,
                     const float* __restrict__ Wb, const float* __restrict__ bib,
                     const float* __restrict__ bhb) {
    int dir = blockIdx.z;
    const float* W  = dir ? Wb  : Wf;
    const float* bi = dir ? bib : bif;
    const float* bh = dir ? bhb : bhf;
    int r0 = blockIdx.x * 64, g0 = blockIdx.y * 64;
    __shared__ float Ash[64*68];   // [e][row]
    __shared__ float Wsh[64*68];   // [e][gate]
    int tid = threadIdx.x;
    int ri = tid & 15, gi = tid >> 4;
    float acc[4][4] = {};
    for (int e0 = 0; e0 < EMBD; e0 += 64) {
        #pragma unroll 4
        for (int q = 0; q < 16; q++) {
            int li = tid + q*256;
            int xx = li >> 6, ee = li & 63;
            Ash[ee*68 + xx] = g_embeds[(r0+xx)*EMBD + e0 + ee];
            Wsh[ee*68 + xx] = W[(g0+xx)*EMBD + e0 + ee];
        }
        __syncthreads();
        #pragma unroll 8
        for (int e = 0; e < 64; e++) {
            float4 av = *(const float4*)&Ash[e*68 + ri*4];
            float4 wv = *(const float4*)&Wsh[e*68 + gi*4];
            float aa[4] = {av.x, av.y, av.z, av.w};
            float ww[4] = {wv.x, wv.y, wv.z, wv.w};
            #pragma unroll
            for (int a = 0; a < 4; a++)
                #pragma unroll
                for (int g = 0; g < 4; g++) acc[a][g] += aa[a]*ww[g];
        }
        __syncthreads();
    }
    #pragma unroll
    for (int a = 0; a < 4; a++)
        #pragma unroll
        for (int g = 0; g < 4; g++) {
            int row = r0 + ri*4 + a, gg = g0 + gi*4 + g;
            g_xw[((size_t)dir*Bz*Ln + row)*1024 + gg] = acc[a][g] + bi[gg] + bh[gg];
        }
}

// K3: one LSTM step. grid (4 n-tiles,16 u-tiles,2 dirs) x 128, dyn smem 90KB.
// gcol = uu*4 + gate so each thread owns all 4 gates of its (n,u) cells.
__global__ void k_lstm(const float* __restrict__ Whh_f, const float* __restrict__ Whh_b,
                       int s) {
    extern __shared__ float smem[];
    float* hsh = smem;            // [256][20] : [e][n-local 16]
    float* wsh = smem + 256*20;   // [256][68] : [e][gcol 64]
    int dir = blockIdx.z;
    int n0 = blockIdx.x*16, u0 = blockIdx.y*16;
    int t = dir ? (Bz-1-s) : s;
    const float* Whh = dir ? Whh_b : Whh_f;
    int rb = (s+1)&1, wb = s&1;
    int tid = threadIdx.x;
    #pragma unroll 4
    for (int q = 0; q < 128; q++) {
        int li = tid + q*128;
        int gcol = li >> 8, e = li & 255;
        int grow = (gcol & 3)*H2 + u0 + (gcol >> 2);
        wsh[e*68 + gcol] = Whh[grow*H2 + e];
    }
    if (s > 0) {
        const float* hp = &g_hstate[rb][dir*Ln*H2];
        #pragma unroll 4
        for (int q = 0; q < 32; q++) {
            int li = tid + q*128;
            int n = li >> 8, e = li & 255;
            hsh[e*20 + n] = hp[(n0+n)*H2 + e];
        }
    }
    __syncthreads();
    int gi = tid & 15, ni = tid >> 4;
    float a0[4] = {}, a1[4] = {};
    if (s > 0) {
        #pragma unroll 8
        for (int e = 0; e < 256; e++) {
            float2 hv = *(const float2*)&hsh[e*20 + ni*2];
            float4 wv = *(const float4*)&wsh[e*68 + gi*4];
            a0[0] += hv.x*wv.x; a0[1] += hv.x*wv.y; a0[2] += hv.x*wv.z; a0[3] += hv.x*wv.w;
            a1[0] += hv.y*wv.x; a1[1] += hv.y*wv.y; a1[2] += hv.y*wv.z; a1[3] += hv.y*wv.w;
        }
    }
    #pragma unroll
    for (int j = 0; j < 2; j++) {
        float* acc = j ? a1 : a0;
        int n = n0 + ni*2 + j, u = u0 + gi;
        const float* xwp = &g_xw[((size_t)dir*Bz*Ln + (size_t)t*Ln + n)*1024];
        float iv = acc[0] + xwp[u],       fv = acc[1] + xwp[256 + u];
        float gv = acc[2] + xwp[512 + u], ov = acc[3] + xwp[768 + u];
        float cold = (s > 0) ? g_cstate[dir*Ln*H2 + n*H2 + u] : 0.0f;
        float ig = 1.f/(1.f + expf(-iv));
        float fg = 1.f/(1.f + expf(-fv));
        float og = 1.f/(1.f + expf(-ov));
        float c  = fg*cold + ig*tanhf(gv);
        float h  = og*tanhf(c);
        g_cstate[dir*Ln*H2 + n*H2 + u]     = c;
        g_hstate[wb][dir*Ln*H2 + n*H2 + u] = h;
        g_hs[((size_t)t*Ln + n)*HIDD + dir*H2 + u] = h;
    }
}

// K4: rank-1 crf projections u,v. 512 blocks x 128.
__global__ void k_uv(const float* __restrict__ Ws) {
    int row = blockIdx.x, l = row & 63, tid = threadIdx.x;
    const float* hc = &g_hs[(size_t)row*HIDD];
    float au = 0.f, av = 0.f;
    for (int d = tid; d < HIDD; d += 128) {
        float h0 = hc[d];
        au += h0 * Ws[d];               av += h0 * Ws[1536 + d];
        if (l > 0)  { float hb = hc[d - HIDD]; au += hb*Ws[512  + d]; av += hb*Ws[1536 + 512  + d]; }
        if (l < 63) { float hn = hc[d + HIDD]; au += hn*Ws[1024 + d]; av += hn*Ws[1536 + 1024 + d]; }
    }
    __shared__ float su[128], sv[128];
    su[tid] = au; sv[tid] = av; __syncthreads();
    for (int st = 64; st > 0; st >>= 1) {
        if (tid < st) { su[tid] += su[tid + st]; sv[tid] += sv[tid + st]; }
        __syncthreads();
    }
    if (tid == 0) { g_u[row] = su[0]; g_v[row] = sv[0]; }
}

// K6: p1 = h@W1^T+b1, p2 = h@W2^T+b2. 128 blocks x 256.
__global__ void k_p12(const float* __restrict__ W1, const float* __restrict__ b1,
                      const float* __restrict__ W2, const float* __restrict__ b2) {
    int r0 = blockIdx.x * 4, tid = threadIdx.x;
    __shared__ float hsh[4*512];
    __shared__ float w1sh[128*36];
    __shared__ float w2sh[128*36];
    #pragma unroll
    for (int q = 0; q < 8; q++) { int li = tid + q*256; hsh[li] = g_hs[(size_t)r0*HIDD + li]; }
    int j = tid & 127, rh = tid >> 7;
    float a00 = 0.f, a01 = 0.f, a10 = 0.f, a11 = 0.f;
    for (int e0 = 0; e0 < HIDD; e0 += 32) {
        #pragma unroll
        for (int q = 0; q < 16; q++) {
            int li = tid + q*256;
            int jj = li >> 5, ee = li & 31;
            w1sh[jj*36 + ee] = W1[jj*HIDD + e0 + ee];
            w2sh[jj*36 + ee] = W2[jj*HIDD + e0 + ee];
        }
        __syncthreads();
        #pragma unroll
        for (int e = 0; e < 32; e += 4) {
            float4 h0 = *(const float4*)&hsh[(rh*2    )*512 + e0 + e];
            float4 h1 = *(const float4*)&hsh[(rh*2 + 1)*512 + e0 + e];
            float4 w1v = *(const float4*)&w1sh[j*36 + e];
            float4 w2v = *(const float4*)&w2sh[j*36 + e];
            a00 += h0.x*w1v.x + h0.y*w1v.y + h0.z*w1v.z + h0.w*w1v.w;
            a01 += h0.x*w2v.x + h0.y*w2v.y + h0.z*w2v.z + h0.w*w2v.w;
            a10 += h1.x*w1v.x + h1.y*w1v.y + h1.z*w1v.z + h1.w*w1v.w;
            a11 += h1.x*w2v.x + h1.y*w2v.y + h1.z*w2v.z + h1.w*w2v.w;
        }
        __syncthreads();
    }
    g_p1[(r0 + rh*2    )*RECD + j] = a00 + b1[j];
    g_p2[(r0 + rh*2    )*RECD + j] = a01 + b2[j];
    g_p1[(r0 + rh*2 + 1)*RECD + j] = a10 + b1[j];
    g_p2[(r0 + rh*2 + 1)*RECD + j] = a11 + b2[j];
}

// K7: s[b,i,:] = p1[b,i].p2[b,:], row logsumexp. 512 blocks x 64.
__global__ void k_scores() {
    int b = blockIdx.x >> 6, i = blockIdx.x & 63, tid = threadIdx.x;
    __shared__ float p1sh[RECD];
    __shared__ float p2sh[64*132];
    __shared__ float red[64];
    p1sh[tid]      = g_p1[(b*Ln + i)*RECD + tid];
    p1sh[tid + 64] = g_p1[(b*Ln + i)*RECD + tid + 64];
    #pragma unroll 8
    for (int q = 0; q < 128; q++) {
        int li = tid + q*64;
        int jj = li >> 7, ee = li & 127;
        p2sh[jj*132 + ee] = g_p2[(b*Ln + jj)*RECD + ee];
    }
    __syncthreads();
    float dot = 0.f;
    #pragma unroll
    for (int e = 0; e < RECD; e += 4) {
        float4 p2v = *(const float4*)&p2sh[tid*132 + e];
        float4 p1v = *(const float4*)&p1sh[e];
        dot += p1v.x*p2v.x + p1v.y*p2v.y + p1v.z*p2v.z + p1v.w*p2v.w;
    }
    g_s[((size_t)b*Ln + i)*Ln + tid] = dot;
    red[tid] = dot; __syncthreads();
    for (int st = 32; st > 0; st >>= 1) { if (tid < st) red[tid] = fmaxf(red[tid], red[tid+st]); __syncthreads(); }
    float mx = red[0]; __syncthreads();
    red[tid] = expf(dot - mx); __syncthreads();
    for (int st = 32; st > 0; st >>= 1) { if (tid < st) red[tid] += red[tid+st]; __syncthreads(); }
    if (tid == 0) g_rowlse[b*Ln + i] = mx + logf(red[0]);
}

__device__ __forceinline__ float warp_lse2(float v1, float v2) {
    float mx = fmaxf(v1, v2);
    #pragma unroll
    for (int o = 16; o; o >>= 1) mx = fmaxf(mx, __shfl_xor_sync(0xffffffffu, mx, o));
    float sum = expf(v1 - mx) + expf(v2 - mx);
    #pragma unroll
    for (int o = 16; o; o >>= 1) sum += __shfl_xor_sync(0xffffffffu, sum, o);
    return mx + logf(sum);
}

// K8: Eisner inside log-partition. 8 blocks x 1024, charts in smem (dyn 66.5KB).
__global__ void k_eisner(const float* __restrict__ bs) {
    extern __shared__ float smf[];
    float* Cr = smf;         float* Cl = smf + 4160;
    float* Ir = smf + 8320;  float* Il = smf + 12480;
    __shared__ float ush[64], vsh[64];
    int b = blockIdx.x, tid = threadIdx.x;
    if (tid < 64) { ush[tid] = g_u[b*Ln + tid] + bs[0]; vsh[tid] = g_v[b*Ln + tid]; }
    for (int idx = tid; idx < 4160; idx += 1024) {
        int i = idx / 65, jj = idx % 65;
        float dv = (jj < 64 && i == jj) ? 0.0f : NEGV;
        Cr[idx] = dv; Cl[idx] = dv; Ir[idx] = NEGV; Il[idx] = NEGV;
    }
    __syncthreads();
    int warp = tid >> 5, lane = tid & 31;
    for (int w = 1; w < Ln; w++) {
        int spans = Ln - w;
        for (int sp = warp; sp < spans; sp += 32) {
            int i = sp, jn = i + w;
            int k1 = i + lane, k2 = i + lane + 32;
            float v1 = (lane      < w) ? Cr[i*65 + k1] + Cl[(k1+1)*65 + jn] : -INFINITY;
            float v2 = (lane + 32 < w) ? Cr[i*65 + k2] + Cl[(k2+1)*65 + jn] : -INFINITY;
            float inc = warp_lse2(v1, v2);
            if (lane == 0) {
                Ir[i*65 + jn] = inc + ush[i]  + vsh[jn];
                Il[i*65 + jn] = inc + ush[jn] + vsh[i];
            }
        }
        __syncthreads();
        for (int tk = warp; tk < 2*spans; tk += 32) {
            int sp = tk >> 1, ch = tk & 1;
            int i = sp, jn = i + w;
            float v1, v2;
            if (ch == 0) {
                int k1 = i + 1 + lane, k2 = i + 33 + lane;
                v1 = (lane      < w) ? Ir[i*65 + k1] + Cr[k1*65 + jn] : -INFINITY;
                v2 = (lane + 32 < w) ? Ir[i*65 + k2] + Cr[k2*65 + jn] : -INFINITY;
            } else {
                int k1 = i + lane, k2 = i + lane + 32;
                v1 = (lane      < w) ? Cl[i*65 + k1] + Il[k1*65 + jn] : -INFINITY;
                v2 = (lane + 32 < w) ? Cl[i*65 + k2] + Il[k2*65 + jn] : -INFINITY;
            }
            float res = warp_lse2(v1, v2);
            if (lane == 0) { if (ch == 0) Cr[i*65 + jn] = res; else Cl[i*65 + jn] = res; }
        }
        __syncthreads();
    }
    if (tid == 0) g_logZ[b] = Cr[Ln - 1];
}

// K9: gather jp at (heads[b,m], m), LSE over m, loss. 1 block x 256.
__global__ void k_final(const int* __restrict__ heads, const float* __restrict__ prior,
                        const float* __restrict__ bs, float* __restrict__ out) {
    int tid = threadIdx.x, warp = tid >> 5, lane = tid & 31;
    __shared__ float sb[8];
    int b = warp;
    float bsv = bs[0];
    int m1 = lane + 1, m2 = lane + 33;
    float v1, v2 = -INFINITY;
    {
        int hd = heads[b*Ln + m1];
        v1 = g_u[b*Ln + hd] + g_v[b*Ln + m1] + bsv
           + g_s[((size_t)b*Ln + hd)*Ln + m1] - g_rowlse[b*Ln + hd]
           + prior[((size_t)b*Ln + hd)*Ln + m1] * (1.0f/64.0f);
    }
    if (m2 < Ln) {
        int hd = heads[b*Ln + m2];
        v2 = g_u[b*Ln + hd] + g_v[b*Ln + m2] + bsv
           + g_s[((size_t)b*Ln + hd)*Ln + m2] - g_rowlse[b*Ln + hd]
           + prior[((size_t)b*Ln + hd)*Ln + m2] * (1.0f/64.0f);
    }
    float mx = fmaxf(v1, v2);
    #pragma unroll
    for (int o = 16; o; o >>= 1) mx = fmaxf(mx, __shfl_xor_sync(0xffffffffu, mx, o));
    float sum = expf(v1 - mx) + expf(v2 - mx);
    #pragma unroll
    for (int o = 16; o; o >>= 1) sum += __shfl_xor_sync(0xffffffffu, sum, o);
    if (lane == 0) sb[b] = (mx + logf(sum)) - g_logZ[b];
    __syncthreads();
    if (tid == 0) {
        float t = 0.f;
        for (int q = 0; q < 8; q++) t += sb[q];
        out[0] = -t * (1.0f/8.0f);
    }
}

extern "C" void kernel_launch(void* const* d_in, const int* in_sizes, int n_in,
                              void* d_out, int out_size) {
    const int*   sents = (const int*)  d_in[0];
    const float* mask  = (const float*)d_in[1];
    const float* prior = (const float*)d_in[2];
    const int*   heads = (const int*)  d_in[3];
    const float* emb   = (const float*)d_in[4];
    const float* Wih_f = (const float*)d_in[5];
    const float* Whh_f = (const float*)d_in[6];
    const float* bih_f = (const float*)d_in[7];
    const float* bhh_f = (const float*)d_in[8];
    const float* Wih_b = (const float*)d_in[9];
    const float* Whh_b = (const float*)d_in[10];
    const float* bih_b = (const float*)d_in[11];
    const float* bhh_b = (const float*)d_in[12];
    const float* W1    = (const float*)d_in[13];
    const float* b1    = (const float*)d_in[14];
    const float* W2    = (const float*)d_in[15];
    const float* b2    = (const float*)d_in[16];
    const float* Ws    = (const float*)d_in[17];
    const float* bsv   = (const float*)d_in[18];
    float* out = (float*)d_out;
    (void)in_sizes; (void)n_in; (void)out_size;

    cudaFuncSetAttribute(k_lstm,   cudaFuncAttributeMaxDynamicSharedMemorySize, 22528*4);
    cudaFuncSetAttribute(k_eisner, cudaFuncAttributeMaxDynamicSharedMemorySize, 16640*4);

    k_embed<<<Bz*Ln, 256>>>(sents, mask, emb);
    dim3 g2(8, 16, 2);
    k_xw<<<g2, 256>>>(Wih_f, bih_f, bhh_f, Wih_b, bih_b, bhh_b);
    dim3 g3(4, 16, 2);
    for (int s = 0; s < Bz; s++)
        k_lstm<<<g3, 128, 22528*4>>>(Whh_f, Whh_b, s);
    k_uv<<<Bz*Ln, 128>>>(Ws);
    k_p12<<<128, 256>>>(W1, b1, W2, b2);
    k_scores<<<Bz*Ln, 64>>>();
    k_eisner<<<Bz, 1024, 16640*4>>>(bsv);
    k_final<<<1, 256>>>(heads, prior, bsv, out);
}

// round 6
// speedup vs baseline: 1.1695x; 1.1695x over previous
#include <cuda_runtime.h>
#include <math.h>

#define Bz 8
#define Ln 64
#define WL 32
#define EMBD 256
#define H2 256
#define HIDD 512
#define RECD 128
#define NEGV -1000000000.0f

__device__ float g_embeds[Bz*Ln*EMBD];
__device__ float g_xw[2*Bz*Ln*1024];
__device__ float g_hT[4*H2*Ln];          // [buf(2)][dir(2)][unit 256][n 64]
__device__ unsigned g_barr[16];          // [dir][step]
__device__ float g_hs[Bz*Ln*HIDD];
__device__ float g_u[Bz*Ln];
__device__ float g_v[Bz*Ln];
__device__ float g_p1[Bz*Ln*RECD];
__device__ float g_p2[Bz*Ln*RECD];
__device__ float g_s[Bz*Ln*Ln];
__device__ float g_rowlse[Bz*Ln];
__device__ float g_logZ[Bz];

// K1: word-average embeddings. 512 blocks x 256 threads.
__global__ void k_embed(const int* __restrict__ sents, const float* __restrict__ mask,
                        const float* __restrict__ emb) {
    int row = blockIdx.x, tid = threadIdx.x;
    __shared__ int sw[WL]; __shared__ float sm[WL]; __shared__ float sden;
    if (tid < WL) { sw[tid] = sents[row*WL + tid]; sm[tid] = mask[row*WL + tid]; }
    __syncthreads();
    if (tid == 0) {
        float e = 0.f;
        for (int w = 0; w < WL; w++) e += sm[w];
        sden = e + (e == 0.0f ? 1.0f : 0.0f);
    }
    __syncthreads();
    float acc = 0.f;
    #pragma unroll 8
    for (int w = 0; w < WL; w++) acc += emb[(size_t)sw[w]*EMBD + tid] * sm[w];
    g_embeds[row*EMBD + tid] = acc / sden;
}

// K2: xW = embeds @ Wih^T + (bih+bhh), both dirs. grid (8,16,2) x 256.
// Also zeroes the LSTM grid-barrier counters (runs before k_lstm_all each replay).
__global__ void k_xw(const float* __restrict__ Wf, const float* __restrict__ bif,
                     const float* __restrict__ bhf,
                     const float* __restrict__ Wb, const float* __restrict__ bib,
                     const float* __restrict__ bhb) {
    if (blockIdx.x == 0 && blockIdx.y == 0 && blockIdx.z == 0 && threadIdx.x < 16)
        g_barr[threadIdx.x] = 0u;
    int dir = blockIdx.z;
    const float* W  = dir ? Wb  : Wf;
    const float* bi = dir ? bib : bif;
    const float* bh = dir ? bhb : bhf;
    int r0 = blockIdx.x * 64, g0 = blockIdx.y * 64;
    __shared__ float Ash[64*68];
    __shared__ float Wsh[64*68];
    int tid = threadIdx.x;
    int ri = tid & 15, gi = tid >> 4;
    float acc[4][4] = {};
    for (int e0 = 0; e0 < EMBD; e0 += 64) {
        #pragma unroll 4
        for (int q = 0; q < 16; q++) {
            int li = tid + q*256;
            int xx = li >> 6, ee = li & 63;
            Ash[ee*68 + xx] = g_embeds[(r0+xx)*EMBD + e0 + ee];
            Wsh[ee*68 + xx] = W[(g0+xx)*EMBD + e0 + ee];
        }
        __syncthreads();
        #pragma unroll 8
        for (int e = 0; e < 64; e++) {
            float4 av = *(const float4*)&Ash[e*68 + ri*4];
            float4 wv = *(const float4*)&Wsh[e*68 + gi*4];
            float aa[4] = {av.x, av.y, av.z, av.w};
            float ww[4] = {wv.x, wv.y, wv.z, wv.w};
            #pragma unroll
            for (int a = 0; a < 4; a++)
                #pragma unroll
                for (int g = 0; g < 4; g++) acc[a][g] += aa[a]*ww[g];
        }
        __syncthreads();
    }
    #pragma unroll
    for (int a = 0; a < 4; a++)
        #pragma unroll
        for (int g = 0; g < 4; g++) {
            int row = r0 + ri*4 + a, gg = g0 + gi*4 + g;
            g_xw[((size_t)dir*Bz*Ln + row)*1024 + gg] = acc[a][g] + bi[gg] + bh[gg];
        }
}

// K3: persistent LSTM — all 8 steps in one kernel.
// 128 blocks x 128 threads. Block (dir, ub) owns 4 units (16 gate-cols).
// Whh slice loaded ONCE into smem; c-state lives in registers; h exchanged
// through a double-buffered transposed global with a per-dir spin barrier.
// smem: wsh[16][260] + hsh[256][68] + gsh[16][68] = 22656 floats = 90.6KB.
__global__ void k_lstm_all(const float* __restrict__ Whh_f, const float* __restrict__ Whh_b) {
    extern __shared__ float smem[];
    float* wsh = smem;                  // [gc 16][e 256] pitch 260
    float* hsh = smem + 4160;           // [e 256][n 64] pitch 68
    float* gsh = smem + 4160 + 17408;   // [gc 16][n 64] pitch 68
    int bx = blockIdx.x;
    int dir = bx >> 6, ub = bx & 63, u0 = ub*4;
    const float* Whh = dir ? Whh_b : Whh_f;
    int tid = threadIdx.x;

    // Load Whh slice once (gc = ul*4 + gate).
    #pragma unroll 8
    for (int q = 0; q < 32; q++) {
        int li = tid + q*128;
        int gc = li >> 8, e = li & 255;
        int ul = gc >> 2, gate = gc & 3;
        wsh[gc*260 + e] = Whh[(gate*H2 + u0 + ul)*H2 + e];
    }
    int ng = tid >> 3, gg = tid & 7;     // matmul tile: rows ng*4..+4, cols gg*2..+2
    int n_c = tid & 63, ul_c = tid >> 6; // update cells: (n_c, u0+ul_c) and (n_c, u0+ul_c+2)
    float c0 = 0.f, c1 = 0.f;
    __syncthreads();

    for (int s = 0; s < Bz; s++) {
        int t = dir ? (Bz-1-s) : s;
        // Prefetch xw gate biases for both cells (independent of h).
        const float* xb = &g_xw[((size_t)(dir*Bz*Ln + t*Ln + n_c))*1024 + u0 + ul_c];
        float xw0[4], xw1[4];
        #pragma unroll
        for (int g = 0; g < 4; g++) { xw0[g] = xb[g*256]; xw1[g] = xb[g*256 + 2]; }

        float a00=0.f,a01=0.f,a10=0.f,a11=0.f,a20=0.f,a21=0.f,a30=0.f,a31=0.f;
        if (s > 0) {
            // Stage full h_prev (transposed [u][n]) from L2.
            const float* hp = &g_hT[((s&1)*2 + dir)*H2*Ln];
            #pragma unroll 8
            for (int q = 0; q < 32; q++) {
                int idx = (tid + q*128)*4;
                int e = idx >> 6, n = idx & 63;
                float4 hv = __ldcg((const float4*)(hp + idx));
                *(float4*)&hsh[e*68 + n] = hv;
            }
            __syncthreads();
            #pragma unroll 4
            for (int e4 = 0; e4 < H2; e4 += 4) {
                float4 w0 = *(const float4*)&wsh[(gg*2  )*260 + e4];
                float4 w1 = *(const float4*)&wsh[(gg*2+1)*260 + e4];
                float wa[4] = {w0.x, w0.y, w0.z, w0.w};
                float wb[4] = {w1.x, w1.y, w1.z, w1.w};
                #pragma unroll
                for (int k = 0; k < 4; k++) {
                    float4 hv = *(const float4*)&hsh[(e4+k)*68 + ng*4];
                    a00 += hv.x*wa[k]; a01 += hv.x*wb[k];
                    a10 += hv.y*wa[k]; a11 += hv.y*wb[k];
                    a20 += hv.z*wa[k]; a21 += hv.z*wb[k];
                    a30 += hv.w*wa[k]; a31 += hv.w*wb[k];
                }
            }
        } else {
            __syncthreads();
        }
        // Stage gates.
        gsh[(gg*2  )*68 + ng*4 + 0] = a00; gsh[(gg*2+1)*68 + ng*4 + 0] = a01;
        gsh[(gg*2  )*68 + ng*4 + 1] = a10; gsh[(gg*2+1)*68 + ng*4 + 1] = a11;
        gsh[(gg*2  )*68 + ng*4 + 2] = a20; gsh[(gg*2+1)*68 + ng*4 + 2] = a21;
        gsh[(gg*2  )*68 + ng*4 + 3] = a30; gsh[(gg*2+1)*68 + ng*4 + 3] = a31;
        __syncthreads();
        // Cell updates (2 cells per thread, c in registers).
        {
            float iv = gsh[(ul_c*4+0)*68 + n_c] + xw0[0];
            float fv = gsh[(ul_c*4+1)*68 + n_c] + xw0[1];
            float gv = gsh[(ul_c*4+2)*68 + n_c] + xw0[2];
            float ov = gsh[(ul_c*4+3)*68 + n_c] + xw0[3];
            float ig = 1.f/(1.f + expf(-iv));
            float fg = 1.f/(1.f + expf(-fv));
            float og = 1.f/(1.f + expf(-ov));
            c0 = fg*c0 + ig*tanhf(gv);
            float h0 = og*tanhf(c0);
            int ul2 = ul_c + 2;
            float iv1 = gsh[(ul2*4+0)*68 + n_c] + xw1[0];
            float fv1 = gsh[(ul2*4+1)*68 + n_c] + xw1[1];
            float gv1 = gsh[(ul2*4+2)*68 + n_c] + xw1[2];
            float ov1 = gsh[(ul2*4+3)*68 + n_c] + xw1[3];
            float ig1 = 1.f/(1.f + expf(-iv1));
            float fg1 = 1.f/(1.f + expf(-fv1));
            float og1 = 1.f/(1.f + expf(-ov1));
            c1 = fg1*c1 + ig1*tanhf(gv1);
            float h1 = og1*tanhf(c1);
            int wbuf = (((s+1)&1)*2 + dir)*H2*Ln;
            __stcg(&g_hT[wbuf + (u0+ul_c )*Ln + n_c], h0);
            __stcg(&g_hT[wbuf + (u0+ul2  )*Ln + n_c], h1);
            g_hs[((size_t)t*Ln + n_c)*HIDD + dir*H2 + u0 + ul_c] = h0;
            g_hs[((size_t)t*Ln + n_c)*HIDD + dir*H2 + u0 + ul2 ] = h1;
        }
        if (s < Bz-1) {
            __threadfence();
            __syncthreads();
            if (tid == 0) {
                unsigned c = atomicAdd(&g_barr[dir*8 + s], 1u) + 1u;
                if (c < 64u) {
                    volatile unsigned* p = &g_barr[dir*8 + s];
                    while (*p < 64u) __nanosleep(32);
                }
            }
            __syncthreads();
        }
    }
}

// K4: rank-1 crf projections u,v. 512 blocks x 128.
__global__ void k_uv(const float* __restrict__ Ws) {
    int row = blockIdx.x, l = row & 63, tid = threadIdx.x;
    const float* hc = &g_hs[(size_t)row*HIDD];
    float au = 0.f, av = 0.f;
    for (int d = tid; d < HIDD; d += 128) {
        float h0 = hc[d];
        au += h0 * Ws[d];               av += h0 * Ws[1536 + d];
        if (l > 0)  { float hb = hc[d - HIDD]; au += hb*Ws[512  + d]; av += hb*Ws[1536 + 512  + d]; }
        if (l < 63) { float hn = hc[d + HIDD]; au += hn*Ws[1024 + d]; av += hn*Ws[1536 + 1024 + d]; }
    }
    __shared__ float su[128], sv[128];
    su[tid] = au; sv[tid] = av; __syncthreads();
    for (int st = 64; st > 0; st >>= 1) {
        if (tid < st) { su[tid] += su[tid + st]; sv[tid] += sv[tid + st]; }
        __syncthreads();
    }
    if (tid == 0) { g_u[row] = su[0]; g_v[row] = sv[0]; }
}

// K6: p1 = h@W1^T+b1, p2 = h@W2^T+b2. 128 blocks x 256.
__global__ void k_p12(const float* __restrict__ W1, const float* __restrict__ b1,
                      const float* __restrict__ W2, const float* __restrict__ b2) {
    int r0 = blockIdx.x * 4, tid = threadIdx.x;
    __shared__ float hsh[4*512];
    __shared__ float w1sh[128*36];
    __shared__ float w2sh[128*36];
    #pragma unroll
    for (int q = 0; q < 8; q++) { int li = tid + q*256; hsh[li] = g_hs[(size_t)r0*HIDD + li]; }
    int j = tid & 127, rh = tid >> 7;
    float a00 = 0.f, a01 = 0.f, a10 = 0.f, a11 = 0.f;
    for (int e0 = 0; e0 < HIDD; e0 += 32) {
        #pragma unroll
        for (int q = 0; q < 16; q++) {
            int li = tid + q*256;
            int jj = li >> 5, ee = li & 31;
            w1sh[jj*36 + ee] = W1[jj*HIDD + e0 + ee];
            w2sh[jj*36 + ee] = W2[jj*HIDD + e0 + ee];
        }
        __syncthreads();
        #pragma unroll
        for (int e = 0; e < 32; e += 4) {
            float4 h0 = *(const float4*)&hsh[(rh*2    )*512 + e0 + e];
            float4 h1 = *(const float4*)&hsh[(rh*2 + 1)*512 + e0 + e];
            float4 w1v = *(const float4*)&w1sh[j*36 + e];
            float4 w2v = *(const float4*)&w2sh[j*36 + e];
            a00 += h0.x*w1v.x + h0.y*w1v.y + h0.z*w1v.z + h0.w*w1v.w;
            a01 += h0.x*w2v.x + h0.y*w2v.y + h0.z*w2v.z + h0.w*w2v.w;
            a10 += h1.x*w1v.x + h1.y*w1v.y + h1.z*w1v.z + h1.w*w1v.w;
            a11 += h1.x*w2v.x + h1.y*w2v.y + h1.z*w2v.z + h1.w*w2v.w;
        }
        __syncthreads();
    }
    g_p1[(r0 + rh*2    )*RECD + j] = a00 + b1[j];
    g_p2[(r0 + rh*2    )*RECD + j] = a01 + b2[j];
    g_p1[(r0 + rh*2 + 1)*RECD + j] = a10 + b1[j];
    g_p2[(r0 + rh*2 + 1)*RECD + j] = a11 + b2[j];
}

// K7: s[b,i,:] = p1[b,i].p2[b,:], row logsumexp. 512 blocks x 64.
__global__ void k_scores() {
    int b = blockIdx.x >> 6, i = blockIdx.x & 63, tid = threadIdx.x;
    __shared__ float p1sh[RECD];
    __shared__ float p2sh[64*132];
    __shared__ float red[64];
    p1sh[tid]      = g_p1[(b*Ln + i)*RECD + tid];
    p1sh[tid + 64] = g_p1[(b*Ln + i)*RECD + tid + 64];
    #pragma unroll 8
    for (int q = 0; q < 128; q++) {
        int li = tid + q*64;
        int jj = li >> 7, ee = li & 127;
        p2sh[jj*132 + ee] = g_p2[(b*Ln + jj)*RECD + ee];
    }
    __syncthreads();
    float dot = 0.f;
    #pragma unroll
    for (int e = 0; e < RECD; e += 4) {
        float4 p2v = *(const float4*)&p2sh[tid*132 + e];
        float4 p1v = *(const float4*)&p1sh[e];
        dot += p1v.x*p2v.x + p1v.y*p2v.y + p1v.z*p2v.z + p1v.w*p2v.w;
    }
    g_s[((size_t)b*Ln + i)*Ln + tid] = dot;
    red[tid] = dot; __syncthreads();
    for (int st = 32; st > 0; st >>= 1) { if (tid < st) red[tid] = fmaxf(red[tid], red[tid+st]); __syncthreads(); }
    float mx = red[0]; __syncthreads();
    red[tid] = expf(dot - mx); __syncthreads();
    for (int st = 32; st > 0; st >>= 1) { if (tid < st) red[tid] += red[tid+st]; __syncthreads(); }
    if (tid == 0) g_rowlse[b*Ln + i] = mx + logf(red[0]);
}

__device__ __forceinline__ float warp_lse2(float v1, float v2) {
    float mx = fmaxf(v1, v2);
    #pragma unroll
    for (int o = 16; o; o >>= 1) mx = fmaxf(mx, __shfl_xor_sync(0xffffffffu, mx, o));
    float sum = expf(v1 - mx) + expf(v2 - mx);
    #pragma unroll
    for (int o = 16; o; o >>= 1) sum += __shfl_xor_sync(0xffffffffu, sum, o);
    return mx + logf(sum);
}

// K8: Eisner inside log-partition. 8 blocks x 1024, charts in smem (dyn 66.5KB).
__global__ void k_eisner(const float* __restrict__ bs) {
    extern __shared__ float smf[];
    float* Cr = smf;         float* Cl = smf + 4160;
    float* Ir = smf + 8320;  float* Il = smf + 12480;
    __shared__ float ush[64], vsh[64];
    int b = blockIdx.x, tid = threadIdx.x;
    if (tid < 64) { ush[tid] = g_u[b*Ln + tid] + bs[0]; vsh[tid] = g_v[b*Ln + tid]; }
    for (int idx = tid; idx < 4160; idx += 1024) {
        int i = idx / 65, jj = idx % 65;
        float dv = (jj < 64 && i == jj) ? 0.0f : NEGV;
        Cr[idx] = dv; Cl[idx] = dv; Ir[idx] = NEGV; Il[idx] = NEGV;
    }
    __syncthreads();
    int warp = tid >> 5, lane = tid & 31;
    for (int w = 1; w < Ln; w++) {
        int spans = Ln - w;
        for (int sp = warp; sp < spans; sp += 32) {
            int i = sp, jn = i + w;
            int k1 = i + lane, k2 = i + lane + 32;
            float v1 = (lane      < w) ? Cr[i*65 + k1] + Cl[(k1+1)*65 + jn] : -INFINITY;
            float v2 = (lane + 32 < w) ? Cr[i*65 + k2] + Cl[(k2+1)*65 + jn] : -INFINITY;
            float inc = warp_lse2(v1, v2);
            if (lane == 0) {
                Ir[i*65 + jn] = inc + ush[i]  + vsh[jn];
                Il[i*65 + jn] = inc + ush[jn] + vsh[i];
            }
        }
        __syncthreads();
        for (int tk = warp; tk < 2*spans; tk += 32) {
            int sp = tk >> 1, ch = tk & 1;
            int i = sp, jn = i + w;
            float v1, v2;
            if (ch == 0) {
                int k1 = i + 1 + lane, k2 = i + 33 + lane;
                v1 = (lane      < w) ? Ir[i*65 + k1] + Cr[k1*65 + jn] : -INFINITY;
                v2 = (lane + 32 < w) ? Ir[i*65 + k2] + Cr[k2*65 + jn] : -INFINITY;
            } else {
                int k1 = i + lane, k2 = i + lane + 32;
                v1 = (lane      < w) ? Cl[i*65 + k1] + Il[k1*65 + jn] : -INFINITY;
                v2 = (lane + 32 < w) ? Cl[i*65 + k2] + Il[k2*65 + jn] : -INFINITY;
            }
            float res = warp_lse2(v1, v2);
            if (lane == 0) { if (ch == 0) Cr[i*65 + jn] = res; else Cl[i*65 + jn] = res; }
        }
        __syncthreads();
    }
    if (tid == 0) g_logZ[b] = Cr[Ln - 1];
}

// K9: gather jp at (heads[b,m], m), LSE over m, loss. 1 block x 256.
__global__ void k_final(const int* __restrict__ heads, const float* __restrict__ prior,
                        const float* __restrict__ bs, float* __restrict__ out) {
    int tid = threadIdx.x, warp = tid >> 5, lane = tid & 31;
    __shared__ float sb[8];
    int b = warp;
    float bsv = bs[0];
    int m1 = lane + 1, m2 = lane + 33;
    float v1, v2 = -INFINITY;
    {
        int hd = heads[b*Ln + m1];
        v1 = g_u[b*Ln + hd] + g_v[b*Ln + m1] + bsv
           + g_s[((size_t)b*Ln + hd)*Ln + m1] - g_rowlse[b*Ln + hd]
           + prior[((size_t)b*Ln + hd)*Ln + m1] * (1.0f/64.0f);
    }
    if (m2 < Ln) {
        int hd = heads[b*Ln + m2];
        v2 = g_u[b*Ln + hd] + g_v[b*Ln + m2] + bsv
           + g_s[((size_t)b*Ln + hd)*Ln + m2] - g_rowlse[b*Ln + hd]
           + prior[((size_t)b*Ln + hd)*Ln + m2] * (1.0f/64.0f);
    }
    float mx = fmaxf(v1, v2);
    #pragma unroll
    for (int o = 16; o; o >>= 1) mx = fmaxf(mx, __shfl_xor_sync(0xffffffffu, mx, o));
    float sum = expf(v1 - mx) + expf(v2 - mx);
    #pragma unroll
    for (int o = 16; o; o >>= 1) sum += __shfl_xor_sync(0xffffffffu, sum, o);
    if (lane == 0) sb[b] = (mx + logf(sum)) - g_logZ[b];
    __syncthreads();
    if (tid == 0) {
        float t = 0.f;
        for (int q = 0; q < 8; q++) t += sb[q];
        out[0] = -t * (1.0f/8.0f);
    }
}

extern "C" void kernel_launch(void* const* d_in, const int* in_sizes, int n_in,
                              void* d_out, int out_size) {
    const int*   sents = (const int*)  d_in[0];
    const float* mask  = (const float*)d_in[1];
    const float* prior = (const float*)d_in[2];
    const int*   heads = (const int*)  d_in[3];
    const float* emb   = (const float*)d_in[4];
    const float* Wih_f = (const float*)d_in[5];
    const float* Whh_f = (const float*)d_in[6];
    const float* bih_f = (const float*)d_in[7];
    const float* bhh_f = (const float*)d_in[8];
    const float* Wih_b = (const float*)d_in[9];
    const float* Whh_b = (const float*)d_in[10];
    const float* bih_b = (const float*)d_in[11];
    const float* bhh_b = (const float*)d_in[12];
    const float* W1    = (const float*)d_in[13];
    const float* b1    = (const float*)d_in[14];
    const float* W2    = (const float*)d_in[15];
    const float* b2    = (const float*)d_in[16];
    const float* Ws    = (const float*)d_in[17];
    const float* bsv   = (const float*)d_in[18];
    float* out = (float*)d_out;
    (void)in_sizes; (void)n_in; (void)out_size;

    cudaFuncSetAttribute(k_lstm_all, cudaFuncAttributeMaxDynamicSharedMemorySize, 22656*4);
    cudaFuncSetAttribute(k_eisner,   cudaFuncAttributeMaxDynamicSharedMemorySize, 16640*4);

    k_embed<<<Bz*Ln, 256>>>(sents, mask, emb);
    dim3 g2(8, 16, 2);
    k_xw<<<g2, 256>>>(Wih_f, bih_f, bhh_f, Wih_b, bih_b, bhh_b);
    k_lstm_all<<<128, 128, 22656*4>>>(Whh_f, Whh_b);
    k_uv<<<Bz*Ln, 128>>>(Ws);
    k_p12<<<128, 256>>>(W1, b1, W2, b2);
    k_scores<<<Bz*Ln, 64>>>();
    k_eisner<<<Bz, 1024, 16640*4>>>(bsv);
    k_final<<<1, 256>>>(heads, prior, bsv, out);
}

// round 7
// speedup vs baseline: 1.3483x; 1.1529x over previous
#include <cuda_runtime.h>
#include <math.h>

#define Bz 8
#define Ln 64
#define WL 32
#define EMBD 256
#define H2 256
#define HIDD 512
#define RECD 128
#define NEGV -1000000000.0f

__device__ float g_embeds[Bz*Ln*EMBD];
__device__ float g_xw[2*Bz*Ln*1024];
__device__ float g_hT[4*H2*Ln];          // [buf(2)][dir(2)][unit 256][n 64]
__device__ unsigned g_barr[16];          // [dir][step]
__device__ float g_hs[Bz*Ln*HIDD];
__device__ float g_u[Bz*Ln];
__device__ float g_v[Bz*Ln];
__device__ float g_p1[Bz*Ln*RECD];
__device__ float g_p2[Bz*Ln*RECD];
__device__ float g_s[Bz*Ln*Ln];
__device__ float g_rowlse[Bz*Ln];
__device__ float g_logZ[Bz];

// K1: word-average embeddings. 512 blocks x 256 threads.
__global__ void k_embed(const int* __restrict__ sents, const float* __restrict__ mask,
                        const float* __restrict__ emb) {
    int row = blockIdx.x, tid = threadIdx.x;
    __shared__ int sw[WL]; __shared__ float sm[WL]; __shared__ float sden;
    if (tid < WL) { sw[tid] = sents[row*WL + tid]; sm[tid] = mask[row*WL + tid]; }
    __syncthreads();
    if (tid == 0) {
        float e = 0.f;
        for (int w = 0; w < WL; w++) e += sm[w];
        sden = e + (e == 0.0f ? 1.0f : 0.0f);
    }
    __syncthreads();
    float acc = 0.f;
    #pragma unroll 8
    for (int w = 0; w < WL; w++) acc += emb[(size_t)sw[w]*EMBD + tid] * sm[w];
    g_embeds[row*EMBD + tid] = acc / sden;
}

// K2: xW = embeds @ Wih^T + (bih+bhh), both dirs. grid (8,16,2) x 256.
// Also zeroes the LSTM grid-barrier counters (runs before k_lstm_all each replay).
__global__ void k_xw(const float* __restrict__ Wf, const float* __restrict__ bif,
                     const float* __restrict__ bhf,
                     const float* __restrict__ Wb, const float* __restrict__ bib,
                     const float* __restrict__ bhb) {
    if (blockIdx.x == 0 && blockIdx.y == 0 && blockIdx.z == 0 && threadIdx.x < 16)
        g_barr[threadIdx.x] = 0u;
    int dir = blockIdx.z;
    const float* W  = dir ? Wb  : Wf;
    const float* bi = dir ? bib : bif;
    const float* bh = dir ? bhb : bhf;
    int r0 = blockIdx.x * 64, g0 = blockIdx.y * 64;
    __shared__ float Ash[64*68];
    __shared__ float Wsh[64*68];
    int tid = threadIdx.x;
    int ri = tid & 15, gi = tid >> 4;
    float acc[4][4] = {};
    for (int e0 = 0; e0 < EMBD; e0 += 64) {
        #pragma unroll 4
        for (int q = 0; q < 16; q++) {
            int li = tid + q*256;
            int xx = li >> 6, ee = li & 63;
            Ash[ee*68 + xx] = g_embeds[(r0+xx)*EMBD + e0 + ee];
            Wsh[ee*68 + xx] = W[(g0+xx)*EMBD + e0 + ee];
        }
        __syncthreads();
        #pragma unroll 8
        for (int e = 0; e < 64; e++) {
            float4 av = *(const float4*)&Ash[e*68 + ri*4];
            float4 wv = *(const float4*)&Wsh[e*68 + gi*4];
            float aa[4] = {av.x, av.y, av.z, av.w};
            float ww[4] = {wv.x, wv.y, wv.z, wv.w};
            #pragma unroll
            for (int a = 0; a < 4; a++)
                #pragma unroll
                for (int g = 0; g < 4; g++) acc[a][g] += aa[a]*ww[g];
        }
        __syncthreads();
    }
    #pragma unroll
    for (int a = 0; a < 4; a++)
        #pragma unroll
        for (int g = 0; g < 4; g++) {
            int row = r0 + ri*4 + a, gg = g0 + gi*4 + g;
            g_xw[((size_t)dir*Bz*Ln + row)*1024 + gg] = acc[a][g] + bi[gg] + bh[gg];
        }
}

__device__ __forceinline__ float fsig(float x) {
    return __fdividef(1.0f, 1.0f + __expf(-x));
}

// K3: persistent LSTM — all 8 steps in one kernel.
// 128 blocks x 128 threads. Block (dir, ub) owns 4 units (16 gate-cols).
__global__ void k_lstm_all(const float* __restrict__ Whh_f, const float* __restrict__ Whh_b) {
    extern __shared__ float smem[];
    float* wsh = smem;                  // [gc 16][e 256] pitch 260
    float* hsh = smem + 4160;           // [e 256][n 64] pitch 68
    float* gsh = smem + 4160 + 17408;   // [gc 16][n 64] pitch 68
    int bx = blockIdx.x;
    int dir = bx >> 6, ub = bx & 63, u0 = ub*4;
    const float* Whh = dir ? Whh_b : Whh_f;
    int tid = threadIdx.x;

    #pragma unroll 8
    for (int q = 0; q < 32; q++) {
        int li = tid + q*128;
        int gc = li >> 8, e = li & 255;
        int ul = gc >> 2, gate = gc & 3;
        wsh[gc*260 + e] = Whh[(gate*H2 + u0 + ul)*H2 + e];
    }
    int ng = tid >> 3, gg = tid & 7;
    int n_c = tid & 63, ul_c = tid >> 6;
    float c0 = 0.f, c1 = 0.f;
    __syncthreads();

    for (int s = 0; s < Bz; s++) {
        int t = dir ? (Bz-1-s) : s;
        const float* xb = &g_xw[((size_t)(dir*Bz*Ln + t*Ln + n_c))*1024 + u0 + ul_c];
        float xw0[4], xw1[4];
        #pragma unroll
        for (int g = 0; g < 4; g++) { xw0[g] = xb[g*256]; xw1[g] = xb[g*256 + 2]; }

        float a00=0.f,a01=0.f,a10=0.f,a11=0.f,a20=0.f,a21=0.f,a30=0.f,a31=0.f;
        if (s > 0) {
            const float* hp = &g_hT[((s&1)*2 + dir)*H2*Ln];
            #pragma unroll 8
            for (int q = 0; q < 32; q++) {
                int idx = (tid + q*128)*4;
                int e = idx >> 6, n = idx & 63;
                float4 hv = __ldcg((const float4*)(hp + idx));
                *(float4*)&hsh[e*68 + n] = hv;
            }
            __syncthreads();
            #pragma unroll 4
            for (int e4 = 0; e4 < H2; e4 += 4) {
                float4 w0 = *(const float4*)&wsh[(gg*2  )*260 + e4];
                float4 w1 = *(const float4*)&wsh[(gg*2+1)*260 + e4];
                float wa[4] = {w0.x, w0.y, w0.z, w0.w};
                float wb[4] = {w1.x, w1.y, w1.z, w1.w};
                #pragma unroll
                for (int k = 0; k < 4; k++) {
                    float4 hv = *(const float4*)&hsh[(e4+k)*68 + ng*4];
                    a00 += hv.x*wa[k]; a01 += hv.x*wb[k];
                    a10 += hv.y*wa[k]; a11 += hv.y*wb[k];
                    a20 += hv.z*wa[k]; a21 += hv.z*wb[k];
                    a30 += hv.w*wa[k]; a31 += hv.w*wb[k];
                }
            }
        } else {
            __syncthreads();
        }
        gsh[(gg*2  )*68 + ng*4 + 0] = a00; gsh[(gg*2+1)*68 + ng*4 + 0] = a01;
        gsh[(gg*2  )*68 + ng*4 + 1] = a10; gsh[(gg*2+1)*68 + ng*4 + 1] = a11;
        gsh[(gg*2  )*68 + ng*4 + 2] = a20; gsh[(gg*2+1)*68 + ng*4 + 2] = a21;
        gsh[(gg*2  )*68 + ng*4 + 3] = a30; gsh[(gg*2+1)*68 + ng*4 + 3] = a31;
        __syncthreads();
        {
            float iv = gsh[(ul_c*4+0)*68 + n_c] + xw0[0];
            float fv = gsh[(ul_c*4+1)*68 + n_c] + xw0[1];
            float gv = gsh[(ul_c*4+2)*68 + n_c] + xw0[2];
            float ov = gsh[(ul_c*4+3)*68 + n_c] + xw0[3];
            c0 = fsig(fv)*c0 + fsig(iv)*__tanhf(gv);
            float h0 = fsig(ov)*__tanhf(c0);
            int ul2 = ul_c + 2;
            float iv1 = gsh[(ul2*4+0)*68 + n_c] + xw1[0];
            float fv1 = gsh[(ul2*4+1)*68 + n_c] + xw1[1];
            float gv1 = gsh[(ul2*4+2)*68 + n_c] + xw1[2];
            float ov1 = gsh[(ul2*4+3)*68 + n_c] + xw1[3];
            c1 = fsig(fv1)*c1 + fsig(iv1)*__tanhf(gv1);
            float h1 = fsig(ov1)*__tanhf(c1);
            int wbuf = (((s+1)&1)*2 + dir)*H2*Ln;
            __stcg(&g_hT[wbuf + (u0+ul_c )*Ln + n_c], h0);
            __stcg(&g_hT[wbuf + (u0+ul2  )*Ln + n_c], h1);
            g_hs[((size_t)t*Ln + n_c)*HIDD + dir*H2 + u0 + ul_c] = h0;
            g_hs[((size_t)t*Ln + n_c)*HIDD + dir*H2 + u0 + ul2 ] = h1;
        }
        if (s < Bz-1) {
            __threadfence();
            __syncthreads();
            if (tid == 0) {
                unsigned c = atomicAdd(&g_barr[dir*8 + s], 1u) + 1u;
                if (c < 64u) {
                    volatile unsigned* p = &g_barr[dir*8 + s];
                    while (*p < 64u) __nanosleep(32);
                }
            }
            __syncthreads();
        }
    }
}

// K4: rank-1 crf projections u,v. 512 blocks x 128, fully vectorized.
__global__ void k_uv(const float* __restrict__ Ws) {
    int row = blockIdx.x, l = row & 63, tid = threadIdx.x;
    const float4* hc = (const float4*)&g_hs[(size_t)row*HIDD];
    const float4* W4 = (const float4*)Ws;
    float4 h0 = hc[tid];
    float4 wu0 = W4[tid],       wv0 = W4[384 + tid];
    float au = h0.x*wu0.x + h0.y*wu0.y + h0.z*wu0.z + h0.w*wu0.w;
    float av = h0.x*wv0.x + h0.y*wv0.y + h0.z*wv0.z + h0.w*wv0.w;
    if (l > 0) {
        float4 hb = hc[tid - 128];
        float4 wu = W4[128 + tid], wv = W4[512 + tid];
        au += hb.x*wu.x + hb.y*wu.y + hb.z*wu.z + hb.w*wu.w;
        av += hb.x*wv.x + hb.y*wv.y + hb.z*wv.z + hb.w*wv.w;
    }
    if (l < 63) {
        float4 hn = hc[tid + 128];
        float4 wu = W4[256 + tid], wv = W4[640 + tid];
        au += hn.x*wu.x + hn.y*wu.y + hn.z*wu.z + hn.w*wu.w;
        av += hn.x*wv.x + hn.y*wv.y + hn.z*wv.z + hn.w*wv.w;
    }
    #pragma unroll
    for (int o = 16; o; o >>= 1) {
        au += __shfl_xor_sync(0xffffffffu, au, o);
        av += __shfl_xor_sync(0xffffffffu, av, o);
    }
    __shared__ float pu[4], pv[4];
    int warp = tid >> 5, lane = tid & 31;
    if (lane == 0) { pu[warp] = au; pv[warp] = av; }
    __syncthreads();
    if (tid == 0) { g_u[row] = pu[0]+pu[1]+pu[2]+pu[3]; g_v[row] = pv[0]+pv[1]+pv[2]+pv[3]; }
}

// K6: p1 = h@W1^T+b1, p2 = h@W2^T+b2. 128 blocks x 256.
__global__ void k_p12(const float* __restrict__ W1, const float* __restrict__ b1,
                      const float* __restrict__ W2, const float* __restrict__ b2) {
    int r0 = blockIdx.x * 4, tid = threadIdx.x;
    __shared__ float hsh[4*512];
    __shared__ float w1sh[128*36];
    __shared__ float w2sh[128*36];
    #pragma unroll
    for (int q = 0; q < 8; q++) { int li = tid + q*256; hsh[li] = g_hs[(size_t)r0*HIDD + li]; }
    int j = tid & 127, rh = tid >> 7;
    float a00 = 0.f, a01 = 0.f, a10 = 0.f, a11 = 0.f;
    for (int e0 = 0; e0 < HIDD; e0 += 32) {
        #pragma unroll
        for (int q = 0; q < 16; q++) {
            int li = tid + q*256;
            int jj = li >> 5, ee = li & 31;
            w1sh[jj*36 + ee] = W1[jj*HIDD + e0 + ee];
            w2sh[jj*36 + ee] = W2[jj*HIDD + e0 + ee];
        }
        __syncthreads();
        #pragma unroll
        for (int e = 0; e < 32; e += 4) {
            float4 h0 = *(const float4*)&hsh[(rh*2    )*512 + e0 + e];
            float4 h1 = *(const float4*)&hsh[(rh*2 + 1)*512 + e0 + e];
            float4 w1v = *(const float4*)&w1sh[j*36 + e];
            float4 w2v = *(const float4*)&w2sh[j*36 + e];
            a00 += h0.x*w1v.x + h0.y*w1v.y + h0.z*w1v.z + h0.w*w1v.w;
            a01 += h0.x*w2v.x + h0.y*w2v.y + h0.z*w2v.z + h0.w*w2v.w;
            a10 += h1.x*w1v.x + h1.y*w1v.y + h1.z*w1v.z + h1.w*w1v.w;
            a11 += h1.x*w2v.x + h1.y*w2v.y + h1.z*w2v.z + h1.w*w2v.w;
        }
        __syncthreads();
    }
    g_p1[(r0 + rh*2    )*RECD + j] = a00 + b1[j];
    g_p2[(r0 + rh*2    )*RECD + j] = a01 + b2[j];
    g_p1[(r0 + rh*2 + 1)*RECD + j] = a10 + b1[j];
    g_p2[(r0 + rh*2 + 1)*RECD + j] = a11 + b2[j];
}

// K7: s[b,i,:] = p1[b,i].p2[b,:], row logsumexp.
// 32 blocks (b, i-quarter) x 256 threads; p1/p2 tiles staged once in smem.
__global__ void k_scores() {
    int b = blockIdx.x >> 2, i0 = (blockIdx.x & 3) * 16, tid = threadIdx.x;
    __shared__ float p1sh[16*132];
    __shared__ float p2sh[64*132];
    // load p1 rows i0..i0+15 (2048 floats) and p2 all 64 rows (8192 floats)
    #pragma unroll
    for (int q = 0; q < 2; q++) {
        int li = (tid + q*256);           // float4 index, 512 total
        int rr = li >> 5, e4 = li & 31;
        *(float4*)&p1sh[rr*132 + e4*4] = *(const float4*)&g_p1[(b*Ln + i0 + rr)*RECD + e4*4];
    }
    #pragma unroll
    for (int q = 0; q < 8; q++) {
        int li = (tid + q*256);           // float4 index, 2048 total
        int rr = li >> 5, e4 = li & 31;
        *(float4*)&p2sh[rr*132 + e4*4] = *(const float4*)&g_p2[(b*Ln + rr)*RECD + e4*4];
    }
    __syncthreads();
    int i_l = tid >> 4, jg = tid & 15;
    int i = i0 + i_l;
    float dots[4];
    #pragma unroll
    for (int q = 0; q < 4; q++) dots[q] = 0.f;
    #pragma unroll 8
    for (int e4 = 0; e4 < 32; e4++) {
        float4 a = *(const float4*)&p1sh[i_l*132 + e4*4];
        #pragma unroll
        for (int q = 0; q < 4; q++) {
            int j = jg + q*16;
            float4 bv = *(const float4*)&p2sh[j*132 + e4*4];
            dots[q] += a.x*bv.x + a.y*bv.y + a.z*bv.z + a.w*bv.w;
        }
    }
    float m = -INFINITY;
    #pragma unroll
    for (int q = 0; q < 4; q++) {
        g_s[((size_t)b*Ln + i)*Ln + jg + q*16] = dots[q];
        m = fmaxf(m, dots[q]);
    }
    #pragma unroll
    for (int o = 8; o; o >>= 1) m = fmaxf(m, __shfl_xor_sync(0xffffffffu, m, o));
    float sum = 0.f;
    #pragma unroll
    for (int q = 0; q < 4; q++) sum += __expf(dots[q] - m);
    #pragma unroll
    for (int o = 8; o; o >>= 1) sum += __shfl_xor_sync(0xffffffffu, sum, o);
    if (jg == 0) g_rowlse[b*Ln + i] = m + __logf(sum);
}

// K8: Eisner inside log-partition. 8 blocks x 1024 (64 half-warp groups),
// charts in smem (dyn 66.5KB), fast exp/log, 4-level shuffles.
__global__ void k_eisner(const float* __restrict__ bs) {
    extern __shared__ float smf[];
    float* Cr = smf;         float* Cl = smf + 4160;
    float* Ir = smf + 8320;  float* Il = smf + 12480;
    __shared__ float ush[64], vsh[64];
    int b = blockIdx.x, tid = threadIdx.x;
    if (tid < 64) { ush[tid] = g_u[b*Ln + tid] + bs[0]; vsh[tid] = g_v[b*Ln + tid]; }
    for (int idx = tid; idx < 4160; idx += 1024) {
        int i = idx / 65, jj = idx % 65;
        float dv = (jj < 64 && i == jj) ? 0.0f : NEGV;
        Cr[idx] = dv; Cl[idx] = dv; Ir[idx] = NEGV; Il[idx] = NEGV;
    }
    __syncthreads();
    int grp = tid >> 4, l16 = tid & 15;
    for (int w = 1; w < Ln; w++) {
        int spans = Ln - w;
        // phase 1: one round (spans <= 63 < 64 groups)
        {
            bool valid = grp < spans;
            int i = valid ? grp : 0, jn = i + w;
            float vv[4]; float m = -INFINITY;
            #pragma unroll
            for (int q = 0; q < 4; q++) {
                int o = l16 + q*16;
                int k = i + o;
                float v = (valid && o < w) ? Cr[i*65 + k] + Cl[(k+1)*65 + jn] : -INFINITY;
                vv[q] = v; m = fmaxf(m, v);
            }
            #pragma unroll
            for (int o = 8; o; o >>= 1) m = fmaxf(m, __shfl_xor_sync(0xffffffffu, m, o));
            float sum = 0.f;
            #pragma unroll
            for (int q = 0; q < 4; q++) sum += __expf(vv[q] - m);
            #pragma unroll
            for (int o = 8; o; o >>= 1) sum += __shfl_xor_sync(0xffffffffu, sum, o);
            float inc = m + __logf(sum);
            if (valid && l16 == 0) {
                Ir[i*65 + jn] = inc + ush[i]  + vsh[jn];
                Il[i*65 + jn] = inc + ush[jn] + vsh[i];
            }
        }
        __syncthreads();
        // phase 2: up to 2 rounds
        int rounds = (2*spans + 63) >> 6;
        for (int r = 0; r < rounds; r++) {
            int task = r*64 + grp;
            bool valid = task < 2*spans;
            int sp = task >> 1, ch = task & 1;
            int i = valid ? sp : 0, jn = i + w;
            float vv[4]; float m = -INFINITY;
            #pragma unroll
            for (int q = 0; q < 4; q++) {
                int o = l16 + q*16;
                float v = -INFINITY;
                if (valid && o < w) {
                    if (ch == 0) { int k = i + 1 + o; v = Ir[i*65 + k] + Cr[k*65 + jn]; }
                    else         { int k = i + o;     v = Cl[i*65 + k] + Il[k*65 + jn]; }
                }
                vv[q] = v; m = fmaxf(m, v);
            }
            #pragma unroll
            for (int o = 8; o; o >>= 1) m = fmaxf(m, __shfl_xor_sync(0xffffffffu, m, o));
            float sum = 0.f;
            #pragma unroll
            for (int q = 0; q < 4; q++) sum += __expf(vv[q] - m);
            #pragma unroll
            for (int o = 8; o; o >>= 1) sum += __shfl_xor_sync(0xffffffffu, sum, o);
            float res = m + __logf(sum);
            if (valid && l16 == 0) {
                if (ch == 0) Cr[i*65 + jn] = res; else Cl[i*65 + jn] = res;
            }
        }
        __syncthreads();
    }
    if (tid == 0) g_logZ[b] = Cr[Ln - 1];
}

// K9: gather jp at (heads[b,m], m), LSE over m, loss. 1 block x 256.
__global__ void k_final(const int* __restrict__ heads, const float* __restrict__ prior,
                        const float* __restrict__ bs, float* __restrict__ out) {
    int tid = threadIdx.x, warp = tid >> 5, lane = tid & 31;
    __shared__ float sb[8];
    int b = warp;
    float bsv = bs[0];
    int m1 = lane + 1, m2 = lane + 33;
    float v1, v2 = -INFINITY;
    {
        int hd = heads[b*Ln + m1];
        v1 = g_u[b*Ln + hd] + g_v[b*Ln + m1] + bsv
           + g_s[((size_t)b*Ln + hd)*Ln + m1] - g_rowlse[b*Ln + hd]
           + prior[((size_t)b*Ln + hd)*Ln + m1] * (1.0f/64.0f);
    }
    if (m2 < Ln) {
        int hd = heads[b*Ln + m2];
        v2 = g_u[b*Ln + hd] + g_v[b*Ln + m2] + bsv
           + g_s[((size_t)b*Ln + hd)*Ln + m2] - g_rowlse[b*Ln + hd]
           + prior[((size_t)b*Ln + hd)*Ln + m2] * (1.0f/64.0f);
    }
    float mx = fmaxf(v1, v2);
    #pragma unroll
    for (int o = 16; o; o >>= 1) mx = fmaxf(mx, __shfl_xor_sync(0xffffffffu, mx, o));
    float sum = __expf(v1 - mx) + __expf(v2 - mx);
    #pragma unroll
    for (int o = 16; o; o >>= 1) sum += __shfl_xor_sync(0xffffffffu, sum, o);
    if (lane == 0) sb[b] = (mx + __logf(sum)) - g_logZ[b];
    __syncthreads();
    if (tid == 0) {
        float t = 0.f;
        for (int q = 0; q < 8; q++) t += sb[q];
        out[0] = -t * (1.0f/8.0f);
    }
}

extern "C" void kernel_launch(void* const* d_in, const int* in_sizes, int n_in,
                              void* d_out, int out_size) {
    const int*   sents = (const int*)  d_in[0];
    const float* mask  = (const float*)d_in[1];
    const float* prior = (const float*)d_in[2];
    const int*   heads = (const int*)  d_in[3];
    const float* emb   = (const float*)d_in[4];
    const float* Wih_f = (const float*)d_in[5];
    const float* Whh_f = (const float*)d_in[6];
    const float* bih_f = (const float*)d_in[7];
    const float* bhh_f = (const float*)d_in[8];
    const float* Wih_b = (const float*)d_in[9];
    const float* Whh_b = (const float*)d_in[10];
    const float* bih_b = (const float*)d_in[11];
    const float* bhh_b = (const float*)d_in[12];
    const float* W1    = (const float*)d_in[13];
    const float* b1    = (const float*)d_in[14];
    const float* W2    = (const float*)d_in[15];
    const float* b2    = (const float*)d_in[16];
    const float* Ws    = (const float*)d_in[17];
    const float* bsv   = (const float*)d_in[18];
    float* out = (float*)d_out;
    (void)in_sizes; (void)n_in; (void)out_size;

    cudaFuncSetAttribute(k_lstm_all, cudaFuncAttributeMaxDynamicSharedMemorySize, 22656*4);
    cudaFuncSetAttribute(k_eisner,   cudaFuncAttributeMaxDynamicSharedMemorySize, 16640*4);

    k_embed<<<Bz*Ln, 256>>>(sents, mask, emb);
    dim3 g2(8, 16, 2);
    k_xw<<<g2, 256>>>(Wih_f, bih_f, bhh_f, Wih_b, bih_b, bhh_b);
    k_lstm_all<<<128, 128, 22656*4>>>(Whh_f, Whh_b);
    k_uv<<<Bz*Ln, 128>>>(Ws);
    k_p12<<<128, 256>>>(W1, b1, W2, b2);
    k_scores<<<32, 256>>>();
    k_eisner<<<Bz, 1024, 16640*4>>>(bsv);
    k_final<<<1, 256>>>(heads, prior, bsv, out);
}

// round 8
// speedup vs baseline: 1.4649x; 1.0865x over previous
#include <cuda_runtime.h>
#include <math.h>

#define Bz 8
#define Ln 64
#define WL 32
#define EMBD 256
#define H2 256
#define HIDD 512
#define RECD 128
#define NEGV -1000000000.0f

__device__ float g_embeds[Bz*Ln*EMBD];
__device__ float g_xw[2*Bz*Ln*1024];
__device__ float g_hT[4*H2*Ln];          // [buf(2)][dir(2)][unit 256][n 64]
__device__ unsigned g_barr[16];          // [dir][step]
__device__ float g_hs[Bz*Ln*HIDD];
__device__ float g_u[Bz*Ln];
__device__ float g_v[Bz*Ln];
__device__ float g_p1[Bz*Ln*RECD];
__device__ float g_p2[Bz*Ln*RECD];
__device__ float g_s[Bz*Ln*Ln];
__device__ float g_rowlse[Bz*Ln];
__device__ float g_logZ[Bz];

// K1: word-average embeddings. 512 blocks x 256 threads.
__global__ void k_embed(const int* __restrict__ sents, const float* __restrict__ mask,
                        const float* __restrict__ emb) {
    int row = blockIdx.x, tid = threadIdx.x;
    __shared__ int sw[WL]; __shared__ float sm[WL]; __shared__ float sden;
    if (tid < WL) { sw[tid] = sents[row*WL + tid]; sm[tid] = mask[row*WL + tid]; }
    __syncthreads();
    if (tid == 0) {
        float e = 0.f;
        for (int w = 0; w < WL; w++) e += sm[w];
        sden = e + (e == 0.0f ? 1.0f : 0.0f);
    }
    __syncthreads();
    float acc = 0.f;
    #pragma unroll 8
    for (int w = 0; w < WL; w++) acc += emb[(size_t)sw[w]*EMBD + tid] * sm[w];
    g_embeds[row*EMBD + tid] = acc / sden;
}

// K2: xW = embeds @ Wih^T + (bih+bhh), both dirs. grid (8,16,2) x 256.
// Also zeroes the LSTM grid-barrier counters (runs before k_lstm_all each replay).
__global__ void k_xw(const float* __restrict__ Wf, const float* __restrict__ bif,
                     const float* __restrict__ bhf,
                     const float* __restrict__ Wb, const float* __restrict__ bib,
                     const float* __restrict__ bhb) {
    if (blockIdx.x == 0 && blockIdx.y == 0 && blockIdx.z == 0 && threadIdx.x < 16)
        g_barr[threadIdx.x] = 0u;
    int dir = blockIdx.z;
    const float* W  = dir ? Wb  : Wf;
    const float* bi = dir ? bib : bif;
    const float* bh = dir ? bhb : bhf;
    int r0 = blockIdx.x * 64, g0 = blockIdx.y * 64;
    __shared__ float Ash[64*68];
    __shared__ float Wsh[64*68];
    int tid = threadIdx.x;
    int ri = tid & 15, gi = tid >> 4;
    float acc[4][4] = {};
    for (int e0 = 0; e0 < EMBD; e0 += 64) {
        #pragma unroll 4
        for (int q = 0; q < 16; q++) {
            int li = tid + q*256;
            int xx = li >> 6, ee = li & 63;
            Ash[ee*68 + xx] = g_embeds[(r0+xx)*EMBD + e0 + ee];
            Wsh[ee*68 + xx] = W[(g0+xx)*EMBD + e0 + ee];
        }
        __syncthreads();
        #pragma unroll 8
        for (int e = 0; e < 64; e++) {
            float4 av = *(const float4*)&Ash[e*68 + ri*4];
            float4 wv = *(const float4*)&Wsh[e*68 + gi*4];
            float aa[4] = {av.x, av.y, av.z, av.w};
            float ww[4] = {wv.x, wv.y, wv.z, wv.w};
            #pragma unroll
            for (int a = 0; a < 4; a++)
                #pragma unroll
                for (int g = 0; g < 4; g++) acc[a][g] += aa[a]*ww[g];
        }
        __syncthreads();
    }
    #pragma unroll
    for (int a = 0; a < 4; a++)
        #pragma unroll
        for (int g = 0; g < 4; g++) {
            int row = r0 + ri*4 + a, gg = g0 + gi*4 + g;
            g_xw[((size_t)dir*Bz*Ln + row)*1024 + gg] = acc[a][g] + bi[gg] + bh[gg];
        }
}

__device__ __forceinline__ float fsig(float x) {
    return __fdividef(1.0f, 1.0f + __expf(-x));
}

// K3: persistent LSTM — all 8 steps in one kernel.
// 128 blocks x 128 threads. Block (dir, ub) owns 4 units (16 gate-cols).
__global__ void k_lstm_all(const float* __restrict__ Whh_f, const float* __restrict__ Whh_b) {
    extern __shared__ float smem[];
    float* wsh = smem;                  // [gc 16][e 256] pitch 260
    float* hsh = smem + 4160;           // [e 256][n 64] pitch 68
    float* gsh = smem + 4160 + 17408;   // [gc 16][n 64] pitch 68
    int bx = blockIdx.x;
    int dir = bx >> 6, ub = bx & 63, u0 = ub*4;
    const float* Whh = dir ? Whh_b : Whh_f;
    int tid = threadIdx.x;

    #pragma unroll 8
    for (int q = 0; q < 32; q++) {
        int li = tid + q*128;
        int gc = li >> 8, e = li & 255;
        int ul = gc >> 2, gate = gc & 3;
        wsh[gc*260 + e] = Whh[(gate*H2 + u0 + ul)*H2 + e];
    }
    int ng = tid >> 3, gg = tid & 7;
    int n_c = tid & 63, ul_c = tid >> 6;
    float c0 = 0.f, c1 = 0.f;
    __syncthreads();

    for (int s = 0; s < Bz; s++) {
        int t = dir ? (Bz-1-s) : s;
        const float* xb = &g_xw[((size_t)(dir*Bz*Ln + t*Ln + n_c))*1024 + u0 + ul_c];
        float xw0[4], xw1[4];
        #pragma unroll
        for (int g = 0; g < 4; g++) { xw0[g] = xb[g*256]; xw1[g] = xb[g*256 + 2]; }

        float a00=0.f,a01=0.f,a10=0.f,a11=0.f,a20=0.f,a21=0.f,a30=0.f,a31=0.f;
        if (s > 0) {
            const float* hp = &g_hT[((s&1)*2 + dir)*H2*Ln];
            #pragma unroll 8
            for (int q = 0; q < 32; q++) {
                int idx = (tid + q*128)*4;
                int e = idx >> 6, n = idx & 63;
                float4 hv = __ldcg((const float4*)(hp + idx));
                *(float4*)&hsh[e*68 + n] = hv;
            }
            __syncthreads();
            #pragma unroll 4
            for (int e4 = 0; e4 < H2; e4 += 4) {
                float4 w0 = *(const float4*)&wsh[(gg*2  )*260 + e4];
                float4 w1 = *(const float4*)&wsh[(gg*2+1)*260 + e4];
                float wa[4] = {w0.x, w0.y, w0.z, w0.w};
                float wb[4] = {w1.x, w1.y, w1.z, w1.w};
                #pragma unroll
                for (int k = 0; k < 4; k++) {
                    float4 hv = *(const float4*)&hsh[(e4+k)*68 + ng*4];
                    a00 += hv.x*wa[k]; a01 += hv.x*wb[k];
                    a10 += hv.y*wa[k]; a11 += hv.y*wb[k];
                    a20 += hv.z*wa[k]; a21 += hv.z*wb[k];
                    a30 += hv.w*wa[k]; a31 += hv.w*wb[k];
                }
            }
        } else {
            __syncthreads();
        }
        gsh[(gg*2  )*68 + ng*4 + 0] = a00; gsh[(gg*2+1)*68 + ng*4 + 0] = a01;
        gsh[(gg*2  )*68 + ng*4 + 1] = a10; gsh[(gg*2+1)*68 + ng*4 + 1] = a11;
        gsh[(gg*2  )*68 + ng*4 + 2] = a20; gsh[(gg*2+1)*68 + ng*4 + 2] = a21;
        gsh[(gg*2  )*68 + ng*4 + 3] = a30; gsh[(gg*2+1)*68 + ng*4 + 3] = a31;
        __syncthreads();
        {
            float iv = gsh[(ul_c*4+0)*68 + n_c] + xw0[0];
            float fv = gsh[(ul_c*4+1)*68 + n_c] + xw0[1];
            float gv = gsh[(ul_c*4+2)*68 + n_c] + xw0[2];
            float ov = gsh[(ul_c*4+3)*68 + n_c] + xw0[3];
            c0 = fsig(fv)*c0 + fsig(iv)*__tanhf(gv);
            float h0 = fsig(ov)*__tanhf(c0);
            int ul2 = ul_c + 2;
            float iv1 = gsh[(ul2*4+0)*68 + n_c] + xw1[0];
            float fv1 = gsh[(ul2*4+1)*68 + n_c] + xw1[1];
            float gv1 = gsh[(ul2*4+2)*68 + n_c] + xw1[2];
            float ov1 = gsh[(ul2*4+3)*68 + n_c] + xw1[3];
            c1 = fsig(fv1)*c1 + fsig(iv1)*__tanhf(gv1);
            float h1 = fsig(ov1)*__tanhf(c1);
            int wbuf = (((s+1)&1)*2 + dir)*H2*Ln;
            __stcg(&g_hT[wbuf + (u0+ul_c )*Ln + n_c], h0);
            __stcg(&g_hT[wbuf + (u0+ul2  )*Ln + n_c], h1);
            g_hs[((size_t)t*Ln + n_c)*HIDD + dir*H2 + u0 + ul_c] = h0;
            g_hs[((size_t)t*Ln + n_c)*HIDD + dir*H2 + u0 + ul2 ] = h1;
        }
        if (s < Bz-1) {
            __threadfence();
            __syncthreads();
            if (tid == 0) {
                unsigned c = atomicAdd(&g_barr[dir*8 + s], 1u) + 1u;
                if (c < 64u) {
                    volatile unsigned* p = &g_barr[dir*8 + s];
                    while (*p < 64u) { }
                }
            }
            __syncthreads();
        }
    }
}

// K4 (fused): blocks 0..255 -> uv (2 rows each); blocks 256..383 -> p12.
__global__ void k_uvp12(const float* __restrict__ Ws,
                        const float* __restrict__ W1, const float* __restrict__ b1,
                        const float* __restrict__ W2, const float* __restrict__ b2) {
    int tid = threadIdx.x;
    if (blockIdx.x < 256) {
        // ---- uv: rank-1 crf projections ----
        int row = blockIdx.x*2 + (tid >> 7);
        int t128 = tid & 127;
        int l = row & 63;
        const float4* hc = (const float4*)&g_hs[(size_t)row*HIDD];
        const float4* W4 = (const float4*)Ws;
        float4 h0 = hc[t128];
        float4 wu0 = W4[t128], wv0 = W4[384 + t128];
        float au = h0.x*wu0.x + h0.y*wu0.y + h0.z*wu0.z + h0.w*wu0.w;
        float av = h0.x*wv0.x + h0.y*wv0.y + h0.z*wv0.z + h0.w*wv0.w;
        if (l > 0) {
            float4 hb = hc[t128 - 128];
            float4 wu = W4[128 + t128], wv = W4[512 + t128];
            au += hb.x*wu.x + hb.y*wu.y + hb.z*wu.z + hb.w*wu.w;
            av += hb.x*wv.x + hb.y*wv.y + hb.z*wv.z + hb.w*wv.w;
        }
        if (l < 63) {
            float4 hn = hc[t128 + 128];
            float4 wu = W4[256 + t128], wv = W4[640 + t128];
            au += hn.x*wu.x + hn.y*wu.y + hn.z*wu.z + hn.w*wu.w;
            av += hn.x*wv.x + hn.y*wv.y + hn.z*wv.z + hn.w*wv.w;
        }
        #pragma unroll
        for (int o = 16; o; o >>= 1) {
            au += __shfl_xor_sync(0xffffffffu, au, o);
            av += __shfl_xor_sync(0xffffffffu, av, o);
        }
        __shared__ float pu[8], pv[8];
        int warp = tid >> 5, lane = tid & 31;
        if (lane == 0) { pu[warp] = au; pv[warp] = av; }
        __syncthreads();
        if ((tid & 127) == 0) {
            int wb = (tid >> 7)*4;
            g_u[row] = pu[wb]+pu[wb+1]+pu[wb+2]+pu[wb+3];
            g_v[row] = pv[wb]+pv[wb+1]+pv[wb+2]+pv[wb+3];
        }
        return;
    }
    // ---- p12: p1 = h@W1^T+b1, p2 = h@W2^T+b2 ----
    int r0 = (blockIdx.x - 256) * 4;
    __shared__ float hsh[4*512];
    __shared__ float w1sh[128*36];
    __shared__ float w2sh[128*36];
    #pragma unroll
    for (int q = 0; q < 8; q++) { int li = tid + q*256; hsh[li] = g_hs[(size_t)r0*HIDD + li]; }
    int j = tid & 127, rh = tid >> 7;
    float a00 = 0.f, a01 = 0.f, a10 = 0.f, a11 = 0.f;
    for (int e0 = 0; e0 < HIDD; e0 += 32) {
        #pragma unroll
        for (int q = 0; q < 16; q++) {
            int li = tid + q*256;
            int jj = li >> 5, ee = li & 31;
            w1sh[jj*36 + ee] = W1[jj*HIDD + e0 + ee];
            w2sh[jj*36 + ee] = W2[jj*HIDD + e0 + ee];
        }
        __syncthreads();
        #pragma unroll
        for (int e = 0; e < 32; e += 4) {
            float4 h0 = *(const float4*)&hsh[(rh*2    )*512 + e0 + e];
            float4 h1 = *(const float4*)&hsh[(rh*2 + 1)*512 + e0 + e];
            float4 w1v = *(const float4*)&w1sh[j*36 + e];
            float4 w2v = *(const float4*)&w2sh[j*36 + e];
            a00 += h0.x*w1v.x + h0.y*w1v.y + h0.z*w1v.z + h0.w*w1v.w;
            a01 += h0.x*w2v.x + h0.y*w2v.y + h0.z*w2v.z + h0.w*w2v.w;
            a10 += h1.x*w1v.x + h1.y*w1v.y + h1.z*w1v.z + h1.w*w1v.w;
            a11 += h1.x*w2v.x + h1.y*w2v.y + h1.z*w2v.z + h1.w*w2v.w;
        }
        __syncthreads();
    }
    g_p1[(r0 + rh*2    )*RECD + j] = a00 + b1[j];
    g_p2[(r0 + rh*2    )*RECD + j] = a01 + b2[j];
    g_p1[(r0 + rh*2 + 1)*RECD + j] = a10 + b1[j];
    g_p2[(r0 + rh*2 + 1)*RECD + j] = a11 + b2[j];
}

// K5 (fused): blocks 0..7 -> Eisner (single-phase, 1 sync/width);
//             blocks 8..39 -> scores (one thread per (i,j)).
__global__ void k_eis_sc(const float* __restrict__ bs) {
    extern __shared__ float smf[];
    int tid = threadIdx.x;
    if (blockIdx.x < 8) {
        float* Cr = smf;         float* Cl = smf + 4160;
        float* Ir = smf + 8320;  float* Il = smf + 12480;
        __shared__ float ush[64], vsh[64];
        int b = blockIdx.x;
        if (tid < 64) { ush[tid] = g_u[b*Ln + tid] + bs[0]; vsh[tid] = g_v[b*Ln + tid]; }
        for (int idx = tid; idx < 4160; idx += 1024) {
            int i = idx / 65, jj = idx % 65;
            float dv = (jj < 64 && i == jj) ? 0.0f : NEGV;
            Cr[idx] = dv; Cl[idx] = dv; Ir[idx] = NEGV; Il[idx] = NEGV;
        }
        __syncthreads();
        int grp = tid >> 4, l16 = tid & 15;
        for (int w = 1; w < Ln; w++) {
            int spans = Ln - w;
            bool valid = grp < spans;
            int i = valid ? grp : 0, jn = i + w;
            int nq = (w + 15) >> 4;
            float t_in[4], t_cr[4], t_cl[4];
            float m_in = -INFINITY, m_cr = -INFINITY, m_cl = -INFINITY;
            #pragma unroll
            for (int q = 0; q < 4; q++) {
                t_in[q] = -INFINITY; t_cr[q] = -INFINITY; t_cl[q] = -INFINITY;
                if (q < nq) {
                    int o = l16 + q*16;
                    if (valid && o < w) {
                        int k = i + o;
                        t_in[q] = Cr[i*65 + k] + Cl[(k+1)*65 + jn];
                        if (o < w - 1) {
                            int k2 = k + 1;
                            t_cr[q] = Ir[i*65 + k2] + Cr[k2*65 + jn];
                            t_cl[q] = Cl[i*65 + k2] + Il[k2*65 + jn];
                        }
                    }
                }
                m_in = fmaxf(m_in, t_in[q]);
                m_cr = fmaxf(m_cr, t_cr[q]);
                m_cl = fmaxf(m_cl, t_cl[q]);
            }
            #pragma unroll
            for (int o = 8; o; o >>= 1) {
                m_in = fmaxf(m_in, __shfl_xor_sync(0xffffffffu, m_in, o));
                m_cr = fmaxf(m_cr, __shfl_xor_sync(0xffffffffu, m_cr, o));
                m_cl = fmaxf(m_cl, __shfl_xor_sync(0xffffffffu, m_cl, o));
            }
            float ms_in = fmaxf(m_in, -1e30f);
            float ms_cr = fmaxf(m_cr, -1e30f);
            float ms_cl = fmaxf(m_cl, -1e30f);
            float s_in = 0.f, s_cr = 0.f, s_cl = 0.f;
            #pragma unroll
            for (int q = 0; q < 4; q++) {
                s_in += __expf(t_in[q] - ms_in);
                s_cr += __expf(t_cr[q] - ms_cr);
                s_cl += __expf(t_cl[q] - ms_cl);
            }
            #pragma unroll
            for (int o = 8; o; o >>= 1) {
                s_in += __shfl_xor_sync(0xffffffffu, s_in, o);
                s_cr += __shfl_xor_sync(0xffffffffu, s_cr, o);
                s_cl += __shfl_xor_sync(0xffffffffu, s_cl, o);
            }
            if (valid && l16 == 0) {
                float inc = ms_in + __logf(s_in);
                float irv = inc + ush[i]  + vsh[jn];
                float ilv = inc + ush[jn] + vsh[i];
                Ir[i*65 + jn] = irv;
                Il[i*65 + jn] = ilv;
                float lcr = ms_cr + __logf(s_cr);
                float M = fmaxf(lcr, irv);
                Cr[i*65 + jn] = M + __logf(__expf(lcr - M) + __expf(irv - M));
                float lcl = ms_cl + __logf(s_cl);
                float Ml = fmaxf(lcl, ilv);
                Cl[i*65 + jn] = Ml + __logf(__expf(lcl - Ml) + __expf(ilv - Ml));
            }
            __syncthreads();
        }
        if (tid == 0) g_logZ[b] = Cr[Ln - 1];
        return;
    }
    // ---- scores: one thread per (i_local, j) ----
    int sb = blockIdx.x - 8;
    int b = sb >> 2, i0 = (sb & 3) * 16;
    float* p1sh = smf;              // 16 x 132
    float* p2sh = smf + 16*132;     // 64 x 132
    __shared__ float mm[32], ss[32];
    if (tid < 512) {
        int rr = tid >> 5, e4 = tid & 31;
        *(float4*)&p1sh[rr*132 + e4*4] = *(const float4*)&g_p1[(b*Ln + i0 + rr)*RECD + e4*4];
    }
    #pragma unroll
    for (int q = 0; q < 2; q++) {
        int li = tid + q*1024;
        int rr = li >> 5, e4 = li & 31;
        *(float4*)&p2sh[rr*132 + e4*4] = *(const float4*)&g_p2[(b*Ln + rr)*RECD + e4*4];
    }
    __syncthreads();
    int i_l = tid >> 6, j = tid & 63;
    float dot = 0.f;
    #pragma unroll 8
    for (int e4 = 0; e4 < 32; e4++) {
        float4 a = *(const float4*)&p1sh[i_l*132 + e4*4];
        float4 bv = *(const float4*)&p2sh[j*132 + e4*4];
        dot += a.x*bv.x + a.y*bv.y + a.z*bv.z + a.w*bv.w;
    }
    int i = i0 + i_l;
    g_s[((size_t)b*Ln + i)*Ln + j] = dot;
    float m = dot;
    #pragma unroll
    for (int o = 16; o; o >>= 1) m = fmaxf(m, __shfl_xor_sync(0xffffffffu, m, o));
    float sum = __expf(dot - m);
    #pragma unroll
    for (int o = 16; o; o >>= 1) sum += __shfl_xor_sync(0xffffffffu, sum, o);
    int warp = tid >> 5, lane = tid & 31;
    if (lane == 0) { mm[warp] = m; ss[warp] = sum; }
    __syncthreads();
    if (tid < 16) {
        float m0 = mm[tid*2], m1 = mm[tid*2+1];
        float M = fmaxf(m0, m1);
        float S = ss[tid*2]*__expf(m0 - M) + ss[tid*2+1]*__expf(m1 - M);
        g_rowlse[b*Ln + i0 + tid] = M + __logf(S);
    }
}

// K6: gather jp at (heads[b,m], m), LSE over m, loss. 1 block x 256.
__global__ void k_final(const int* __restrict__ heads, const float* __restrict__ prior,
                        const float* __restrict__ bs, float* __restrict__ out) {
    int tid = threadIdx.x, warp = tid >> 5, lane = tid & 31;
    __shared__ float sb[8];
    int b = warp;
    float bsv = bs[0];
    int m1 = lane + 1, m2 = lane + 33;
    float v1, v2 = -INFINITY;
    {
        int hd = heads[b*Ln + m1];
        v1 = g_u[b*Ln + hd] + g_v[b*Ln + m1] + bsv
           + g_s[((size_t)b*Ln + hd)*Ln + m1] - g_rowlse[b*Ln + hd]
           + prior[((size_t)b*Ln + hd)*Ln + m1] * (1.0f/64.0f);
    }
    if (m2 < Ln) {
        int hd = heads[b*Ln + m2];
        v2 = g_u[b*Ln + hd] + g_v[b*Ln + m2] + bsv
           + g_s[((size_t)b*Ln + hd)*Ln + m2] - g_rowlse[b*Ln + hd]
           + prior[((size_t)b*Ln + hd)*Ln + m2] * (1.0f/64.0f);
    }
    float mx = fmaxf(v1, v2);
    #pragma unroll
    for (int o = 16; o; o >>= 1) mx = fmaxf(mx, __shfl_xor_sync(0xffffffffu, mx, o));
    float sum = __expf(v1 - mx) + __expf(v2 - mx);
    #pragma unroll
    for (int o = 16; o; o >>= 1) sum += __shfl_xor_sync(0xffffffffu, sum, o);
    if (lane == 0) sb[b] = (mx + __logf(sum)) - g_logZ[b];
    __syncthreads();
    if (tid == 0) {
        float t = 0.f;
        for (int q = 0; q < 8; q++) t += sb[q];
        out[0] = -t * (1.0f/8.0f);
    }
}

extern "C" void kernel_launch(void* const* d_in, const int* in_sizes, int n_in,
                              void* d_out, int out_size) {
    const int*   sents = (const int*)  d_in[0];
    const float* mask  = (const float*)d_in[1];
    const float* prior = (const float*)d_in[2];
    const int*   heads = (const int*)  d_in[3];
    const float* emb   = (const float*)d_in[4];
    const float* Wih_f = (const float*)d_in[5];
    const float* Whh_f = (const float*)d_in[6];
    const float* bih_f = (const float*)d_in[7];
    const float* bhh_f = (const float*)d_in[8];
    const float* Wih_b = (const float*)d_in[9];
    const float* Whh_b = (const float*)d_in[10];
    const float* bih_b = (const float*)d_in[11];
    const float* bhh_b = (const float*)d_in[12];
    const float* W1    = (const float*)d_in[13];
    const float* b1    = (const float*)d_in[14];
    const float* W2    = (const float*)d_in[15];
    const float* b2    = (const float*)d_in[16];
    const float* Ws    = (const float*)d_in[17];
    const float* bsv   = (const float*)d_in[18];
    float* out = (float*)d_out;
    (void)in_sizes; (void)n_in; (void)out_size;

    cudaFuncSetAttribute(k_lstm_all, cudaFuncAttributeMaxDynamicSharedMemorySize, 22656*4);
    cudaFuncSetAttribute(k_eis_sc,   cudaFuncAttributeMaxDynamicSharedMemorySize, 16640*4);

    k_embed<<<Bz*Ln, 256>>>(sents, mask, emb);
    dim3 g2(8, 16, 2);
    k_xw<<<g2, 256>>>(Wih_f, bih_f, bhh_f, Wih_b, bih_b, bhh_b);
    k_lstm_all<<<128, 128, 22656*4>>>(Whh_f, Whh_b);
    k_uvp12<<<384, 256>>>(Ws, W1, b1, W2, b2);
    k_eis_sc<<<40, 1024, 16640*4>>>(bsv);
    k_final<<<1, 256>>>(heads, prior, bsv, out);
}

// round 9
// speedup vs baseline: 1.4832x; 1.0125x over previous
#include <cuda_runtime.h>
#include <math.h>

#define Bz 8
#define Ln 64
#define WL 32
#define EMBD 256
#define H2 256
#define HIDD 512
#define RECD 128
#define NEGV -1000000000.0f

__device__ float g_embeds[Bz*Ln*EMBD];
__device__ float g_xw[2*Bz*Ln*1024];
__device__ float g_hT[4*H2*Ln];          // [buf(2)][dir(2)][unit 256][n 64]
__device__ unsigned g_barr[16];          // [dir][step]
__device__ float g_hs[Bz*Ln*HIDD];
__device__ float g_u[Bz*Ln];
__device__ float g_v[Bz*Ln];
__device__ float g_p1[Bz*Ln*RECD];
__device__ float g_p2[Bz*Ln*RECD];
__device__ float g_s[Bz*Ln*Ln];
__device__ float g_rowlse[Bz*Ln];
__device__ float g_logZ[Bz];

// K1: word-average embeddings. 512 blocks x 256 threads.
__global__ void k_embed(const int* __restrict__ sents, const float* __restrict__ mask,
                        const float* __restrict__ emb) {
    int row = blockIdx.x, tid = threadIdx.x;
    __shared__ int sw[WL]; __shared__ float sm[WL]; __shared__ float sden;
    if (tid < WL) { sw[tid] = sents[row*WL + tid]; sm[tid] = mask[row*WL + tid]; }
    __syncthreads();
    if (tid == 0) {
        float e = 0.f;
        for (int w = 0; w < WL; w++) e += sm[w];
        sden = e + (e == 0.0f ? 1.0f : 0.0f);
    }
    __syncthreads();
    float acc = 0.f;
    #pragma unroll 8
    for (int w = 0; w < WL; w++) acc += emb[(size_t)sw[w]*EMBD + tid] * sm[w];
    g_embeds[row*EMBD + tid] = acc / sden;
}

// K2: xW = embeds @ Wih^T + (bih+bhh), both dirs. grid (8,16,2) x 256.
// Also zeroes the LSTM grid-barrier counters (runs before k_lstm_all each replay).
__global__ void k_xw(const float* __restrict__ Wf, const float* __restrict__ bif,
                     const float* __restrict__ bhf,
                     const float* __restrict__ Wb, const float* __restrict__ bib,
                     const float* __restrict__ bhb) {
    if (blockIdx.x == 0 && blockIdx.y == 0 && blockIdx.z == 0 && threadIdx.x < 16)
        g_barr[threadIdx.x] = 0u;
    int dir = blockIdx.z;
    const float* W  = dir ? Wb  : Wf;
    const float* bi = dir ? bib : bif;
    const float* bh = dir ? bhb : bhf;
    int r0 = blockIdx.x * 64, g0 = blockIdx.y * 64;
    __shared__ float Ash[64*68];
    __shared__ float Wsh[64*68];
    int tid = threadIdx.x;
    int ri = tid & 15, gi = tid >> 4;
    float acc[4][4] = {};
    for (int e0 = 0; e0 < EMBD; e0 += 64) {
        #pragma unroll 4
        for (int q = 0; q < 16; q++) {
            int li = tid + q*256;
            int xx = li >> 6, ee = li & 63;
            Ash[ee*68 + xx] = g_embeds[(r0+xx)*EMBD + e0 + ee];
            Wsh[ee*68 + xx] = W[(g0+xx)*EMBD + e0 + ee];
        }
        __syncthreads();
        #pragma unroll 8
        for (int e = 0; e < 64; e++) {
            float4 av = *(const float4*)&Ash[e*68 + ri*4];
            float4 wv = *(const float4*)&Wsh[e*68 + gi*4];
            float aa[4] = {av.x, av.y, av.z, av.w};
            float ww[4] = {wv.x, wv.y, wv.z, wv.w};
            #pragma unroll
            for (int a = 0; a < 4; a++)
                #pragma unroll
                for (int g = 0; g < 4; g++) acc[a][g] += aa[a]*ww[g];
        }
        __syncthreads();
    }
    #pragma unroll
    for (int a = 0; a < 4; a++)
        #pragma unroll
        for (int g = 0; g < 4; g++) {
            int row = r0 + ri*4 + a, gg = g0 + gi*4 + g;
            g_xw[((size_t)dir*Bz*Ln + row)*1024 + gg] = acc[a][g] + bi[gg] + bh[gg];
        }
}

__device__ __forceinline__ float fsig(float x) {
    return __fdividef(1.0f, 1.0f + __expf(-x));
}

// K3: persistent LSTM — all 8 steps in one kernel.
// 128 blocks x 128 threads. Block (dir, ub) owns 4 units (16 gate-cols).
__global__ void k_lstm_all(const float* __restrict__ Whh_f, const float* __restrict__ Whh_b) {
    extern __shared__ float smem[];
    float* wsh = smem;                  // [gc 16][e 256] pitch 260
    float* hsh = smem + 4160;           // [e 256][n 64] pitch 68
    float* gsh = smem + 4160 + 17408;   // [gc 16][n 64] pitch 68
    int bx = blockIdx.x;
    int dir = bx >> 6, ub = bx & 63, u0 = ub*4;
    const float* Whh = dir ? Whh_b : Whh_f;
    int tid = threadIdx.x;

    #pragma unroll 8
    for (int q = 0; q < 32; q++) {
        int li = tid + q*128;
        int gc = li >> 8, e = li & 255;
        int ul = gc >> 2, gate = gc & 3;
        wsh[gc*260 + e] = Whh[(gate*H2 + u0 + ul)*H2 + e];
    }
    int ng = tid >> 3, gg = tid & 7;
    int n_c = tid & 63, ul_c = tid >> 6;
    float c0 = 0.f, c1 = 0.f;
    __syncthreads();

    for (int s = 0; s < Bz; s++) {
        int t = dir ? (Bz-1-s) : s;
        const float* xb = &g_xw[((size_t)(dir*Bz*Ln + t*Ln + n_c))*1024 + u0 + ul_c];
        float xw0[4], xw1[4];
        #pragma unroll
        for (int g = 0; g < 4; g++) { xw0[g] = xb[g*256]; xw1[g] = xb[g*256 + 2]; }

        float a00=0.f,a01=0.f,a10=0.f,a11=0.f,a20=0.f,a21=0.f,a30=0.f,a31=0.f;
        if (s > 0) {
            const float* hp = &g_hT[((s&1)*2 + dir)*H2*Ln];
            #pragma unroll 8
            for (int q = 0; q < 32; q++) {
                int idx = (tid + q*128)*4;
                int e = idx >> 6, n = idx & 63;
                float4 hv = __ldcg((const float4*)(hp + idx));
                *(float4*)&hsh[e*68 + n] = hv;
            }
            __syncthreads();
            #pragma unroll 4
            for (int e4 = 0; e4 < H2; e4 += 4) {
                float4 w0 = *(const float4*)&wsh[(gg*2  )*260 + e4];
                float4 w1 = *(const float4*)&wsh[(gg*2+1)*260 + e4];
                float wa[4] = {w0.x, w0.y, w0.z, w0.w};
                float wb[4] = {w1.x, w1.y, w1.z, w1.w};
                #pragma unroll
                for (int k = 0; k < 4; k++) {
                    float4 hv = *(const float4*)&hsh[(e4+k)*68 + ng*4];
                    a00 += hv.x*wa[k]; a01 += hv.x*wb[k];
                    a10 += hv.y*wa[k]; a11 += hv.y*wb[k];
                    a20 += hv.z*wa[k]; a21 += hv.z*wb[k];
                    a30 += hv.w*wa[k]; a31 += hv.w*wb[k];
                }
            }
        } else {
            __syncthreads();
        }
        gsh[(gg*2  )*68 + ng*4 + 0] = a00; gsh[(gg*2+1)*68 + ng*4 + 0] = a01;
        gsh[(gg*2  )*68 + ng*4 + 1] = a10; gsh[(gg*2+1)*68 + ng*4 + 1] = a11;
        gsh[(gg*2  )*68 + ng*4 + 2] = a20; gsh[(gg*2+1)*68 + ng*4 + 2] = a21;
        gsh[(gg*2  )*68 + ng*4 + 3] = a30; gsh[(gg*2+1)*68 + ng*4 + 3] = a31;
        __syncthreads();
        {
            float iv = gsh[(ul_c*4+0)*68 + n_c] + xw0[0];
            float fv = gsh[(ul_c*4+1)*68 + n_c] + xw0[1];
            float gv = gsh[(ul_c*4+2)*68 + n_c] + xw0[2];
            float ov = gsh[(ul_c*4+3)*68 + n_c] + xw0[3];
            c0 = fsig(fv)*c0 + fsig(iv)*__tanhf(gv);
            float h0 = fsig(ov)*__tanhf(c0);
            int ul2 = ul_c + 2;
            float iv1 = gsh[(ul2*4+0)*68 + n_c] + xw1[0];
            float fv1 = gsh[(ul2*4+1)*68 + n_c] + xw1[1];
            float gv1 = gsh[(ul2*4+2)*68 + n_c] + xw1[2];
            float ov1 = gsh[(ul2*4+3)*68 + n_c] + xw1[3];
            c1 = fsig(fv1)*c1 + fsig(iv1)*__tanhf(gv1);
            float h1 = fsig(ov1)*__tanhf(c1);
            int wbuf = (((s+1)&1)*2 + dir)*H2*Ln;
            __stcg(&g_hT[wbuf + (u0+ul_c )*Ln + n_c], h0);
            __stcg(&g_hT[wbuf + (u0+ul2  )*Ln + n_c], h1);
            g_hs[((size_t)t*Ln + n_c)*HIDD + dir*H2 + u0 + ul_c] = h0;
            g_hs[((size_t)t*Ln + n_c)*HIDD + dir*H2 + u0 + ul2 ] = h1;
        }
        if (s < Bz-1) {
            __threadfence();
            __syncthreads();
            if (tid == 0) {
                unsigned c = atomicAdd(&g_barr[dir*8 + s], 1u) + 1u;
                if (c < 64u) {
                    volatile unsigned* p = &g_barr[dir*8 + s];
                    while (*p < 64u) { }
                }
            }
            __syncthreads();
        }
    }
}

// K4 (fused): blocks 0..255 -> uv (2 rows each);
//             blocks 256..383 -> p12 GEMM (8 row-tiles x 16 col-tiles).
__global__ void k_uvp12(const float* __restrict__ Ws,
                        const float* __restrict__ W1, const float* __restrict__ b1,
                        const float* __restrict__ W2, const float* __restrict__ b2) {
    int tid = threadIdx.x;
    if (blockIdx.x < 256) {
        // ---- uv: rank-1 crf projections ----
        int row = blockIdx.x*2 + (tid >> 7);
        int t128 = tid & 127;
        int l = row & 63;
        const float4* hc = (const float4*)&g_hs[(size_t)row*HIDD];
        const float4* W4 = (const float4*)Ws;
        float4 h0 = hc[t128];
        float4 wu0 = W4[t128], wv0 = W4[384 + t128];
        float au = h0.x*wu0.x + h0.y*wu0.y + h0.z*wu0.z + h0.w*wu0.w;
        float av = h0.x*wv0.x + h0.y*wv0.y + h0.z*wv0.z + h0.w*wv0.w;
        if (l > 0) {
            float4 hb = hc[t128 - 128];
            float4 wu = W4[128 + t128], wv = W4[512 + t128];
            au += hb.x*wu.x + hb.y*wu.y + hb.z*wu.z + hb.w*wu.w;
            av += hb.x*wv.x + hb.y*wv.y + hb.z*wv.z + hb.w*wv.w;
        }
        if (l < 63) {
            float4 hn = hc[t128 + 128];
            float4 wu = W4[256 + t128], wv = W4[640 + t128];
            au += hn.x*wu.x + hn.y*wu.y + hn.z*wu.z + hn.w*wu.w;
            av += hn.x*wv.x + hn.y*wv.y + hn.z*wv.z + hn.w*wv.w;
        }
        #pragma unroll
        for (int o = 16; o; o >>= 1) {
            au += __shfl_xor_sync(0xffffffffu, au, o);
            av += __shfl_xor_sync(0xffffffffu, av, o);
        }
        __shared__ float pu[8], pv[8];
        int warp = tid >> 5, lane = tid & 31;
        if (lane == 0) { pu[warp] = au; pv[warp] = av; }
        __syncthreads();
        if ((tid & 127) == 0) {
            int wb = (tid >> 7)*4;
            g_u[row] = pu[wb]+pu[wb+1]+pu[wb+2]+pu[wb+3];
            g_v[row] = pv[wb]+pv[wb+1]+pv[wb+2]+pv[wb+3];
        }
        return;
    }
    // ---- p12 GEMM: out[512 x 256] = h[512 x 512] @ [W1|W2]^T, blocked ----
    int pb = blockIdx.x - 256;          // 0..127
    int br = pb >> 4;                   // 8 row tiles of 64 rows
    int bc = pb & 15;                   // 16 col tiles of 16 cols
    const float* W    = (bc < 8) ? W1 : W2;
    const float* bias = (bc < 8) ? b1 : b2;
    float* dst        = (bc < 8) ? g_p1 : g_p2;
    int c0 = (bc & 7) * 16;
    int r0 = br * 64;
    __shared__ float hsh[64*68];        // [k 64][row 64] pitch 68
    __shared__ float wsh[16*68];        // [c 16][k 64]  pitch 68
    int tr = tid >> 4, tc = tid & 15;   // 16 row-groups x 16 cols
    float acc0 = 0.f, acc1 = 0.f, acc2 = 0.f, acc3 = 0.f;
    int srow = tid & 63, skq = tid >> 6;        // h staging: 16 floats each
    int swc = tid >> 4, swk = (tid & 15) * 4;   // w staging: 4 floats each
    for (int k0 = 0; k0 < HIDD; k0 += 64) {
        const float4* hsrc = (const float4*)&g_hs[(size_t)(r0+srow)*HIDD + k0 + skq*16];
        float4 v0 = hsrc[0], v1 = hsrc[1], v2 = hsrc[2], v3 = hsrc[3];
        int kb = skq*16;
        hsh[(kb+ 0)*68+srow]=v0.x; hsh[(kb+ 1)*68+srow]=v0.y;
        hsh[(kb+ 2)*68+srow]=v0.z; hsh[(kb+ 3)*68+srow]=v0.w;
        hsh[(kb+ 4)*68+srow]=v1.x; hsh[(kb+ 5)*68+srow]=v1.y;
        hsh[(kb+ 6)*68+srow]=v1.z; hsh[(kb+ 7)*68+srow]=v1.w;
        hsh[(kb+ 8)*68+srow]=v2.x; hsh[(kb+ 9)*68+srow]=v2.y;
        hsh[(kb+10)*68+srow]=v2.z; hsh[(kb+11)*68+srow]=v2.w;
        hsh[(kb+12)*68+srow]=v3.x; hsh[(kb+13)*68+srow]=v3.y;
        hsh[(kb+14)*68+srow]=v3.z; hsh[(kb+15)*68+srow]=v3.w;
        *(float4*)&wsh[swc*68 + swk] =
            *(const float4*)&W[(size_t)(c0 + swc)*HIDD + k0 + swk];
        __syncthreads();
        #pragma unroll 8
        for (int k = 0; k < 64; k += 4) {
            float4 wv = *(const float4*)&wsh[tc*68 + k];
            float4 h0 = *(const float4*)&hsh[(k+0)*68 + tr*4];
            float4 h1 = *(const float4*)&hsh[(k+1)*68 + tr*4];
            float4 h2 = *(const float4*)&hsh[(k+2)*68 + tr*4];
            float4 h3 = *(const float4*)&hsh[(k+3)*68 + tr*4];
            acc0 += h0.x*wv.x + h1.x*wv.y + h2.x*wv.z + h3.x*wv.w;
            acc1 += h0.y*wv.x + h1.y*wv.y + h2.y*wv.z + h3.y*wv.w;
            acc2 += h0.z*wv.x + h1.z*wv.y + h2.z*wv.z + h3.z*wv.w;
            acc3 += h0.w*wv.x + h1.w*wv.y + h2.w*wv.z + h3.w*wv.w;
        }
        __syncthreads();
    }
    float bv = bias[c0 + tc];
    dst[(r0 + tr*4 + 0)*RECD + c0 + tc] = acc0 + bv;
    dst[(r0 + tr*4 + 1)*RECD + c0 + tc] = acc1 + bv;
    dst[(r0 + tr*4 + 2)*RECD + c0 + tc] = acc2 + bv;
    dst[(r0 + tr*4 + 3)*RECD + c0 + tc] = acc3 + bv;
}

// K5 (fused): blocks 0..7 -> Eisner (single-phase, 1 sync/width);
//             blocks 8..39 -> scores (one thread per (i,j)).
__global__ void k_eis_sc(const float* __restrict__ bs) {
    extern __shared__ float smf[];
    int tid = threadIdx.x;
    if (blockIdx.x < 8) {
        float* Cr = smf;         float* Cl = smf + 4160;
        float* Ir = smf + 8320;  float* Il = smf + 12480;
        __shared__ float ush[64], vsh[64];
        int b = blockIdx.x;
        if (tid < 64) { ush[tid] = g_u[b*Ln + tid] + bs[0]; vsh[tid] = g_v[b*Ln + tid]; }
        for (int idx = tid; idx < 4160; idx += 1024) {
            int i = idx / 65, jj = idx % 65;
            float dv = (jj < 64 && i == jj) ? 0.0f : NEGV;
            Cr[idx] = dv; Cl[idx] = dv; Ir[idx] = NEGV; Il[idx] = NEGV;
        }
        __syncthreads();
        int grp = tid >> 4, l16 = tid & 15;
        for (int w = 1; w < Ln; w++) {
            int spans = Ln - w;
            bool valid = grp < spans;
            int i = valid ? grp : 0, jn = i + w;
            int nq = (w + 15) >> 4;
            float t_in[4], t_cr[4], t_cl[4];
            float m_in = -INFINITY, m_cr = -INFINITY, m_cl = -INFINITY;
            #pragma unroll
            for (int q = 0; q < 4; q++) {
                t_in[q] = -INFINITY; t_cr[q] = -INFINITY; t_cl[q] = -INFINITY;
                if (q < nq) {
                    int o = l16 + q*16;
                    if (valid && o < w) {
                        int k = i + o;
                        t_in[q] = Cr[i*65 + k] + Cl[(k+1)*65 + jn];
                        if (o < w - 1) {
                            int k2 = k + 1;
                            t_cr[q] = Ir[i*65 + k2] + Cr[k2*65 + jn];
                            t_cl[q] = Cl[i*65 + k2] + Il[k2*65 + jn];
                        }
                    }
                }
                m_in = fmaxf(m_in, t_in[q]);
                m_cr = fmaxf(m_cr, t_cr[q]);
                m_cl = fmaxf(m_cl, t_cl[q]);
            }
            #pragma unroll
            for (int o = 8; o; o >>= 1) {
                m_in = fmaxf(m_in, __shfl_xor_sync(0xffffffffu, m_in, o));
                m_cr = fmaxf(m_cr, __shfl_xor_sync(0xffffffffu, m_cr, o));
                m_cl = fmaxf(m_cl, __shfl_xor_sync(0xffffffffu, m_cl, o));
            }
            float ms_in = fmaxf(m_in, -1e30f);
            float ms_cr = fmaxf(m_cr, -1e30f);
            float ms_cl = fmaxf(m_cl, -1e30f);
            float s_in = 0.f, s_cr = 0.f, s_cl = 0.f;
            #pragma unroll
            for (int q = 0; q < 4; q++) {
                s_in += __expf(t_in[q] - ms_in);
                s_cr += __expf(t_cr[q] - ms_cr);
                s_cl += __expf(t_cl[q] - ms_cl);
            }
            #pragma unroll
            for (int o = 8; o; o >>= 1) {
                s_in += __shfl_xor_sync(0xffffffffu, s_in, o);
                s_cr += __shfl_xor_sync(0xffffffffu, s_cr, o);
                s_cl += __shfl_xor_sync(0xffffffffu, s_cl, o);
            }
            if (valid && l16 == 0) {
                float inc = ms_in + __logf(s_in);
                float irv = inc + ush[i]  + vsh[jn];
                float ilv = inc + ush[jn] + vsh[i];
                Ir[i*65 + jn] = irv;
                Il[i*65 + jn] = ilv;
                float lcr = ms_cr + __logf(s_cr);
                float M = fmaxf(lcr, irv);
                Cr[i*65 + jn] = M + __logf(__expf(lcr - M) + __expf(irv - M));
                float lcl = ms_cl + __logf(s_cl);
                float Ml = fmaxf(lcl, ilv);
                Cl[i*65 + jn] = Ml + __logf(__expf(lcl - Ml) + __expf(ilv - Ml));
            }
            __syncthreads();
        }
        if (tid == 0) g_logZ[b] = Cr[Ln - 1];
        return;
    }
    // ---- scores: one thread per (i_local, j) ----
    int sb = blockIdx.x - 8;
    int b = sb >> 2, i0 = (sb & 3) * 16;
    float* p1sh = smf;              // 16 x 132
    float* p2sh = smf + 16*132;     // 64 x 132
    __shared__ float mm[32], ss[32];
    if (tid < 512) {
        int rr = tid >> 5, e4 = tid & 31;
        *(float4*)&p1sh[rr*132 + e4*4] = *(const float4*)&g_p1[(b*Ln + i0 + rr)*RECD + e4*4];
    }
    #pragma unroll
    for (int q = 0; q < 2; q++) {
        int li = tid + q*1024;
        int rr = li >> 5, e4 = li & 31;
        *(float4*)&p2sh[rr*132 + e4*4] = *(const float4*)&g_p2[(b*Ln + rr)*RECD + e4*4];
    }
    __syncthreads();
    int i_l = tid >> 6, j = tid & 63;
    float dot = 0.f;
    #pragma unroll 8
    for (int e4 = 0; e4 < 32; e4++) {
        float4 a = *(const float4*)&p1sh[i_l*132 + e4*4];
        float4 bv = *(const float4*)&p2sh[j*132 + e4*4];
        dot += a.x*bv.x + a.y*bv.y + a.z*bv.z + a.w*bv.w;
    }
    int i = i0 + i_l;
    g_s[((size_t)b*Ln + i)*Ln + j] = dot;
    float m = dot;
    #pragma unroll
    for (int o = 16; o; o >>= 1) m = fmaxf(m, __shfl_xor_sync(0xffffffffu, m, o));
    float sum = __expf(dot - m);
    #pragma unroll
    for (int o = 16; o; o >>= 1) sum += __shfl_xor_sync(0xffffffffu, sum, o);
    int warp = tid >> 5, lane = tid & 31;
    if (lane == 0) { mm[warp] = m; ss[warp] = sum; }
    __syncthreads();
    if (tid < 16) {
        float m0 = mm[tid*2], m1 = mm[tid*2+1];
        float M = fmaxf(m0, m1);
        float S = ss[tid*2]*__expf(m0 - M) + ss[tid*2+1]*__expf(m1 - M);
        g_rowlse[b*Ln + i0 + tid] = M + __logf(S);
    }
}

// K6: gather jp at (heads[b,m], m), LSE over m, loss. 1 block x 256.
__global__ void k_final(const int* __restrict__ heads, const float* __restrict__ prior,
                        const float* __restrict__ bs, float* __restrict__ out) {
    int tid = threadIdx.x, warp = tid >> 5, lane = tid & 31;
    __shared__ float sb[8];
    int b = warp;
    float bsv = bs[0];
    int m1 = lane + 1, m2 = lane + 33;
    float v1, v2 = -INFINITY;
    {
        int hd = heads[b*Ln + m1];
        v1 = g_u[b*Ln + hd] + g_v[b*Ln + m1] + bsv
           + g_s[((size_t)b*Ln + hd)*Ln + m1] - g_rowlse[b*Ln + hd]
           + prior[((size_t)b*Ln + hd)*Ln + m1] * (1.0f/64.0f);
    }
    if (m2 < Ln) {
        int hd = heads[b*Ln + m2];
        v2 = g_u[b*Ln + hd] + g_v[b*Ln + m2] + bsv
           + g_s[((size_t)b*Ln + hd)*Ln + m2] - g_rowlse[b*Ln + hd]
           + prior[((size_t)b*Ln + hd)*Ln + m2] * (1.0f/64.0f);
    }
    float mx = fmaxf(v1, v2);
    #pragma unroll
    for (int o = 16; o; o >>= 1) mx = fmaxf(mx, __shfl_xor_sync(0xffffffffu, mx, o));
    float sum = __expf(v1 - mx) + __expf(v2 - mx);
    #pragma unroll
    for (int o = 16; o; o >>= 1) sum += __shfl_xor_sync(0xffffffffu, sum, o);
    if (lane == 0) sb[b] = (mx + __logf(sum)) - g_logZ[b];
    __syncthreads();
    if (tid == 0) {
        float t = 0.f;
        for (int q = 0; q < 8; q++) t += sb[q];
        out[0] = -t * (1.0f/8.0f);
    }
}

extern "C" void kernel_launch(void* const* d_in, const int* in_sizes, int n_in,
                              void* d_out, int out_size) {
    const int*   sents = (const int*)  d_in[0];
    const float* mask  = (const float*)d_in[1];
    const float* prior = (const float*)d_in[2];
    const int*   heads = (const int*)  d_in[3];
    const float* emb   = (const float*)d_in[4];
    const float* Wih_f = (const float*)d_in[5];
    const float* Whh_f = (const float*)d_in[6];
    const float* bih_f = (const float*)d_in[7];
    const float* bhh_f = (const float*)d_in[8];
    const float* Wih_b = (const float*)d_in[9];
    const float* Whh_b = (const float*)d_in[10];
    const float* bih_b = (const float*)d_in[11];
    const float* bhh_b = (const float*)d_in[12];
    const float* W1    = (const float*)d_in[13];
    const float* b1    = (const float*)d_in[14];
    const float* W2    = (const float*)d_in[15];
    const float* b2    = (const float*)d_in[16];
    const float* Ws    = (const float*)d_in[17];
    const float* bsv   = (const float*)d_in[18];
    float* out = (float*)d_out;
    (void)in_sizes; (void)n_in; (void)out_size;

    cudaFuncSetAttribute(k_lstm_all, cudaFuncAttributeMaxDynamicSharedMemorySize, 22656*4);
    cudaFuncSetAttribute(k_eis_sc,   cudaFuncAttributeMaxDynamicSharedMemorySize, 16640*4);

    k_embed<<<Bz*Ln, 256>>>(sents, mask, emb);
    dim3 g2(8, 16, 2);
    k_xw<<<g2, 256>>>(Wih_f, bih_f, bhh_f, Wih_b, bih_b, bhh_b);
    k_lstm_all<<<128, 128, 22656*4>>>(Whh_f, Whh_b);
    k_uvp12<<<384, 256>>>(Ws, W1, b1, W2, b2);
    k_eis_sc<<<40, 1024, 16640*4>>>(bsv);
    k_final<<<1, 256>>>(heads, prior, bsv, out);
}

// round 11
// speedup vs baseline: 1.4854x; 1.0014x over previous
#include <cuda_runtime.h>
#include <math.h>

#define Bz 8
#define Ln 64
#define WL 32
#define EMBD 256
#define H2 256
#define HIDD 512
#define RECD 128
#define NEGV -1000000000.0f

__device__ float g_embeds[Bz*Ln*EMBD];
__device__ float g_xw[2*Bz*Ln*1024];
__device__ float g_hT[4*H2*Ln];          // [buf(2)][dir(2)][unit 256][n 64]
__device__ unsigned g_barr[16];          // lstm [dir][step]
__device__ unsigned g_barr2;             // embed->xw grid barrier
__device__ unsigned g_barr3;             // eis/scores->final grid barrier
__device__ float g_hs[Bz*Ln*HIDD];
__device__ float g_u[Bz*Ln];
__device__ float g_v[Bz*Ln];
__device__ float g_p1[Bz*Ln*RECD];
__device__ float g_p2[Bz*Ln*RECD];
__device__ float g_s[Bz*Ln*Ln];
__device__ float g_rowlse[Bz*Ln];
__device__ float g_logZ[Bz];

__device__ __forceinline__ float fsig(float x) {
    return __fdividef(1.0f, 1.0f + __expf(-x));
}

// K1 (fused): embed (2 rows/block) -> grid barrier -> xW GEMM.
// grid (8,16,2) x 256 threads; 256 blocks co-resident (occ>=2/SM).
__global__ void k_emb_xw(const int* __restrict__ sents, const float* __restrict__ mask,
                         const float* __restrict__ emb,
                         const float* __restrict__ Wf, const float* __restrict__ bif,
                         const float* __restrict__ bhf,
                         const float* __restrict__ Wb, const float* __restrict__ bib,
                         const float* __restrict__ bhb) {
    int lin = blockIdx.x + blockIdx.y*8 + blockIdx.z*128;   // 0..255
    int tid = threadIdx.x;
    __shared__ __align__(16) float Ash[64*68];
    __shared__ __align__(16) float Wsh[64*68];
    __shared__ int sw[WL]; __shared__ float sm[WL]; __shared__ float sden;
    // ---- embed phase: rows 2*lin, 2*lin+1 ----
    #pragma unroll
    for (int r = 0; r < 2; r++) {
        int row = lin*2 + r;
        if (tid < WL) { sw[tid] = sents[row*WL + tid]; sm[tid] = mask[row*WL + tid]; }
        __syncthreads();
        if (tid == 0) {
            float e = 0.f;
            for (int w = 0; w < WL; w++) e += sm[w];
            sden = e + (e == 0.0f ? 1.0f : 0.0f);
        }
        __syncthreads();
        float acc = 0.f;
        #pragma unroll 8
        for (int w = 0; w < WL; w++) acc += emb[(size_t)sw[w]*EMBD + tid] * sm[w];
        g_embeds[row*EMBD + tid] = acc / sden;
        __syncthreads();
    }
    // ---- grid barrier (256 blocks) ----
    __threadfence();
    if (tid == 0) {
        unsigned c = atomicAdd(&g_barr2, 1u) + 1u;
        if (c < 256u) {
            volatile unsigned* p = &g_barr2;
            while (*p < 256u) { }
        }
    }
    __syncthreads();
    // ---- xw phase ----
    int dir = blockIdx.z;
    const float* W  = dir ? Wb  : Wf;
    const float* bi = dir ? bib : bif;
    const float* bh = dir ? bhb : bhf;
    int r0 = blockIdx.x * 64, g0 = blockIdx.y * 64;
    int ri = tid & 15, gi = tid >> 4;
    float acc[4][4] = {};
    for (int e0 = 0; e0 < EMBD; e0 += 64) {
        #pragma unroll 4
        for (int q = 0; q < 16; q++) {
            int li = tid + q*256;
            int xx = li >> 6, ee = li & 63;
            Ash[ee*68 + xx] = __ldcg(&g_embeds[(r0+xx)*EMBD + e0 + ee]);
            Wsh[ee*68 + xx] = W[(g0+xx)*EMBD + e0 + ee];
        }
        __syncthreads();
        #pragma unroll 8
        for (int e = 0; e < 64; e++) {
            float4 av = *(const float4*)&Ash[e*68 + ri*4];
            float4 wv = *(const float4*)&Wsh[e*68 + gi*4];
            float aa[4] = {av.x, av.y, av.z, av.w};
            float ww[4] = {wv.x, wv.y, wv.z, wv.w};
            #pragma unroll
            for (int a = 0; a < 4; a++)
                #pragma unroll
                for (int g = 0; g < 4; g++) acc[a][g] += aa[a]*ww[g];
        }
        __syncthreads();
    }
    #pragma unroll
    for (int a = 0; a < 4; a++)
        #pragma unroll
        for (int g = 0; g < 4; g++) {
            int row = r0 + ri*4 + a, gg = g0 + gi*4 + g;
            g_xw[((size_t)dir*Bz*Ln + row)*1024 + gg] = acc[a][g] + bi[gg] + bh[gg];
        }
}

// K2: persistent LSTM — all 8 steps in one kernel.
// 128 blocks x 128 threads. Block (dir, ub) owns 4 units (16 gate-cols).
__global__ void k_lstm_all(const float* __restrict__ Whh_f, const float* __restrict__ Whh_b) {
    extern __shared__ float smem[];
    float* wsh = smem;                  // [gc 16][e 256] pitch 260
    float* hsh = smem + 4160;           // [e 256][n 64] pitch 68
    float* gsh = smem + 4160 + 17408;   // [gc 16][n 64] pitch 68
    int bx = blockIdx.x;
    int dir = bx >> 6, ub = bx & 63, u0 = ub*4;
    const float* Whh = dir ? Whh_b : Whh_f;
    int tid = threadIdx.x;

    #pragma unroll 8
    for (int q = 0; q < 32; q++) {
        int li = tid + q*128;
        int gc = li >> 8, e = li & 255;
        int ul = gc >> 2, gate = gc & 3;
        wsh[gc*260 + e] = Whh[(gate*H2 + u0 + ul)*H2 + e];
    }
    int ng = tid >> 3, gg = tid & 7;
    int n_c = tid & 63, ul_c = tid >> 6;
    float c0 = 0.f, c1 = 0.f;
    __syncthreads();

    for (int s = 0; s < Bz; s++) {
        int t = dir ? (Bz-1-s) : s;
        const float* xb = &g_xw[((size_t)(dir*Bz*Ln + t*Ln + n_c))*1024 + u0 + ul_c];
        float xw0[4], xw1[4];
        #pragma unroll
        for (int g = 0; g < 4; g++) { xw0[g] = xb[g*256]; xw1[g] = xb[g*256 + 2]; }

        float a00=0.f,a01=0.f,a10=0.f,a11=0.f,a20=0.f,a21=0.f,a30=0.f,a31=0.f;
        if (s > 0) {
            const float* hp = &g_hT[((s&1)*2 + dir)*H2*Ln];
            #pragma unroll 8
            for (int q = 0; q < 32; q++) {
                int idx = (tid + q*128)*4;
                int e = idx >> 6, n = idx & 63;
                float4 hv = __ldcg((const float4*)(hp + idx));
                *(float4*)&hsh[e*68 + n] = hv;
            }
            __syncthreads();
            #pragma unroll 4
            for (int e4 = 0; e4 < H2; e4 += 4) {
                float4 w0 = *(const float4*)&wsh[(gg*2  )*260 + e4];
                float4 w1 = *(const float4*)&wsh[(gg*2+1)*260 + e4];
                float wa[4] = {w0.x, w0.y, w0.z, w0.w};
                float wb[4] = {w1.x, w1.y, w1.z, w1.w};
                #pragma unroll
                for (int k = 0; k < 4; k++) {
                    float4 hv = *(const float4*)&hsh[(e4+k)*68 + ng*4];
                    a00 += hv.x*wa[k]; a01 += hv.x*wb[k];
                    a10 += hv.y*wa[k]; a11 += hv.y*wb[k];
                    a20 += hv.z*wa[k]; a21 += hv.z*wb[k];
                    a30 += hv.w*wa[k]; a31 += hv.w*wb[k];
                }
            }
        } else {
            __syncthreads();
        }
        gsh[(gg*2  )*68 + ng*4 + 0] = a00; gsh[(gg*2+1)*68 + ng*4 + 0] = a01;
        gsh[(gg*2  )*68 + ng*4 + 1] = a10; gsh[(gg*2+1)*68 + ng*4 + 1] = a11;
        gsh[(gg*2  )*68 + ng*4 + 2] = a20; gsh[(gg*2+1)*68 + ng*4 + 2] = a21;
        gsh[(gg*2  )*68 + ng*4 + 3] = a30; gsh[(gg*2+1)*68 + ng*4 + 3] = a31;
        __syncthreads();
        {
            float iv = gsh[(ul_c*4+0)*68 + n_c] + xw0[0];
            float fv = gsh[(ul_c*4+1)*68 + n_c] + xw0[1];
            float gv = gsh[(ul_c*4+2)*68 + n_c] + xw0[2];
            float ov = gsh[(ul_c*4+3)*68 + n_c] + xw0[3];
            c0 = fsig(fv)*c0 + fsig(iv)*__tanhf(gv);
            float h0 = fsig(ov)*__tanhf(c0);
            int ul2 = ul_c + 2;
            float iv1 = gsh[(ul2*4+0)*68 + n_c] + xw1[0];
            float fv1 = gsh[(ul2*4+1)*68 + n_c] + xw1[1];
            float gv1 = gsh[(ul2*4+2)*68 + n_c] + xw1[2];
            float ov1 = gsh[(ul2*4+3)*68 + n_c] + xw1[3];
            c1 = fsig(fv1)*c1 + fsig(iv1)*__tanhf(gv1);
            float h1 = fsig(ov1)*__tanhf(c1);
            int wbuf = (((s+1)&1)*2 + dir)*H2*Ln;
            __stcg(&g_hT[wbuf + (u0+ul_c )*Ln + n_c], h0);
            __stcg(&g_hT[wbuf + (u0+ul2  )*Ln + n_c], h1);
            g_hs[((size_t)t*Ln + n_c)*HIDD + dir*H2 + u0 + ul_c] = h0;
            g_hs[((size_t)t*Ln + n_c)*HIDD + dir*H2 + u0 + ul2 ] = h1;
        }
        if (s < Bz-1) {
            __threadfence();
            __syncthreads();
            if (tid == 0) {
                unsigned c = atomicAdd(&g_barr[dir*8 + s], 1u) + 1u;
                if (c < 64u) {
                    volatile unsigned* p = &g_barr[dir*8 + s];
                    while (*p < 64u) { }
                }
            }
            __syncthreads();
        }
    }
}

// K3 (fused): blocks 0..63 -> p12 GEMM (64 rows x 32 cols, 4x2 reg tile);
//             blocks 64..319 -> uv (2 rows each). p12 first => wave-1 start.
__global__ void k_uvp12(const float* __restrict__ Ws,
                        const float* __restrict__ W1, const float* __restrict__ b1,
                        const float* __restrict__ W2, const float* __restrict__ b2) {
    int tid = threadIdx.x;
    __shared__ __align__(16) float hsh[64*68];    // [k][row]
    __shared__ __align__(16) float wsh[32*68];    // [c][k]
    __shared__ float pu[8], pv[8];
    if (blockIdx.x < 64) {
        // ---- p12 GEMM: out[512 x 256] = h @ [W1|W2]^T ----
        int pb = blockIdx.x;
        int br = pb >> 3;               // 8 row tiles of 64
        int bc = pb & 7;                // 8 col tiles of 32
        const float* W    = (bc < 4) ? W1 : W2;
        const float* bias = (bc < 4) ? b1 : b2;
        float* dst        = (bc < 4) ? g_p1 : g_p2;
        int c0 = (bc & 3) * 32;
        int r0 = br * 64;
        int tr = tid >> 4, tc = tid & 15;   // 16 rg x 16 cg(2 cols)
        float a0[2] = {}, a1[2] = {}, a2[2] = {}, a3[2] = {};
        int srow = tid & 63, skq = tid >> 6;
        int swc = tid >> 3, swk8 = (tid & 7) * 8;
        for (int k0 = 0; k0 < HIDD; k0 += 64) {
            const float4* hsrc = (const float4*)&g_hs[(size_t)(r0+srow)*HIDD + k0 + skq*16];
            float4 v0 = hsrc[0], v1 = hsrc[1], v2 = hsrc[2], v3 = hsrc[3];
            int kb = skq*16;
            hsh[(kb+ 0)*68+srow]=v0.x; hsh[(kb+ 1)*68+srow]=v0.y;
            hsh[(kb+ 2)*68+srow]=v0.z; hsh[(kb+ 3)*68+srow]=v0.w;
            hsh[(kb+ 4)*68+srow]=v1.x; hsh[(kb+ 5)*68+srow]=v1.y;
            hsh[(kb+ 6)*68+srow]=v1.z; hsh[(kb+ 7)*68+srow]=v1.w;
            hsh[(kb+ 8)*68+srow]=v2.x; hsh[(kb+ 9)*68+srow]=v2.y;
            hsh[(kb+10)*68+srow]=v2.z; hsh[(kb+11)*68+srow]=v2.w;
            hsh[(kb+12)*68+srow]=v3.x; hsh[(kb+13)*68+srow]=v3.y;
            hsh[(kb+14)*68+srow]=v3.z; hsh[(kb+15)*68+srow]=v3.w;
            *(float4*)&wsh[swc*68 + swk8] =
                *(const float4*)&W[(size_t)(c0 + swc)*HIDD + k0 + swk8];
            *(float4*)&wsh[swc*68 + swk8 + 4] =
                *(const float4*)&W[(size_t)(c0 + swc)*HIDD + k0 + swk8 + 4];
            __syncthreads();
            #pragma unroll 8
            for (int k = 0; k < 64; k += 4) {
                float4 w0 = *(const float4*)&wsh[(tc*2  )*68 + k];
                float4 w1 = *(const float4*)&wsh[(tc*2+1)*68 + k];
                float4 h0 = *(const float4*)&hsh[(k+0)*68 + tr*4];
                float4 h1 = *(const float4*)&hsh[(k+1)*68 + tr*4];
                float4 h2 = *(const float4*)&hsh[(k+2)*68 + tr*4];
                float4 h3 = *(const float4*)&hsh[(k+3)*68 + tr*4];
                a0[0] += h0.x*w0.x + h1.x*w0.y + h2.x*w0.z + h3.x*w0.w;
                a1[0] += h0.y*w0.x + h1.y*w0.y + h2.y*w0.z + h3.y*w0.w;
                a2[0] += h0.z*w0.x + h1.z*w0.y + h2.z*w0.z + h3.z*w0.w;
                a3[0] += h0.w*w0.x + h1.w*w0.y + h2.w*w0.z + h3.w*w0.w;
                a0[1] += h0.x*w1.x + h1.x*w1.y + h2.x*w1.z + h3.x*w1.w;
                a1[1] += h0.y*w1.x + h1.y*w1.y + h2.y*w1.z + h3.y*w1.w;
                a2[1] += h0.z*w1.x + h1.z*w1.y + h2.z*w1.z + h3.z*w1.w;
                a3[1] += h0.w*w1.x + h1.w*w1.y + h2.w*w1.z + h3.w*w1.w;
            }
            __syncthreads();
        }
        int cc = c0 + tc*2;
        float2 bv = { bias[cc], bias[cc+1] };
        *(float2*)&dst[(r0 + tr*4 + 0)*RECD + cc] = make_float2(a0[0]+bv.x, a0[1]+bv.y);
        *(float2*)&dst[(r0 + tr*4 + 1)*RECD + cc] = make_float2(a1[0]+bv.x, a1[1]+bv.y);
        *(float2*)&dst[(r0 + tr*4 + 2)*RECD + cc] = make_float2(a2[0]+bv.x, a2[1]+bv.y);
        *(float2*)&dst[(r0 + tr*4 + 3)*RECD + cc] = make_float2(a3[0]+bv.x, a3[1]+bv.y);
        return;
    }
    // ---- uv: rank-1 crf projections ----
    int row = (blockIdx.x - 64)*2 + (tid >> 7);
    int t128 = tid & 127;
    int l = row & 63;
    const float4* hc = (const float4*)&g_hs[(size_t)row*HIDD];
    const float4* W4 = (const float4*)Ws;
    float4 h0 = hc[t128];
    float4 wu0 = W4[t128], wv0 = W4[384 + t128];
    float au = h0.x*wu0.x + h0.y*wu0.y + h0.z*wu0.z + h0.w*wu0.w;
    float av = h0.x*wv0.x + h0.y*wv0.y + h0.z*wv0.z + h0.w*wv0.w;
    if (l > 0) {
        float4 hb = hc[t128 - 128];
        float4 wu = W4[128 + t128], wv = W4[512 + t128];
        au += hb.x*wu.x + hb.y*wu.y + hb.z*wu.z + hb.w*wu.w;
        av += hb.x*wv.x + hb.y*wv.y + hb.z*wv.z + hb.w*wv.w;
    }
    if (l < 63) {
        float4 hn = hc[t128 + 128];
        float4 wu = W4[256 + t128], wv = W4[640 + t128];
        au += hn.x*wu.x + hn.y*wu.y + hn.z*wu.z + hn.w*wu.w;
        av += hn.x*wv.x + hn.y*wv.y + hn.z*wv.z + hn.w*wv.w;
    }
    #pragma unroll
    for (int o = 16; o; o >>= 1) {
        au += __shfl_xor_sync(0xffffffffu, au, o);
        av += __shfl_xor_sync(0xffffffffu, av, o);
    }
    int warp = tid >> 5, lane = tid & 31;
    if (lane == 0) { pu[warp] = au; pv[warp] = av; }
    __syncthreads();
    if ((tid & 127) == 0) {
        int wb = (tid >> 7)*4;
        g_u[row] = pu[wb]+pu[wb+1]+pu[wb+2]+pu[wb+3];
        g_v[row] = pv[wb]+pv[wb+1]+pv[wb+2]+pv[wb+3];
    }
}

// K4 (fused): blocks 0..7 Eisner; blocks 8..39 scores; block 0 then waits on
// a 40-block arrive counter and computes the final loss; resets all counters.
__global__ void k_eis_sc(const float* __restrict__ bs, const int* __restrict__ heads,
                         const float* __restrict__ prior, float* __restrict__ out) {
    extern __shared__ float smf[];
    int tid = threadIdx.x;
    if (blockIdx.x < 8) {
        float* Cr = smf;         float* Cl = smf + 4160;
        float* Ir = smf + 8320;  float* Il = smf + 12480;
        __shared__ float ush[64], vsh[64];
        int b = blockIdx.x;
        if (tid < 64) { ush[tid] = g_u[b*Ln + tid] + bs[0]; vsh[tid] = g_v[b*Ln + tid]; }
        for (int idx = tid; idx < 4160; idx += 1024) {
            int i = idx / 65, jj = idx % 65;
            float dv = (jj < 64 && i == jj) ? 0.0f : NEGV;
            Cr[idx] = dv; Cl[idx] = dv; Ir[idx] = NEGV; Il[idx] = NEGV;
        }
        __syncthreads();
        int grp = tid >> 4, l16 = tid & 15;
        for (int w = 1; w < Ln; w++) {
            int spans = Ln - w;
            bool valid = grp < spans;
            int i = valid ? grp : 0, jn = i + w;
            int nq = (w + 15) >> 4;
            float t_in[4], t_cr[4], t_cl[4];
            float m_in = -INFINITY, m_cr = -INFINITY, m_cl = -INFINITY;
            #pragma unroll
            for (int q = 0; q < 4; q++) {
                t_in[q] = -INFINITY; t_cr[q] = -INFINITY; t_cl[q] = -INFINITY;
                if (q < nq) {
                    int o = l16 + q*16;
                    if (valid && o < w) {
                        int k = i + o;
                        t_in[q] = Cr[i*65 + k] + Cl[(k+1)*65 + jn];
                        if (o < w - 1) {
                            int k2 = k + 1;
                            t_cr[q] = Ir[i*65 + k2] + Cr[k2*65 + jn];
                            t_cl[q] = Cl[i*65 + k2] + Il[k2*65 + jn];
                        }
                    }
                }
                m_in = fmaxf(m_in, t_in[q]);
                m_cr = fmaxf(m_cr, t_cr[q]);
                m_cl = fmaxf(m_cl, t_cl[q]);
            }
            #pragma unroll
            for (int o = 8; o; o >>= 1) {
                m_in = fmaxf(m_in, __shfl_xor_sync(0xffffffffu, m_in, o));
                m_cr = fmaxf(m_cr, __shfl_xor_sync(0xffffffffu, m_cr, o));
                m_cl = fmaxf(m_cl, __shfl_xor_sync(0xffffffffu, m_cl, o));
            }
            float ms_in = fmaxf(m_in, -1e30f);
            float ms_cr = fmaxf(m_cr, -1e30f);
            float ms_cl = fmaxf(m_cl, -1e30f);
            float s_in = 0.f, s_cr = 0.f, s_cl = 0.f;
            #pragma unroll
            for (int q = 0; q < 4; q++) {
                s_in += __expf(t_in[q] - ms_in);
                s_cr += __expf(t_cr[q] - ms_cr);
                s_cl += __expf(t_cl[q] - ms_cl);
            }
            #pragma unroll
            for (int o = 8; o; o >>= 1) {
                s_in += __shfl_xor_sync(0xffffffffu, s_in, o);
                s_cr += __shfl_xor_sync(0xffffffffu, s_cr, o);
                s_cl += __shfl_xor_sync(0xffffffffu, s_cl, o);
            }
            if (valid && l16 == 0) {
                float inc = ms_in + __logf(s_in);
                float irv = inc + ush[i]  + vsh[jn];
                float ilv = inc + ush[jn] + vsh[i];
                Ir[i*65 + jn] = irv;
                Il[i*65 + jn] = ilv;
                float lcr = ms_cr + __logf(s_cr);
                float M = fmaxf(lcr, irv);
                Cr[i*65 + jn] = M + __logf(__expf(lcr - M) + __expf(irv - M));
                float lcl = ms_cl + __logf(s_cl);
                float Ml = fmaxf(lcl, ilv);
                Cl[i*65 + jn] = Ml + __logf(__expf(lcl - Ml) + __expf(ilv - Ml));
            }
            __syncthreads();
        }
        if (tid == 0) g_logZ[b] = Cr[Ln - 1];
        // ---- arrive; block 0 runs final ----
        __threadfence();
        __syncthreads();
        if (blockIdx.x == 0) {
            if (tid == 0) {
                unsigned c = atomicAdd(&g_barr3, 1u) + 1u;
                if (c < 40u) {
                    volatile unsigned* p = &g_barr3;
                    while (*p < 40u) { }
                }
            }
            __syncthreads();
            if (tid < 256) {
                int warp = tid >> 5, lane = tid & 31;
                __shared__ float sb[8];
                int b2 = warp;
                float bsv = bs[0];
                int m1 = lane + 1, m2 = lane + 33;
                float v1, v2;
                {
                    int hd = heads[b2*Ln + m1];
                    v1 = __ldcg(&g_u[b2*Ln + hd]) + __ldcg(&g_v[b2*Ln + m1]) + bsv
                       + __ldcg(&g_s[((size_t)b2*Ln + hd)*Ln + m1])
                       - __ldcg(&g_rowlse[b2*Ln + hd])
                       + prior[((size_t)b2*Ln + hd)*Ln + m1] * (1.0f/64.0f);
                }
                if (m2 < Ln) {
                    int hd = heads[b2*Ln + m2];
                    v2 = __ldcg(&g_u[b2*Ln + hd]) + __ldcg(&g_v[b2*Ln + m2]) + bsv
                       + __ldcg(&g_s[((size_t)b2*Ln + hd)*Ln + m2])
                       - __ldcg(&g_rowlse[b2*Ln + hd])
                       + prior[((size_t)b2*Ln + hd)*Ln + m2] * (1.0f/64.0f);
                } else v2 = -INFINITY;
                float mx = fmaxf(v1, v2);
                #pragma unroll
                for (int o = 16; o; o >>= 1) mx = fmaxf(mx, __shfl_xor_sync(0xffffffffu, mx, o));
                float sum = __expf(v1 - mx) + __expf(v2 - mx);
                #pragma unroll
                for (int o = 16; o; o >>= 1) sum += __shfl_xor_sync(0xffffffffu, sum, o);
                if (lane == 0) sb[b2] = (mx + __logf(sum)) - __ldcg(&g_logZ[b2]);
                __syncthreads();
                if (tid == 0) {
                    float t = 0.f;
                    for (int q = 0; q < 8; q++) t += sb[q];
                    out[0] = -t * (1.0f/8.0f);
                    // reset all barrier counters for the next replay
                    for (int q = 0; q < 16; q++) g_barr[q] = 0u;
                    g_barr2 = 0u;
                    g_barr3 = 0u;
                }
            }
        } else {
            if (tid == 0) atomicAdd(&g_barr3, 1u);
        }
        return;
    }
    // ---- scores: one thread per (i_local, j) ----
    int sb2 = blockIdx.x - 8;
    int b = sb2 >> 2, i0 = (sb2 & 3) * 16;
    float* p1sh = smf;              // 16 x 132
    float* p2sh = smf + 16*132;     // 64 x 132
    __shared__ float mm[32], ss[32];
    if (tid < 512) {
        int rr = tid >> 5, e4 = tid & 31;
        *(float4*)&p1sh[rr*132 + e4*4] = *(const float4*)&g_p1[(b*Ln + i0 + rr)*RECD + e4*4];
    }
    #pragma unroll
    for (int q = 0; q < 2; q++) {
        int li = tid + q*1024;
        int rr = li >> 5, e4 = li & 31;
        *(float4*)&p2sh[rr*132 + e4*4] = *(const float4*)&g_p2[(b*Ln + rr)*RECD + e4*4];
    }
    __syncthreads();
    int i_l = tid >> 6, j = tid & 63;
    float dot = 0.f;
    #pragma unroll 8
    for (int e4 = 0; e4 < 32; e4++) {
        float4 a = *(const float4*)&p1sh[i_l*132 + e4*4];
        float4 bv = *(const float4*)&p2sh[j*132 + e4*4];
        dot += a.x*bv.x + a.y*bv.y + a.z*bv.z + a.w*bv.w;
    }
    int i = i0 + i_l;
    g_s[((size_t)b*Ln + i)*Ln + j] = dot;
    float m = dot;
    #pragma unroll
    for (int o = 16; o; o >>= 1) m = fmaxf(m, __shfl_xor_sync(0xffffffffu, m, o));
    float sum = __expf(dot - m);
    #pragma unroll
    for (int o = 16; o; o >>= 1) sum += __shfl_xor_sync(0xffffffffu, sum, o);
    int warp = tid >> 5, lane = tid & 31;
    if (lane == 0) { mm[warp] = m; ss[warp] = sum; }
    __syncthreads();
    if (tid < 16) {
        float m0 = mm[tid*2], m1 = mm[tid*2+1];
        float M = fmaxf(m0, m1);
        float S = ss[tid*2]*__expf(m0 - M) + ss[tid*2+1]*__expf(m1 - M);
        g_rowlse[b*Ln + i0 + tid] = M + __logf(S);
    }
    __threadfence();
    __syncthreads();
    if (tid == 0) atomicAdd(&g_barr3, 1u);
}

extern "C" void kernel_launch(void* const* d_in, const int* in_sizes, int n_in,
                              void* d_out, int out_size) {
    const int*   sents = (const int*)  d_in[0];
    const float* mask  = (const float*)d_in[1];
    const float* prior = (const float*)d_in[2];
    const int*   heads = (const int*)  d_in[3];
    const float* emb   = (const float*)d_in[4];
    const float* Wih_f = (const float*)d_in[5];
    const float* Whh_f = (const float*)d_in[6];
    const float* bih_f = (const float*)d_in[7];
    const float* bhh_f = (const float*)d_in[8];
    const float* Wih_b = (const float*)d_in[9];
    const float* Whh_b = (const float*)d_in[10];
    const float* bih_b = (const float*)d_in[11];
    const float* bhh_b = (const float*)d_in[12];
    const float* W1    = (const float*)d_in[13];
    const float* b1    = (const float*)d_in[14];
    const float* W2    = (const float*)d_in[15];
    const float* b2    = (const float*)d_in[16];
    const float* Ws    = (const float*)d_in[17];
    const float* bsv   = (const float*)d_in[18];
    float* out = (float*)d_out;
    (void)in_sizes; (void)n_in; (void)out_size;

    cudaFuncSetAttribute(k_lstm_all, cudaFuncAttributeMaxDynamicSharedMemorySize, 22656*4);
    cudaFuncSetAttribute(k_eis_sc,   cudaFuncAttributeMaxDynamicSharedMemorySize, 16640*4);

    dim3 g1(8, 16, 2);
    k_emb_xw<<<g1, 256>>>(sents, mask, emb, Wih_f, bih_f, bhh_f, Wih_b, bih_b, bhh_b);
    k_lstm_all<<<128, 128, 22656*4>>>(Whh_f, Whh_b);
    k_uvp12<<<320, 256>>>(Ws, W1, b1, W2, b2);
    k_eis_sc<<<40, 1024, 16640*4>>>(bsv, heads, prior, out);
}

// round 12
// speedup vs baseline: 1.6926x; 1.1395x over previous
#include <cuda_runtime.h>
#include <math.h>

#define Bz 8
#define Ln 64
#define WL 32
#define EMBD 256
#define H2 256
#define HIDD 512
#define RECD 128
#define NEGV -1000000000.0f

__device__ float g_embeds[Bz*Ln*EMBD];
__device__ float g_xw[2*Bz*Ln*1024];
__device__ float g_hT[4*H2*Ln];          // [buf(2)][dir(2)][unit 256][n 64]
__device__ unsigned g_barr[16];          // lstm [dir][step]
__device__ unsigned g_barr2;             // embed->xw grid barrier
__device__ unsigned g_barr3;             // eis/scores->final grid barrier
__device__ float g_hs[Bz*Ln*HIDD];
__device__ float g_u[Bz*Ln];
__device__ float g_v[Bz*Ln];
__device__ float g_p1[Bz*Ln*RECD];
__device__ float g_p2[Bz*Ln*RECD];
__device__ float g_s[Bz*Ln*Ln];
__device__ float g_rowlse[Bz*Ln];
__device__ float g_logZ[Bz];

__device__ __forceinline__ float fsig(float x) {
    return __fdividef(1.0f, 1.0f + __expf(-x));
}

// K1 (fused): embed (2 rows/block) -> grid barrier -> xW GEMM.
__global__ void k_emb_xw(const int* __restrict__ sents, const float* __restrict__ mask,
                         const float* __restrict__ emb,
                         const float* __restrict__ Wf, const float* __restrict__ bif,
                         const float* __restrict__ bhf,
                         const float* __restrict__ Wb, const float* __restrict__ bib,
                         const float* __restrict__ bhb) {
    int lin = blockIdx.x + blockIdx.y*8 + blockIdx.z*128;   // 0..255
    int tid = threadIdx.x;
    __shared__ __align__(16) float Ash[64*68];
    __shared__ __align__(16) float Wsh[64*68];
    __shared__ int sw[WL]; __shared__ float sm[WL]; __shared__ float sden;
    #pragma unroll
    for (int r = 0; r < 2; r++) {
        int row = lin*2 + r;
        if (tid < WL) { sw[tid] = sents[row*WL + tid]; sm[tid] = mask[row*WL + tid]; }
        __syncthreads();
        if (tid == 0) {
            float e = 0.f;
            for (int w = 0; w < WL; w++) e += sm[w];
            sden = e + (e == 0.0f ? 1.0f : 0.0f);
        }
        __syncthreads();
        float acc = 0.f;
        #pragma unroll 8
        for (int w = 0; w < WL; w++) acc += emb[(size_t)sw[w]*EMBD + tid] * sm[w];
        g_embeds[row*EMBD + tid] = acc / sden;
        __syncthreads();
    }
    __threadfence();
    if (tid == 0) {
        unsigned c = atomicAdd(&g_barr2, 1u) + 1u;
        if (c < 256u) {
            volatile unsigned* p = &g_barr2;
            while (*p < 256u) { }
        }
    }
    __syncthreads();
    int dir = blockIdx.z;
    const float* W  = dir ? Wb  : Wf;
    const float* bi = dir ? bib : bif;
    const float* bh = dir ? bhb : bhf;
    int r0 = blockIdx.x * 64, g0 = blockIdx.y * 64;
    int ri = tid & 15, gi = tid >> 4;
    float acc[4][4] = {};
    for (int e0 = 0; e0 < EMBD; e0 += 64) {
        #pragma unroll 4
        for (int q = 0; q < 16; q++) {
            int li = tid + q*256;
            int xx = li >> 6, ee = li & 63;
            Ash[ee*68 + xx] = __ldcg(&g_embeds[(r0+xx)*EMBD + e0 + ee]);
            Wsh[ee*68 + xx] = W[(g0+xx)*EMBD + e0 + ee];
        }
        __syncthreads();
        #pragma unroll 8
        for (int e = 0; e < 64; e++) {
            float4 av = *(const float4*)&Ash[e*68 + ri*4];
            float4 wv = *(const float4*)&Wsh[e*68 + gi*4];
            float aa[4] = {av.x, av.y, av.z, av.w};
            float ww[4] = {wv.x, wv.y, wv.z, wv.w};
            #pragma unroll
            for (int a = 0; a < 4; a++)
                #pragma unroll
                for (int g = 0; g < 4; g++) acc[a][g] += aa[a]*ww[g];
        }
        __syncthreads();
    }
    #pragma unroll
    for (int a = 0; a < 4; a++)
        #pragma unroll
        for (int g = 0; g < 4; g++) {
            int row = r0 + ri*4 + a, gg = g0 + gi*4 + g;
            g_xw[((size_t)dir*Bz*Ln + row)*1024 + gg] = acc[a][g] + bi[gg] + bh[gg];
        }
}

// K2: persistent LSTM — all 8 steps in one kernel.
__global__ void k_lstm_all(const float* __restrict__ Whh_f, const float* __restrict__ Whh_b) {
    extern __shared__ float smem[];
    float* wsh = smem;                  // [gc 16][e 256] pitch 260
    float* hsh = smem + 4160;           // [e 256][n 64] pitch 68
    float* gsh = smem + 4160 + 17408;   // [gc 16][n 64] pitch 68
    int bx = blockIdx.x;
    int dir = bx >> 6, ub = bx & 63, u0 = ub*4;
    const float* Whh = dir ? Whh_b : Whh_f;
    int tid = threadIdx.x;

    #pragma unroll 8
    for (int q = 0; q < 32; q++) {
        int li = tid + q*128;
        int gc = li >> 8, e = li & 255;
        int ul = gc >> 2, gate = gc & 3;
        wsh[gc*260 + e] = Whh[(gate*H2 + u0 + ul)*H2 + e];
    }
    int ng = tid >> 3, gg = tid & 7;
    int n_c = tid & 63, ul_c = tid >> 6;
    float c0 = 0.f, c1 = 0.f;
    __syncthreads();

    for (int s = 0; s < Bz; s++) {
        int t = dir ? (Bz-1-s) : s;
        const float* xb = &g_xw[((size_t)(dir*Bz*Ln + t*Ln + n_c))*1024 + u0 + ul_c];
        float xw0[4], xw1[4];
        #pragma unroll
        for (int g = 0; g < 4; g++) { xw0[g] = xb[g*256]; xw1[g] = xb[g*256 + 2]; }

        float a00=0.f,a01=0.f,a10=0.f,a11=0.f,a20=0.f,a21=0.f,a30=0.f,a31=0.f;
        if (s > 0) {
            const float* hp = &g_hT[((s&1)*2 + dir)*H2*Ln];
            #pragma unroll 8
            for (int q = 0; q < 32; q++) {
                int idx = (tid + q*128)*4;
                int e = idx >> 6, n = idx & 63;
                float4 hv = __ldcg((const float4*)(hp + idx));
                *(float4*)&hsh[e*68 + n] = hv;
            }
            __syncthreads();
            #pragma unroll 4
            for (int e4 = 0; e4 < H2; e4 += 4) {
                float4 w0 = *(const float4*)&wsh[(gg*2  )*260 + e4];
                float4 w1 = *(const float4*)&wsh[(gg*2+1)*260 + e4];
                float wa[4] = {w0.x, w0.y, w0.z, w0.w};
                float wb[4] = {w1.x, w1.y, w1.z, w1.w};
                #pragma unroll
                for (int k = 0; k < 4; k++) {
                    float4 hv = *(const float4*)&hsh[(e4+k)*68 + ng*4];
                    a00 += hv.x*wa[k]; a01 += hv.x*wb[k];
                    a10 += hv.y*wa[k]; a11 += hv.y*wb[k];
                    a20 += hv.z*wa[k]; a21 += hv.z*wb[k];
                    a30 += hv.w*wa[k]; a31 += hv.w*wb[k];
                }
            }
        } else {
            __syncthreads();
        }
        gsh[(gg*2  )*68 + ng*4 + 0] = a00; gsh[(gg*2+1)*68 + ng*4 + 0] = a01;
        gsh[(gg*2  )*68 + ng*4 + 1] = a10; gsh[(gg*2+1)*68 + ng*4 + 1] = a11;
        gsh[(gg*2  )*68 + ng*4 + 2] = a20; gsh[(gg*2+1)*68 + ng*4 + 2] = a21;
        gsh[(gg*2  )*68 + ng*4 + 3] = a30; gsh[(gg*2+1)*68 + ng*4 + 3] = a31;
        __syncthreads();
        {
            float iv = gsh[(ul_c*4+0)*68 + n_c] + xw0[0];
            float fv = gsh[(ul_c*4+1)*68 + n_c] + xw0[1];
            float gv = gsh[(ul_c*4+2)*68 + n_c] + xw0[2];
            float ov = gsh[(ul_c*4+3)*68 + n_c] + xw0[3];
            c0 = fsig(fv)*c0 + fsig(iv)*__tanhf(gv);
            float h0 = fsig(ov)*__tanhf(c0);
            int ul2 = ul_c + 2;
            float iv1 = gsh[(ul2*4+0)*68 + n_c] + xw1[0];
            float fv1 = gsh[(ul2*4+1)*68 + n_c] + xw1[1];
            float gv1 = gsh[(ul2*4+2)*68 + n_c] + xw1[2];
            float ov1 = gsh[(ul2*4+3)*68 + n_c] + xw1[3];
            c1 = fsig(fv1)*c1 + fsig(iv1)*__tanhf(gv1);
            float h1 = fsig(ov1)*__tanhf(c1);
            int wbuf = (((s+1)&1)*2 + dir)*H2*Ln;
            __stcg(&g_hT[wbuf + (u0+ul_c )*Ln + n_c], h0);
            __stcg(&g_hT[wbuf + (u0+ul2  )*Ln + n_c], h1);
            g_hs[((size_t)t*Ln + n_c)*HIDD + dir*H2 + u0 + ul_c] = h0;
            g_hs[((size_t)t*Ln + n_c)*HIDD + dir*H2 + u0 + ul2 ] = h1;
        }
        if (s < Bz-1) {
            __threadfence();
            __syncthreads();
            if (tid == 0) {
                unsigned c = atomicAdd(&g_barr[dir*8 + s], 1u) + 1u;
                if (c < 64u) {
                    volatile unsigned* p = &g_barr[dir*8 + s];
                    while (*p < 64u) { }
                }
            }
            __syncthreads();
        }
    }
}

// K3 (fused): blocks 0..63 -> p12 GEMM; blocks 64..319 -> uv.
__global__ void k_uvp12(const float* __restrict__ Ws,
                        const float* __restrict__ W1, const float* __restrict__ b1,
                        const float* __restrict__ W2, const float* __restrict__ b2) {
    int tid = threadIdx.x;
    __shared__ __align__(16) float hsh[64*68];    // [k][row]
    __shared__ __align__(16) float wsh[32*68];    // [c][k]
    __shared__ float pu[8], pv[8];
    if (blockIdx.x < 64) {
        int pb = blockIdx.x;
        int br = pb >> 3;
        int bc = pb & 7;
        const float* W    = (bc < 4) ? W1 : W2;
        const float* bias = (bc < 4) ? b1 : b2;
        float* dst        = (bc < 4) ? g_p1 : g_p2;
        int c0 = (bc & 3) * 32;
        int r0 = br * 64;
        int tr = tid >> 4, tc = tid & 15;
        float a0[2] = {}, a1[2] = {}, a2[2] = {}, a3[2] = {};
        int srow = tid & 63, skq = tid >> 6;
        int swc = tid >> 3, swk8 = (tid & 7) * 8;
        for (int k0 = 0; k0 < HIDD; k0 += 64) {
            const float4* hsrc = (const float4*)&g_hs[(size_t)(r0+srow)*HIDD + k0 + skq*16];
            float4 v0 = hsrc[0], v1 = hsrc[1], v2 = hsrc[2], v3 = hsrc[3];
            int kb = skq*16;
            hsh[(kb+ 0)*68+srow]=v0.x; hsh[(kb+ 1)*68+srow]=v0.y;
            hsh[(kb+ 2)*68+srow]=v0.z; hsh[(kb+ 3)*68+srow]=v0.w;
            hsh[(kb+ 4)*68+srow]=v1.x; hsh[(kb+ 5)*68+srow]=v1.y;
            hsh[(kb+ 6)*68+srow]=v1.z; hsh[(kb+ 7)*68+srow]=v1.w;
            hsh[(kb+ 8)*68+srow]=v2.x; hsh[(kb+ 9)*68+srow]=v2.y;
            hsh[(kb+10)*68+srow]=v2.z; hsh[(kb+11)*68+srow]=v2.w;
            hsh[(kb+12)*68+srow]=v3.x; hsh[(kb+13)*68+srow]=v3.y;
            hsh[(kb+14)*68+srow]=v3.z; hsh[(kb+15)*68+srow]=v3.w;
            *(float4*)&wsh[swc*68 + swk8] =
                *(const float4*)&W[(size_t)(c0 + swc)*HIDD + k0 + swk8];
            *(float4*)&wsh[swc*68 + swk8 + 4] =
                *(const float4*)&W[(size_t)(c0 + swc)*HIDD + k0 + swk8 + 4];
            __syncthreads();
            #pragma unroll 8
            for (int k = 0; k < 64; k += 4) {
                float4 w0 = *(const float4*)&wsh[(tc*2  )*68 + k];
                float4 w1 = *(const float4*)&wsh[(tc*2+1)*68 + k];
                float4 h0 = *(const float4*)&hsh[(k+0)*68 + tr*4];
                float4 h1 = *(const float4*)&hsh[(k+1)*68 + tr*4];
                float4 h2 = *(const float4*)&hsh[(k+2)*68 + tr*4];
                float4 h3 = *(const float4*)&hsh[(k+3)*68 + tr*4];
                a0[0] += h0.x*w0.x + h1.x*w0.y + h2.x*w0.z + h3.x*w0.w;
                a1[0] += h0.y*w0.x + h1.y*w0.y + h2.y*w0.z + h3.y*w0.w;
                a2[0] += h0.z*w0.x + h1.z*w0.y + h2.z*w0.z + h3.z*w0.w;
                a3[0] += h0.w*w0.x + h1.w*w0.y + h2.w*w0.z + h3.w*w0.w;
                a0[1] += h0.x*w1.x + h1.x*w1.y + h2.x*w1.z + h3.x*w1.w;
                a1[1] += h0.y*w1.x + h1.y*w1.y + h2.y*w1.z + h3.y*w1.w;
                a2[1] += h0.z*w1.x + h1.z*w1.y + h2.z*w1.z + h3.z*w1.w;
                a3[1] += h0.w*w1.x + h1.w*w1.y + h2.w*w1.z + h3.w*w1.w;
            }
            __syncthreads();
        }
        int cc = c0 + tc*2;
        float2 bv = { bias[cc], bias[cc+1] };
        *(float2*)&dst[(r0 + tr*4 + 0)*RECD + cc] = make_float2(a0[0]+bv.x, a0[1]+bv.y);
        *(float2*)&dst[(r0 + tr*4 + 1)*RECD + cc] = make_float2(a1[0]+bv.x, a1[1]+bv.y);
        *(float2*)&dst[(r0 + tr*4 + 2)*RECD + cc] = make_float2(a2[0]+bv.x, a2[1]+bv.y);
        *(float2*)&dst[(r0 + tr*4 + 3)*RECD + cc] = make_float2(a3[0]+bv.x, a3[1]+bv.y);
        return;
    }
    // ---- uv ----
    int row = (blockIdx.x - 64)*2 + (tid >> 7);
    int t128 = tid & 127;
    int l = row & 63;
    const float4* hc = (const float4*)&g_hs[(size_t)row*HIDD];
    const float4* W4 = (const float4*)Ws;
    float4 h0 = hc[t128];
    float4 wu0 = W4[t128], wv0 = W4[384 + t128];
    float au = h0.x*wu0.x + h0.y*wu0.y + h0.z*wu0.z + h0.w*wu0.w;
    float av = h0.x*wv0.x + h0.y*wv0.y + h0.z*wv0.z + h0.w*wv0.w;
    if (l > 0) {
        float4 hb = hc[t128 - 128];
        float4 wu = W4[128 + t128], wv = W4[512 + t128];
        au += hb.x*wu.x + hb.y*wu.y + hb.z*wu.z + hb.w*wu.w;
        av += hb.x*wv.x + hb.y*wv.y + hb.z*wv.z + hb.w*wv.w;
    }
    if (l < 63) {
        float4 hn = hc[t128 + 128];
        float4 wu = W4[256 + t128], wv = W4[640 + t128];
        au += hn.x*wu.x + hn.y*wu.y + hn.z*wu.z + hn.w*wu.w;
        av += hn.x*wv.x + hn.y*wv.y + hn.z*wv.z + hn.w*wv.w;
    }
    #pragma unroll
    for (int o = 16; o; o >>= 1) {
        au += __shfl_xor_sync(0xffffffffu, au, o);
        av += __shfl_xor_sync(0xffffffffu, av, o);
    }
    int warp = tid >> 5, lane = tid & 31;
    if (lane == 0) { pu[warp] = au; pv[warp] = av; }
    __syncthreads();
    if ((tid & 127) == 0) {
        int wb = (tid >> 7)*4;
        g_u[row] = pu[wb]+pu[wb+1]+pu[wb+2]+pu[wb+3];
        g_v[row] = pv[wb]+pv[wb+1]+pv[wb+2]+pv[wb+3];
    }
}

// Eisner width-step: NQ = ceil(w/16) known at compile time.
template<int NQ>
__device__ __forceinline__ void eis_step(
    float* __restrict__ Cr, float* __restrict__ Cl,
    float* __restrict__ Ir, float* __restrict__ Il,
    const float* __restrict__ ush, const float* __restrict__ vsh,
    int w, int spans, int grp, int l16)
{
    bool valid = grp < spans;
    int i = valid ? grp : 0, jn = i + w;
    float t_in[NQ], t_cr[NQ], t_cl[NQ];
    float m_in = -INFINITY, m_cr = -INFINITY, m_cl = -INFINITY;
    #pragma unroll
    for (int q = 0; q < NQ; q++) {
        int o = l16 + q*16;
        t_in[q] = -INFINITY; t_cr[q] = -INFINITY; t_cl[q] = -INFINITY;
        if (valid && o < w) {
            int k = i + o;
            t_in[q] = Cr[i*65 + k] + Cl[(k+1)*65 + jn];
            if (o < w - 1) {
                int k2 = k + 1;
                t_cr[q] = Ir[i*65 + k2] + Cr[k2*65 + jn];
                t_cl[q] = Cl[i*65 + k2] + Il[k2*65 + jn];
            }
        }
        m_in = fmaxf(m_in, t_in[q]);
        m_cr = fmaxf(m_cr, t_cr[q]);
        m_cl = fmaxf(m_cl, t_cl[q]);
    }
    #pragma unroll
    for (int o = 8; o; o >>= 1) {
        m_in = fmaxf(m_in, __shfl_xor_sync(0xffffffffu, m_in, o));
        m_cr = fmaxf(m_cr, __shfl_xor_sync(0xffffffffu, m_cr, o));
        m_cl = fmaxf(m_cl, __shfl_xor_sync(0xffffffffu, m_cl, o));
    }
    float ms_in = fmaxf(m_in, -1e30f);
    float ms_cr = fmaxf(m_cr, -1e30f);
    float ms_cl = fmaxf(m_cl, -1e30f);
    float s_in = 0.f, s_cr = 0.f, s_cl = 0.f;
    #pragma unroll
    for (int q = 0; q < NQ; q++) {
        s_in += __expf(t_in[q] - ms_in);
        s_cr += __expf(t_cr[q] - ms_cr);
        s_cl += __expf(t_cl[q] - ms_cl);
    }
    #pragma unroll
    for (int o = 8; o; o >>= 1) {
        s_in += __shfl_xor_sync(0xffffffffu, s_in, o);
        s_cr += __shfl_xor_sync(0xffffffffu, s_cr, o);
        s_cl += __shfl_xor_sync(0xffffffffu, s_cl, o);
    }
    if (valid && l16 == 0) {
        float inc = ms_in + __logf(s_in);
        float irv = inc + ush[i]  + vsh[jn];
        float ilv = inc + ush[jn] + vsh[i];
        Ir[i*65 + jn] = irv;
        Il[i*65 + jn] = ilv;
        float lcr = ms_cr + __logf(s_cr);
        float M = fmaxf(lcr, irv);
        Cr[i*65 + jn] = M + __logf(__expf(lcr - M) + __expf(irv - M));
        float lcl = ms_cl + __logf(s_cl);
        float Ml = fmaxf(lcl, ilv);
        Cl[i*65 + jn] = Ml + __logf(__expf(lcl - Ml) + __expf(ilv - Ml));
    }
}

#define EIS_BAND(W0, W1B, NQV)                                              \
    for (int w = (W0); w <= (W1B); w++) {                                    \
        int spans = Ln - w;                                                  \
        if (wrp*2 < spans)                                                   \
            eis_step<NQV>(Cr, Cl, Ir, Il, ush, vsh, w, spans, grp, l16);     \
        __syncthreads();                                                     \
    }

// K4 (fused): blocks 0..7 Eisner; blocks 8..39 scores; block 0 runs final.
__global__ void k_eis_sc(const float* __restrict__ bs, const int* __restrict__ heads,
                         const float* __restrict__ prior, float* __restrict__ out) {
    extern __shared__ float smf[];
    int tid = threadIdx.x;
    if (blockIdx.x < 8) {
        float* Cr = smf;         float* Cl = smf + 4160;
        float* Ir = smf + 8320;  float* Il = smf + 12480;
        __shared__ float ush[64], vsh[64];
        int b = blockIdx.x;
        if (tid < 64) { ush[tid] = g_u[b*Ln + tid] + bs[0]; vsh[tid] = g_v[b*Ln + tid]; }
        for (int idx = tid; idx < 4160; idx += 1024) {
            int i = idx / 65, jj = idx % 65;
            float dv = (jj < 64 && i == jj) ? 0.0f : NEGV;
            Cr[idx] = dv; Cl[idx] = dv; Ir[idx] = NEGV; Il[idx] = NEGV;
        }
        __syncthreads();
        int grp = tid >> 4, l16 = tid & 15, wrp = tid >> 5;
        EIS_BAND(1, 16, 1)
        EIS_BAND(17, 32, 2)
        EIS_BAND(33, 48, 3)
        EIS_BAND(49, 63, 4)
        if (tid == 0) g_logZ[b] = Cr[Ln - 1];
        __threadfence();
        __syncthreads();
        if (blockIdx.x == 0) {
            if (tid == 0) {
                unsigned c = atomicAdd(&g_barr3, 1u) + 1u;
                if (c < 40u) {
                    volatile unsigned* p = &g_barr3;
                    while (*p < 40u) { }
                }
            }
            __syncthreads();
            if (tid < 256) {
                int warp = tid >> 5, lane = tid & 31;
                __shared__ float sb[8];
                int b2 = warp;
                float bsv = bs[0];
                int m1 = lane + 1, m2 = lane + 33;
                float v1, v2;
                {
                    int hd = heads[b2*Ln + m1];
                    v1 = __ldcg(&g_u[b2*Ln + hd]) + __ldcg(&g_v[b2*Ln + m1]) + bsv
                       + __ldcg(&g_s[((size_t)b2*Ln + hd)*Ln + m1])
                       - __ldcg(&g_rowlse[b2*Ln + hd])
                       + prior[((size_t)b2*Ln + hd)*Ln + m1] * (1.0f/64.0f);
                }
                if (m2 < Ln) {
                    int hd = heads[b2*Ln + m2];
                    v2 = __ldcg(&g_u[b2*Ln + hd]) + __ldcg(&g_v[b2*Ln + m2]) + bsv
                       + __ldcg(&g_s[((size_t)b2*Ln + hd)*Ln + m2])
                       - __ldcg(&g_rowlse[b2*Ln + hd])
                       + prior[((size_t)b2*Ln + hd)*Ln + m2] * (1.0f/64.0f);
                } else v2 = -INFINITY;
                float mx = fmaxf(v1, v2);
                #pragma unroll
                for (int o = 16; o; o >>= 1) mx = fmaxf(mx, __shfl_xor_sync(0xffffffffu, mx, o));
                float sum = __expf(v1 - mx) + __expf(v2 - mx);
                #pragma unroll
                for (int o = 16; o; o >>= 1) sum += __shfl_xor_sync(0xffffffffu, sum, o);
                if (lane == 0) sb[b2] = (mx + __logf(sum)) - __ldcg(&g_logZ[b2]);
                __syncthreads();
                if (tid == 0) {
                    float t = 0.f;
                    for (int q = 0; q < 8; q++) t += sb[q];
                    out[0] = -t * (1.0f/8.0f);
                    for (int q = 0; q < 16; q++) g_barr[q] = 0u;
                    g_barr2 = 0u;
                    g_barr3 = 0u;
                }
            }
        } else {
            if (tid == 0) atomicAdd(&g_barr3, 1u);
        }
        return;
    }
    // ---- scores ----
    int sb2 = blockIdx.x - 8;
    int b = sb2 >> 2, i0 = (sb2 & 3) * 16;
    float* p1sh = smf;              // 16 x 132
    float* p2sh = smf + 16*132;     // 64 x 132
    __shared__ float mm[32], ss[32];
    if (tid < 512) {
        int rr = tid >> 5, e4 = tid & 31;
        *(float4*)&p1sh[rr*132 + e4*4] = *(const float4*)&g_p1[(b*Ln + i0 + rr)*RECD + e4*4];
    }
    #pragma unroll
    for (int q = 0; q < 2; q++) {
        int li = tid + q*1024;
        int rr = li >> 5, e4 = li & 31;
        *(float4*)&p2sh[rr*132 + e4*4] = *(const float4*)&g_p2[(b*Ln + rr)*RECD + e4*4];
    }
    __syncthreads();
    int i_l = tid >> 6, j = tid & 63;
    float dot = 0.f;
    #pragma unroll 8
    for (int e4 = 0; e4 < 32; e4++) {
        float4 a = *(const float4*)&p1sh[i_l*132 + e4*4];
        float4 bv = *(const float4*)&p2sh[j*132 + e4*4];
        dot += a.x*bv.x + a.y*bv.y + a.z*bv.z + a.w*bv.w;
    }
    int i = i0 + i_l;
    g_s[((size_t)b*Ln + i)*Ln + j] = dot;
    float m = dot;
    #pragma unroll
    for (int o = 16; o; o >>= 1) m = fmaxf(m, __shfl_xor_sync(0xffffffffu, m, o));
    float sum = __expf(dot - m);
    #pragma unroll
    for (int o = 16; o; o >>= 1) sum += __shfl_xor_sync(0xffffffffu, sum, o);
    int warp = tid >> 5, lane = tid & 31;
    if (lane == 0) { mm[warp] = m; ss[warp] = sum; }
    __syncthreads();
    if (tid < 16) {
        float m0 = mm[tid*2], m1 = mm[tid*2+1];
        float M = fmaxf(m0, m1);
        float S = ss[tid*2]*__expf(m0 - M) + ss[tid*2+1]*__expf(m1 - M);
        g_rowlse[b*Ln + i0 + tid] = M + __logf(S);
    }
    __threadfence();
    __syncthreads();
    if (tid == 0) atomicAdd(&g_barr3, 1u);
}

extern "C" void kernel_launch(void* const* d_in, const int* in_sizes, int n_in,
                              void* d_out, int out_size) {
    const int*   sents = (const int*)  d_in[0];
    const float* mask  = (const float*)d_in[1];
    const float* prior = (const float*)d_in[2];
    const int*   heads = (const int*)  d_in[3];
    const float* emb   = (const float*)d_in[4];
    const float* Wih_f = (const float*)d_in[5];
    const float* Whh_f = (const float*)d_in[6];
    const float* bih_f = (const float*)d_in[7];
    const float* bhh_f = (const float*)d_in[8];
    const float* Wih_b = (const float*)d_in[9];
    const float* Whh_b = (const float*)d_in[10];
    const float* bih_b = (const float*)d_in[11];
    const float* bhh_b = (const float*)d_in[12];
    const float* W1    = (const float*)d_in[13];
    const float* b1    = (const float*)d_in[14];
    const float* W2    = (const float*)d_in[15];
    const float* b2    = (const float*)d_in[16];
    const float* Ws    = (const float*)d_in[17];
    const float* bsv   = (const float*)d_in[18];
    float* out = (float*)d_out;
    (void)in_sizes; (void)n_in; (void)out_size;

    cudaFuncSetAttribute(k_lstm_all, cudaFuncAttributeMaxDynamicSharedMemorySize, 22656*4);
    cudaFuncSetAttribute(k_eis_sc,   cudaFuncAttributeMaxDynamicSharedMemorySize, 16640*4);

    dim3 g1(8, 16, 2);
    k_emb_xw<<<g1, 256>>>(sents, mask, emb, Wih_f, bih_f, bhh_f, Wih_b, bih_b, bhh_b);
    k_lstm_all<<<128, 128, 22656*4>>>(Whh_f, Whh_b);
    k_uvp12<<<320, 256>>>(Ws, W1, b1, W2, b2);
    k_eis_sc<<<40, 1024, 16640*4>>>(bsv, heads, prior, out);
}

// round 13
// speedup vs baseline: 1.8411x; 1.0877x over previous
#include <cuda_runtime.h>
#include <math.h>

#define Bz 8
#define Ln 64
#define WL 32
#define EMBD 256
#define H2 256
#define HIDD 512
#define RECD 128
#define NEGV -1000000000.0f

__device__ float g_embeds[Bz*Ln*EMBD];
__device__ float g_xw[2*Bz*Ln*1024];
__device__ float g_hT[4*H2*Ln];          // [buf(2)][dir(2)][unit 256][n 64]
__device__ unsigned g_barr[16];          // lstm [dir][step]
__device__ unsigned g_barr2;             // embed->xw grid barrier
__device__ unsigned g_barr3;             // eis/scores->final arrivals
__device__ unsigned g_barrU;             // uv done (64 blocks)
__device__ unsigned g_barrP;             // p12 done (16 blocks)
__device__ float g_hs[Bz*Ln*HIDD];
__device__ float g_u[Bz*Ln];
__device__ float g_v[Bz*Ln];
__device__ float g_p1[Bz*Ln*RECD];
__device__ float g_p2[Bz*Ln*RECD];
__device__ float g_s[Bz*Ln*Ln];
__device__ float g_rowlse[Bz*Ln];
__device__ float g_logZ[Bz];

__device__ __forceinline__ float fsig(float x) {
    return __fdividef(1.0f, 1.0f + __expf(-x));
}

// K1 (fused): embed (2 rows/block) -> grid barrier -> xW GEMM.
__global__ void k_emb_xw(const int* __restrict__ sents, const float* __restrict__ mask,
                         const float* __restrict__ emb,
                         const float* __restrict__ Wf, const float* __restrict__ bif,
                         const float* __restrict__ bhf,
                         const float* __restrict__ Wb, const float* __restrict__ bib,
                         const float* __restrict__ bhb) {
    int lin = blockIdx.x + blockIdx.y*8 + blockIdx.z*128;   // 0..255
    int tid = threadIdx.x;
    __shared__ __align__(16) float Ash[64*68];
    __shared__ __align__(16) float Wsh[64*68];
    __shared__ int sw[WL]; __shared__ float sm[WL]; __shared__ float sden;
    #pragma unroll
    for (int r = 0; r < 2; r++) {
        int row = lin*2 + r;
        if (tid < WL) { sw[tid] = sents[row*WL + tid]; sm[tid] = mask[row*WL + tid]; }
        __syncthreads();
        if (tid == 0) {
            float e = 0.f;
            for (int w = 0; w < WL; w++) e += sm[w];
            sden = e + (e == 0.0f ? 1.0f : 0.0f);
        }
        __syncthreads();
        float acc = 0.f;
        #pragma unroll 8
        for (int w = 0; w < WL; w++) acc += emb[(size_t)sw[w]*EMBD + tid] * sm[w];
        g_embeds[row*EMBD + tid] = acc / sden;
        __syncthreads();
    }
    __threadfence();
    if (tid == 0) {
        unsigned c = atomicAdd(&g_barr2, 1u) + 1u;
        if (c < 256u) {
            volatile unsigned* p = &g_barr2;
            while (*p < 256u) { }
        }
    }
    __syncthreads();
    int dir = blockIdx.z;
    const float* W  = dir ? Wb  : Wf;
    const float* bi = dir ? bib : bif;
    const float* bh = dir ? bhb : bhf;
    int r0 = blockIdx.x * 64, g0 = blockIdx.y * 64;
    int ri = tid & 15, gi = tid >> 4;
    float acc[4][4] = {};
    for (int e0 = 0; e0 < EMBD; e0 += 64) {
        #pragma unroll 4
        for (int q = 0; q < 16; q++) {
            int li = tid + q*256;
            int xx = li >> 6, ee = li & 63;
            Ash[ee*68 + xx] = __ldcg(&g_embeds[(r0+xx)*EMBD + e0 + ee]);
            Wsh[ee*68 + xx] = W[(g0+xx)*EMBD + e0 + ee];
        }
        __syncthreads();
        #pragma unroll 8
        for (int e = 0; e < 64; e++) {
            float4 av = *(const float4*)&Ash[e*68 + ri*4];
            float4 wv = *(const float4*)&Wsh[e*68 + gi*4];
            float aa[4] = {av.x, av.y, av.z, av.w};
            float ww[4] = {wv.x, wv.y, wv.z, wv.w};
            #pragma unroll
            for (int a = 0; a < 4; a++)
                #pragma unroll
                for (int g = 0; g < 4; g++) acc[a][g] += aa[a]*ww[g];
        }
        __syncthreads();
    }
    #pragma unroll
    for (int a = 0; a < 4; a++)
        #pragma unroll
        for (int g = 0; g < 4; g++) {
            int row = r0 + ri*4 + a, gg = g0 + gi*4 + g;
            g_xw[((size_t)dir*Bz*Ln + row)*1024 + gg] = acc[a][g] + bi[gg] + bh[gg];
        }
}

// K2: persistent LSTM — all 8 steps in one kernel.
__global__ void k_lstm_all(const float* __restrict__ Whh_f, const float* __restrict__ Whh_b) {
    extern __shared__ float smem[];
    float* wsh = smem;                  // [gc 16][e 256] pitch 260
    float* hsh = smem + 4160;           // [e 256][n 64] pitch 68
    float* gsh = smem + 4160 + 17408;   // [gc 16][n 64] pitch 68
    int bx = blockIdx.x;
    int dir = bx >> 6, ub = bx & 63, u0 = ub*4;
    const float* Whh = dir ? Whh_b : Whh_f;
    int tid = threadIdx.x;

    #pragma unroll 8
    for (int q = 0; q < 32; q++) {
        int li = tid + q*128;
        int gc = li >> 8, e = li & 255;
        int ul = gc >> 2, gate = gc & 3;
        wsh[gc*260 + e] = Whh[(gate*H2 + u0 + ul)*H2 + e];
    }
    int ng = tid >> 3, gg = tid & 7;
    int n_c = tid & 63, ul_c = tid >> 6;
    float c0 = 0.f, c1 = 0.f;
    __syncthreads();

    for (int s = 0; s < Bz; s++) {
        int t = dir ? (Bz-1-s) : s;
        const float* xb = &g_xw[((size_t)(dir*Bz*Ln + t*Ln + n_c))*1024 + u0 + ul_c];
        float xw0[4], xw1[4];
        #pragma unroll
        for (int g = 0; g < 4; g++) { xw0[g] = xb[g*256]; xw1[g] = xb[g*256 + 2]; }

        float a00=0.f,a01=0.f,a10=0.f,a11=0.f,a20=0.f,a21=0.f,a30=0.f,a31=0.f;
        if (s > 0) {
            const float* hp = &g_hT[((s&1)*2 + dir)*H2*Ln];
            #pragma unroll 8
            for (int q = 0; q < 32; q++) {
                int idx = (tid + q*128)*4;
                int e = idx >> 6, n = idx & 63;
                float4 hv = __ldcg((const float4*)(hp + idx));
                *(float4*)&hsh[e*68 + n] = hv;
            }
            __syncthreads();
            #pragma unroll 4
            for (int e4 = 0; e4 < H2; e4 += 4) {
                float4 w0 = *(const float4*)&wsh[(gg*2  )*260 + e4];
                float4 w1 = *(const float4*)&wsh[(gg*2+1)*260 + e4];
                float wa[4] = {w0.x, w0.y, w0.z, w0.w};
                float wb[4] = {w1.x, w1.y, w1.z, w1.w};
                #pragma unroll
                for (int k = 0; k < 4; k++) {
                    float4 hv = *(const float4*)&hsh[(e4+k)*68 + ng*4];
                    a00 += hv.x*wa[k]; a01 += hv.x*wb[k];
                    a10 += hv.y*wa[k]; a11 += hv.y*wb[k];
                    a20 += hv.z*wa[k]; a21 += hv.z*wb[k];
                    a30 += hv.w*wa[k]; a31 += hv.w*wb[k];
                }
            }
        } else {
            __syncthreads();
        }
        gsh[(gg*2  )*68 + ng*4 + 0] = a00; gsh[(gg*2+1)*68 + ng*4 + 0] = a01;
        gsh[(gg*2  )*68 + ng*4 + 1] = a10; gsh[(gg*2+1)*68 + ng*4 + 1] = a11;
        gsh[(gg*2  )*68 + ng*4 + 2] = a20; gsh[(gg*2+1)*68 + ng*4 + 2] = a21;
        gsh[(gg*2  )*68 + ng*4 + 3] = a30; gsh[(gg*2+1)*68 + ng*4 + 3] = a31;
        __syncthreads();
        {
            float iv = gsh[(ul_c*4+0)*68 + n_c] + xw0[0];
            float fv = gsh[(ul_c*4+1)*68 + n_c] + xw0[1];
            float gv = gsh[(ul_c*4+2)*68 + n_c] + xw0[2];
            float ov = gsh[(ul_c*4+3)*68 + n_c] + xw0[3];
            c0 = fsig(fv)*c0 + fsig(iv)*__tanhf(gv);
            float h0 = fsig(ov)*__tanhf(c0);
            int ul2 = ul_c + 2;
            float iv1 = gsh[(ul2*4+0)*68 + n_c] + xw1[0];
            float fv1 = gsh[(ul2*4+1)*68 + n_c] + xw1[1];
            float gv1 = gsh[(ul2*4+2)*68 + n_c] + xw1[2];
            float ov1 = gsh[(ul2*4+3)*68 + n_c] + xw1[3];
            c1 = fsig(fv1)*c1 + fsig(iv1)*__tanhf(gv1);
            float h1 = fsig(ov1)*__tanhf(c1);
            int wbuf = (((s+1)&1)*2 + dir)*H2*Ln;
            __stcg(&g_hT[wbuf + (u0+ul_c )*Ln + n_c], h0);
            __stcg(&g_hT[wbuf + (u0+ul2  )*Ln + n_c], h1);
            g_hs[((size_t)t*Ln + n_c)*HIDD + dir*H2 + u0 + ul_c] = h0;
            g_hs[((size_t)t*Ln + n_c)*HIDD + dir*H2 + u0 + ul2 ] = h1;
        }
        if (s < Bz-1) {
            __threadfence();
            __syncthreads();
            if (tid == 0) {
                unsigned c = atomicAdd(&g_barr[dir*8 + s], 1u) + 1u;
                if (c < 64u) {
                    volatile unsigned* p = &g_barr[dir*8 + s];
                    while (*p < 64u) { }
                }
            }
            __syncthreads();
        }
    }
}

// Eisner width-step: NQ = ceil(w/16) known at compile time.
template<int NQ>
__device__ __forceinline__ void eis_step(
    float* __restrict__ Cr, float* __restrict__ Cl,
    float* __restrict__ Ir, float* __restrict__ Il,
    const float* __restrict__ ush, const float* __restrict__ vsh,
    int w, int spans, int grp, int l16)
{
    bool valid = grp < spans;
    int i = valid ? grp : 0, jn = i + w;
    float t_in[NQ], t_cr[NQ], t_cl[NQ];
    float m_in = -INFINITY, m_cr = -INFINITY, m_cl = -INFINITY;
    #pragma unroll
    for (int q = 0; q < NQ; q++) {
        int o = l16 + q*16;
        t_in[q] = -INFINITY; t_cr[q] = -INFINITY; t_cl[q] = -INFINITY;
        if (valid && o < w) {
            int k = i + o;
            t_in[q] = Cr[i*65 + k] + Cl[(k+1)*65 + jn];
            if (o < w - 1) {
                int k2 = k + 1;
                t_cr[q] = Ir[i*65 + k2] + Cr[k2*65 + jn];
                t_cl[q] = Cl[i*65 + k2] + Il[k2*65 + jn];
            }
        }
        m_in = fmaxf(m_in, t_in[q]);
        m_cr = fmaxf(m_cr, t_cr[q]);
        m_cl = fmaxf(m_cl, t_cl[q]);
    }
    #pragma unroll
    for (int o = 8; o; o >>= 1) {
        m_in = fmaxf(m_in, __shfl_xor_sync(0xffffffffu, m_in, o));
        m_cr = fmaxf(m_cr, __shfl_xor_sync(0xffffffffu, m_cr, o));
        m_cl = fmaxf(m_cl, __shfl_xor_sync(0xffffffffu, m_cl, o));
    }
    float ms_in = fmaxf(m_in, -1e30f);
    float ms_cr = fmaxf(m_cr, -1e30f);
    float ms_cl = fmaxf(m_cl, -1e30f);
    float s_in = 0.f, s_cr = 0.f, s_cl = 0.f;
    #pragma unroll
    for (int q = 0; q < NQ; q++) {
        s_in += __expf(t_in[q] - ms_in);
        s_cr += __expf(t_cr[q] - ms_cr);
        s_cl += __expf(t_cl[q] - ms_cl);
    }
    #pragma unroll
    for (int o = 8; o; o >>= 1) {
        s_in += __shfl_xor_sync(0xffffffffu, s_in, o);
        s_cr += __shfl_xor_sync(0xffffffffu, s_cr, o);
        s_cl += __shfl_xor_sync(0xffffffffu, s_cl, o);
    }
    if (valid && l16 == 0) {
        float inc = ms_in + __logf(s_in);
        float irv = inc + ush[i]  + vsh[jn];
        float ilv = inc + ush[jn] + vsh[i];
        Ir[i*65 + jn] = irv;
        Il[i*65 + jn] = ilv;
        float lcr = ms_cr + __logf(s_cr);
        float M = fmaxf(lcr, irv);
        Cr[i*65 + jn] = M + __logf(__expf(lcr - M) + __expf(irv - M));
        float lcl = ms_cl + __logf(s_cl);
        float Ml = fmaxf(lcl, ilv);
        Cl[i*65 + jn] = Ml + __logf(__expf(lcl - Ml) + __expf(ilv - Ml));
    }
}

#define EIS_BAND(W0, W1B, NQV)                                              \
    for (int w = (W0); w <= (W1B); w++) {                                    \
        int spans = Ln - w;                                                  \
        if (wrp*2 < spans)                                                   \
            eis_step<NQV>(Cr, Cl, Ir, Il, ush, vsh, w, spans, grp, l16);     \
        __syncthreads();                                                     \
    }

// K3 (tail, fully fused): blocks 0..7 eisner(+final in blk0); 8..39 scores;
// 40..55 p12 (4 col-subtiles per block); 56..119 uv (8 rows/block).
// Intra-kernel spin barriers: uv->eisner (g_barrU), p12->scores (g_barrP),
// all->final (g_barr3). 120 blocks x 1024 thr, single co-resident wave.
__global__ void __launch_bounds__(1024, 1)
k_tail(const float* __restrict__ bs, const int* __restrict__ heads,
       const float* __restrict__ prior, const float* __restrict__ Ws,
       const float* __restrict__ W1, const float* __restrict__ b1,
       const float* __restrict__ W2, const float* __restrict__ b2,
       float* __restrict__ out) {
    extern __shared__ float smf[];
    int tid = threadIdx.x;
    int bid = blockIdx.x;
    if (bid < 8) {
        // ---- Eisner ----
        float* Cr = smf;         float* Cl = smf + 4160;
        float* Ir = smf + 8320;  float* Il = smf + 12480;
        __shared__ float ush[64], vsh[64];
        int b = bid;
        for (int idx = tid; idx < 4160; idx += 1024) {
            int i = idx / 65, jj = idx % 65;
            float dv = (jj < 64 && i == jj) ? 0.0f : NEGV;
            Cr[idx] = dv; Cl[idx] = dv; Ir[idx] = NEGV; Il[idx] = NEGV;
        }
        // wait for uv producers
        if (tid == 0) {
            volatile unsigned* p = &g_barrU;
            while (*p < 64u) { }
        }
        __syncthreads();
        if (tid < 64) {
            ush[tid] = __ldcg(&g_u[b*Ln + tid]) + bs[0];
            vsh[tid] = __ldcg(&g_v[b*Ln + tid]);
        }
        __syncthreads();
        int grp = tid >> 4, l16 = tid & 15, wrp = tid >> 5;
        EIS_BAND(1, 16, 1)
        EIS_BAND(17, 32, 2)
        EIS_BAND(33, 48, 3)
        EIS_BAND(49, 63, 4)
        if (tid == 0) g_logZ[b] = Cr[Ln - 1];
        __threadfence();
        __syncthreads();
        if (bid == 0) {
            if (tid == 0) {
                unsigned c = atomicAdd(&g_barr3, 1u) + 1u;
                if (c < 40u) {
                    volatile unsigned* p = &g_barr3;
                    while (*p < 40u) { }
                }
            }
            __syncthreads();
            if (tid < 256) {
                int warp = tid >> 5, lane = tid & 31;
                __shared__ float sb[8];
                int b2 = warp;
                float bsv = bs[0];
                int m1 = lane + 1, m2 = lane + 33;
                float v1, v2;
                {
                    int hd = heads[b2*Ln + m1];
                    v1 = __ldcg(&g_u[b2*Ln + hd]) + __ldcg(&g_v[b2*Ln + m1]) + bsv
                       + __ldcg(&g_s[((size_t)b2*Ln + hd)*Ln + m1])
                       - __ldcg(&g_rowlse[b2*Ln + hd])
                       + prior[((size_t)b2*Ln + hd)*Ln + m1] * (1.0f/64.0f);
                }
                if (m2 < Ln) {
                    int hd = heads[b2*Ln + m2];
                    v2 = __ldcg(&g_u[b2*Ln + hd]) + __ldcg(&g_v[b2*Ln + m2]) + bsv
                       + __ldcg(&g_s[((size_t)b2*Ln + hd)*Ln + m2])
                       - __ldcg(&g_rowlse[b2*Ln + hd])
                       + prior[((size_t)b2*Ln + hd)*Ln + m2] * (1.0f/64.0f);
                } else v2 = -INFINITY;
                float mx = fmaxf(v1, v2);
                #pragma unroll
                for (int o = 16; o; o >>= 1) mx = fmaxf(mx, __shfl_xor_sync(0xffffffffu, mx, o));
                float sum = __expf(v1 - mx) + __expf(v2 - mx);
                #pragma unroll
                for (int o = 16; o; o >>= 1) sum += __shfl_xor_sync(0xffffffffu, sum, o);
                if (lane == 0) sb[b2] = (mx + __logf(sum)) - __ldcg(&g_logZ[b2]);
                __syncthreads();
                if (tid == 0) {
                    float t = 0.f;
                    for (int q = 0; q < 8; q++) t += sb[q];
                    out[0] = -t * (1.0f/8.0f);
                    for (int q = 0; q < 16; q++) g_barr[q] = 0u;
                    g_barr2 = 0u; g_barr3 = 0u; g_barrU = 0u; g_barrP = 0u;
                }
            }
        } else {
            if (tid == 0) atomicAdd(&g_barr3, 1u);
        }
        return;
    }
    if (bid < 40) {
        // ---- scores (waits for p12) ----
        int sb2 = bid - 8;
        int b = sb2 >> 2, i0 = (sb2 & 3) * 16;
        float* p1sh = smf;              // 16 x 132
        float* p2sh = smf + 16*132;     // 64 x 132
        __shared__ float mm[32], ss[32];
        if (tid == 0) {
            volatile unsigned* p = &g_barrP;
            while (*p < 16u) { }
        }
        __syncthreads();
        if (tid < 512) {
            int rr = tid >> 5, e4 = tid & 31;
            *(float4*)&p1sh[rr*132 + e4*4] =
                __ldcg((const float4*)&g_p1[(b*Ln + i0 + rr)*RECD + e4*4]);
        }
        #pragma unroll
        for (int q = 0; q < 2; q++) {
            int li = tid + q*1024;
            int rr = li >> 5, e4 = li & 31;
            *(float4*)&p2sh[rr*132 + e4*4] =
                __ldcg((const float4*)&g_p2[(b*Ln + rr)*RECD + e4*4]);
        }
        __syncthreads();
        int i_l = tid >> 6, j = tid & 63;
        float dot = 0.f;
        #pragma unroll 8
        for (int e4 = 0; e4 < 32; e4++) {
            float4 a = *(const float4*)&p1sh[i_l*132 + e4*4];
            float4 bv = *(const float4*)&p2sh[j*132 + e4*4];
            dot += a.x*bv.x + a.y*bv.y + a.z*bv.z + a.w*bv.w;
        }
        int i = i0 + i_l;
        g_s[((size_t)b*Ln + i)*Ln + j] = dot;
        float m = dot;
        #pragma unroll
        for (int o = 16; o; o >>= 1) m = fmaxf(m, __shfl_xor_sync(0xffffffffu, m, o));
        float sum = __expf(dot - m);
        #pragma unroll
        for (int o = 16; o; o >>= 1) sum += __shfl_xor_sync(0xffffffffu, sum, o);
        int warp = tid >> 5, lane = tid & 31;
        if (lane == 0) { mm[warp] = m; ss[warp] = sum; }
        __syncthreads();
        if (tid < 16) {
            float m0 = mm[tid*2], m1 = mm[tid*2+1];
            float M = fmaxf(m0, m1);
            float S = ss[tid*2]*__expf(m0 - M) + ss[tid*2+1]*__expf(m1 - M);
            g_rowlse[b*Ln + i0 + tid] = M + __logf(S);
        }
        __threadfence();
        __syncthreads();
        if (tid == 0) atomicAdd(&g_barr3, 1u);
        return;
    }
    if (bid < 56) {
        // ---- p12 GEMM: 16 blocks, 4 col-subtiles sharing one h row-tile ----
        int pbi = bid - 40;             // 0..15
        int br = pbi >> 1, cq = pbi & 1;
        int st = tid >> 8;              // subtile 0..3
        int stid = tid & 255;
        int bc = cq*4 + st;
        const float* W    = (bc < 4) ? W1 : W2;
        const float* bias = (bc < 4) ? b1 : b2;
        float* dst        = (bc < 4) ? g_p1 : g_p2;
        int c0 = (bc & 3) * 32;
        int r0 = br * 64;
        float* hsh = smf;                         // 64k x 64row pitch 68
        float* wsh = smf + 4352 + st*2176;        // 32c x 64k pitch 68
        int tr = stid >> 4, tc = stid & 15;
        float a0[2] = {}, a1[2] = {}, a2[2] = {}, a3[2] = {};
        int srow = tid & 63, skq = tid >> 6;      // 0..15
        int swc = stid >> 3, swk8 = (stid & 7) * 8;
        for (int k0 = 0; k0 < HIDD; k0 += 64) {
            float4 v = *(const float4*)&g_hs[(size_t)(r0+srow)*HIDD + k0 + skq*4];
            int kb = skq*4;
            hsh[(kb+0)*68+srow]=v.x; hsh[(kb+1)*68+srow]=v.y;
            hsh[(kb+2)*68+srow]=v.z; hsh[(kb+3)*68+srow]=v.w;
            *(float4*)&wsh[swc*68 + swk8] =
                *(const float4*)&W[(size_t)(c0 + swc)*HIDD + k0 + swk8];
            *(float4*)&wsh[swc*68 + swk8 + 4] =
                *(const float4*)&W[(size_t)(c0 + swc)*HIDD + k0 + swk8 + 4];
            __syncthreads();
            #pragma unroll 8
            for (int k = 0; k < 64; k += 4) {
                float4 w0 = *(const float4*)&wsh[(tc*2  )*68 + k];
                float4 w1 = *(const float4*)&wsh[(tc*2+1)*68 + k];
                float4 h0 = *(const float4*)&hsh[(k+0)*68 + tr*4];
                float4 h1 = *(const float4*)&hsh[(k+1)*68 + tr*4];
                float4 h2 = *(const float4*)&hsh[(k+2)*68 + tr*4];
                float4 h3 = *(const float4*)&hsh[(k+3)*68 + tr*4];
                a0[0] += h0.x*w0.x + h1.x*w0.y + h2.x*w0.z + h3.x*w0.w;
                a1[0] += h0.y*w0.x + h1.y*w0.y + h2.y*w0.z + h3.y*w0.w;
                a2[0] += h0.z*w0.x + h1.z*w0.y + h2.z*w0.z + h3.z*w0.w;
                a3[0] += h0.w*w0.x + h1.w*w0.y + h2.w*w0.z + h3.w*w0.w;
                a0[1] += h0.x*w1.x + h1.x*w1.y + h2.x*w1.z + h3.x*w1.w;
                a1[1] += h0.y*w1.x + h1.y*w1.y + h2.y*w1.z + h3.y*w1.w;
                a2[1] += h0.z*w1.x + h1.z*w1.y + h2.z*w1.z + h3.z*w1.w;
                a3[1] += h0.w*w1.x + h1.w*w1.y + h2.w*w1.z + h3.w*w1.w;
            }
            __syncthreads();
        }
        int cc = c0 + tc*2;
        float2 bv = { bias[cc], bias[cc+1] };
        *(float2*)&dst[(r0 + tr*4 + 0)*RECD + cc] = make_float2(a0[0]+bv.x, a0[1]+bv.y);
        *(float2*)&dst[(r0 + tr*4 + 1)*RECD + cc] = make_float2(a1[0]+bv.x, a1[1]+bv.y);
        *(float2*)&dst[(r0 + tr*4 + 2)*RECD + cc] = make_float2(a2[0]+bv.x, a2[1]+bv.y);
        *(float2*)&dst[(r0 + tr*4 + 3)*RECD + cc] = make_float2(a3[0]+bv.x, a3[1]+bv.y);
        __threadfence();
        __syncthreads();
        if (tid == 0) atomicAdd(&g_barrP, 1u);
        return;
    }
    // ---- uv: 64 blocks x 8 rows ----
    {
        __shared__ float pu[32], pv[32];
        int row = (bid - 56)*8 + (tid >> 7);
        int t128 = tid & 127;
        int l = row & 63;
        const float4* hc = (const float4*)&g_hs[(size_t)row*HIDD];
        const float4* W4 = (const float4*)Ws;
        float4 h0 = hc[t128];
        float4 wu0 = W4[t128], wv0 = W4[384 + t128];
        float au = h0.x*wu0.x + h0.y*wu0.y + h0.z*wu0.z + h0.w*wu0.w;
        float av = h0.x*wv0.x + h0.y*wv0.y + h0.z*wv0.z + h0.w*wv0.w;
        if (l > 0) {
            float4 hb = hc[t128 - 128];
            float4 wu = W4[128 + t128], wv = W4[512 + t128];
            au += hb.x*wu.x + hb.y*wu.y + hb.z*wu.z + hb.w*wu.w;
            av += hb.x*wv.x + hb.y*wv.y + hb.z*wv.z + hb.w*wv.w;
        }
        if (l < 63) {
            float4 hn = hc[t128 + 128];
            float4 wu = W4[256 + t128], wv = W4[640 + t128];
            au += hn.x*wu.x + hn.y*wu.y + hn.z*wu.z + hn.w*wu.w;
            av += hn.x*wv.x + hn.y*wv.y + hn.z*wv.z + hn.w*wv.w;
        }
        #pragma unroll
        for (int o = 16; o; o >>= 1) {
            au += __shfl_xor_sync(0xffffffffu, au, o);
            av += __shfl_xor_sync(0xffffffffu, av, o);
        }
        int warp = tid >> 5, lane = tid & 31;
        if (lane == 0) { pu[warp] = au; pv[warp] = av; }
        __syncthreads();
        if (t128 == 0) {
            int wb = (tid >> 7)*4;
            g_u[row] = pu[wb]+pu[wb+1]+pu[wb+2]+pu[wb+3];
            g_v[row] = pv[wb]+pv[wb+1]+pv[wb+2]+pv[wb+3];
        }
        __threadfence();
        __syncthreads();
        if (tid == 0) atomicAdd(&g_barrU, 1u);
    }
}

extern "C" void kernel_launch(void* const* d_in, const int* in_sizes, int n_in,
                              void* d_out, int out_size) {
    const int*   sents = (const int*)  d_in[0];
    const float* mask  = (const float*)d_in[1];
    const float* prior = (const float*)d_in[2];
    const int*   heads = (const int*)  d_in[3];
    const float* emb   = (const float*)d_in[4];
    const float* Wih_f = (const float*)d_in[5];
    const float* Whh_f = (const float*)d_in[6];
    const float* bih_f = (const float*)d_in[7];
    const float* bhh_f = (const float*)d_in[8];
    const float* Wih_b = (const float*)d_in[9];
    const float* Whh_b = (const float*)d_in[10];
    const float* bih_b = (const float*)d_in[11];
    const float* bhh_b = (const float*)d_in[12];
    const float* W1    = (const float*)d_in[13];
    const float* b1    = (const float*)d_in[14];
    const float* W2    = (const float*)d_in[15];
    const float* b2    = (const float*)d_in[16];
    const float* Ws    = (const float*)d_in[17];
    const float* bsv   = (const float*)d_in[18];
    float* out = (float*)d_out;
    (void)in_sizes; (void)n_in; (void)out_size;

    cudaFuncSetAttribute(k_lstm_all, cudaFuncAttributeMaxDynamicSharedMemorySize, 22656*4);
    cudaFuncSetAttribute(k_tail,     cudaFuncAttributeMaxDynamicSharedMemorySize, 16640*4);

    dim3 g1(8, 16, 2);
    k_emb_xw<<<g1, 256>>>(sents, mask, emb, Wih_f, bih_f, bhh_f, Wih_b, bih_b, bhh_b);
    k_lstm_all<<<128, 128, 22656*4>>>(Whh_f, Whh_b);
    k_tail<<<120, 1024, 16640*4>>>(bsv, heads, prior, Ws, W1, b1, W2, b2, out);
}